// round 11
// baseline (speedup 1.0000x reference)
#include <cuda_runtime.h>
#include <cuda_fp16.h>
#include <math.h>
#include <stdint.h>

#define BB 8
#define CC 128
#define TT 8
#define HWD 1024
#define NPOS 8192
#define CT 1024

// ---------------- scratch ----------------
__device__ float g_qf[BB][128][HWD];
__device__ float g_kf[BB][128][HWD];
__device__ __half g_vf_s[BB][CT][HWD];
__device__ float g_attn[BB][HWD][HWD];
__device__ __half g_attn_s[BB][HWD][HWD];
__device__ float g_ecam_p[32][BB][CC][CC];
__device__ float g_acam[BB][CC][CC];
__device__ float g_etim_p[BB][CC][36];
__device__ float g_atim[BB][TT][TT];

// ---------------- helpers ----------------
__device__ __forceinline__ void mma_f16(float* c, const uint32_t* a, const uint32_t* b) {
    asm volatile(
        "mma.sync.aligned.m16n8k16.row.col.f32.f16.f16.f32 "
        "{%0,%1,%2,%3}, {%4,%5,%6,%7}, {%8,%9}, {%0,%1,%2,%3};"
        : "+f"(c[0]), "+f"(c[1]), "+f"(c[2]), "+f"(c[3])
        : "r"(a[0]), "r"(a[1]), "r"(a[2]), "r"(a[3]), "r"(b[0]), "r"(b[1]));
}
__device__ __forceinline__ void mma_tf32(float* c, const uint32_t* a, const uint32_t* b) {
    asm volatile(
        "mma.sync.aligned.m16n8k8.row.col.f32.tf32.tf32.f32 "
        "{%0,%1,%2,%3}, {%4,%5,%6,%7}, {%8,%9}, {%0,%1,%2,%3};"
        : "+f"(c[0]), "+f"(c[1]), "+f"(c[2]), "+f"(c[3])
        : "r"(a[0]), "r"(a[1]), "r"(a[2]), "r"(a[3]), "r"(b[0]), "r"(b[1]));
}
__device__ __forceinline__ uint32_t f2tf32(float a) {
    uint32_t r; asm("cvt.rna.tf32.f32 %0, %1;" : "=r"(r) : "f"(a)); return r;
}
__device__ __forceinline__ void split_tf32(float a, float& h, float& l) {
    uint32_t hu = f2tf32(a);
    h = __uint_as_float(hu);
    l = __uint_as_float(f2tf32(a - h));
}
__device__ __forceinline__ void split4(float4 v, float4& h, float4& l) {
    split_tf32(v.x, h.x, l.x);
    split_tf32(v.y, h.y, l.y);
    split_tf32(v.z, h.z, l.z);
    split_tf32(v.w, h.w, l.w);
}
__device__ __forceinline__ void split_h(float a, __half& h, __half& l) {
    h = __float2half_rn(a);
    l = __float2half_rn(a - __half2float(h));
}
__device__ __forceinline__ uint32_t packh(__half a, __half b) {
    return ((uint32_t)__half_as_ushort(b) << 16) | __half_as_ushort(a);
}
__device__ __forceinline__ uint32_t f2u(float a) { return __float_as_uint(a); }
__device__ __forceinline__ uint32_t smem_to_u32(const void* p) {
    uint32_t a;
    asm("{ .reg .u64 t; cvta.to.shared.u64 t, %1; cvt.u32.u64 %0, t; }" : "=r"(a) : "l"(p));
    return a;
}
__device__ __forceinline__ void cp16(uint32_t s, const void* g) {
    asm volatile("cp.async.cg.shared.global [%0], [%1], 16;"
                 :: "r"(s), "l"(__cvta_generic_to_global(g)) : "memory");
}
#define CP_COMMIT() asm volatile("cp.async.commit_group;" ::: "memory")
#define CP_WAIT(n)  asm volatile("cp.async.wait_group %0;" :: "n"(n) : "memory")

// ---------------- 1) fused q/k/v projection via tf32 MMA ----------------
#define QKV_SMEM_BYTES ((2048 * 2 + 32 * 136 * 2) * 4)
__global__ __launch_bounds__(256, 2) void k_qkv_tc(
    const float* __restrict__ x,
    const float* __restrict__ Wq, const float* __restrict__ bq,
    const float* __restrict__ Wk, const float* __restrict__ bk,
    const float* __restrict__ Wv, const float* __restrict__ bv)
{
    extern __shared__ float dsm[];
    float* Wh = dsm;
    float* Wl = dsm + 2048;
    float* Bh = dsm + 4096;
    float* Bl = dsm + 4096 + 32 * 136;

    int b     = blockIdx.z;
    int rows0 = blockIdx.y * 64;
    int pos0  = blockIdx.x * 128;
    int tid = threadIdx.x, wid = tid >> 5, lane = tid & 31;
    int gid = lane >> 2, tq = lane & 3;
    int wm = (wid >> 1) * 16;
    int wn = (wid & 1) * 64;
    const float* xb = x + (size_t)b * (CC * NPOS);

    float acc[8][4] = {};

    for (int kc = 0; kc < 128; kc += 32) {
#pragma unroll
        for (int q = 0; q < 2; q++) {
            int e = tid + q * 256;
            int row = e >> 3, c4 = e & 7;
            int r = rows0 + row;
            float4 v = make_float4(0.f, 0.f, 0.f, 0.f);
            if (r < 16)       v = *(const float4*)(Wq + r * 128 + kc + c4 * 4);
            else if (r < 32)  v = *(const float4*)(Wk + (r - 16) * 128 + kc + c4 * 4);
            else if (r < 160) v = *(const float4*)(Wv + (r - 32) * 128 + kc + c4 * 4);
            float4 h, l; split4(v, h, l);
            int so = row * 32 + ((c4 * 4) ^ ((row & 7) * 4));
            *(float4*)&Wh[so] = h;
            *(float4*)&Wl[so] = l;
        }
#pragma unroll
        for (int q = 0; q < 4; q++) {
            int e = tid + q * 256;
            int f = e >> 5, ng = e & 31;
            float4 v = *(const float4*)(xb + (size_t)(kc + f) * NPOS + pos0 + ng * 4);
            float4 h, l; split4(v, h, l);
            *(float4*)&Bh[f * 136 + ng * 4] = h;
            *(float4*)&Bl[f * 136 + ng * 4] = l;
        }
        __syncthreads();
#pragma unroll
        for (int kk = 0; kk < 32; kk += 8) {
            uint32_t Af[4], Alf[4], Bf[8][2], Blf[8][2];
            int r0 = wm + gid, r1 = r0 + 8;
            int cA0 = kk + tq, cA1 = kk + tq + 4;
            Af[0]  = f2u(Wh[r0 * 32 + (cA0 ^ ((r0 & 7) * 4))]);
            Af[1]  = f2u(Wh[r1 * 32 + (cA0 ^ ((r1 & 7) * 4))]);
            Af[2]  = f2u(Wh[r0 * 32 + (cA1 ^ ((r0 & 7) * 4))]);
            Af[3]  = f2u(Wh[r1 * 32 + (cA1 ^ ((r1 & 7) * 4))]);
            Alf[0] = f2u(Wl[r0 * 32 + (cA0 ^ ((r0 & 7) * 4))]);
            Alf[1] = f2u(Wl[r1 * 32 + (cA0 ^ ((r1 & 7) * 4))]);
            Alf[2] = f2u(Wl[r0 * 32 + (cA1 ^ ((r0 & 7) * 4))]);
            Alf[3] = f2u(Wl[r1 * 32 + (cA1 ^ ((r1 & 7) * 4))]);
#pragma unroll
            for (int j = 0; j < 8; j++) {
                int n = wn + 8 * j + gid;
                Bf[j][0]  = f2u(Bh[(kk + tq) * 136 + n]);
                Bf[j][1]  = f2u(Bh[(kk + tq + 4) * 136 + n]);
                Blf[j][0] = f2u(Bl[(kk + tq) * 136 + n]);
                Blf[j][1] = f2u(Bl[(kk + tq + 4) * 136 + n]);
            }
#pragma unroll
            for (int j = 0; j < 8; j++) mma_tf32(acc[j], Af,  Bf[j]);
#pragma unroll
            for (int j = 0; j < 8; j++) mma_tf32(acc[j], Af,  Blf[j]);
#pragma unroll
            for (int j = 0; j < 8; j++) mma_tf32(acc[j], Alf, Bf[j]);
        }
        __syncthreads();
    }

    int t   = pos0 >> 10;
    int hw0 = pos0 & 1023;
#pragma unroll
    for (int j = 0; j < 8; j++) {
        int hw = hw0 + wn + 8 * j + 2 * tq;
#pragma unroll
        for (int half = 0; half < 2; half++) {
            int r = rows0 + wm + gid + half * 8;
            if (r >= 160) continue;
            float v0 = acc[j][half * 2 + 0];
            float v1 = acc[j][half * 2 + 1];
            if (r < 16) {
                float bias = bq[r];
                *(float2*)&g_qf[b][r * TT + t][hw] = make_float2(v0 + bias, v1 + bias);
            } else if (r < 32) {
                float bias = bk[r - 16];
                *(float2*)&g_kf[b][(r - 16) * TT + t][hw] = make_float2(v0 + bias, v1 + bias);
            } else {
                float bias = bv[r - 32];
                int row = (r - 32) * TT + t;
                *(uint32_t*)&g_vf_s[b][row][hw] =
                    packh(__float2half_rn(v0 + bias), __float2half_rn(v1 + bias));
            }
        }
    }
}

// ---------------- 2) PAM energy via tf32 MMA ----------------
#define EN_SMEM_BYTES (4 * 32 * 136 * 4)
__global__ __launch_bounds__(256, 2) void k_energy_tc()
{
    extern __shared__ float dsm[];
    float* Ah = dsm;
    float* Al = dsm + 32 * 136;
    float* Bh = dsm + 2 * 32 * 136;
    float* Bl = dsm + 3 * 32 * 136;

    int b  = blockIdx.z;
    int n0 = blockIdx.y * 128;
    int m0 = blockIdx.x * 128;
    int tid = threadIdx.x, wid = tid >> 5, lane = tid & 31;
    int gid = lane >> 2, tq = lane & 3;
    int wm = (wid >> 1) * 32;
    int wn = (wid & 1) * 64;

    float acc[2][8][4] = {};

    for (int kc = 0; kc < 128; kc += 32) {
#pragma unroll
        for (int q = 0; q < 4; q++) {
            int e = tid + q * 256;
            int f = e >> 5, ng = e & 31;
            float4 va = *(const float4*)(&g_qf[b][kc + f][n0 + ng * 4]);
            float4 vb = *(const float4*)(&g_kf[b][kc + f][m0 + ng * 4]);
            float4 h, l;
            split4(va, h, l);
            *(float4*)&Ah[f * 136 + ng * 4] = h;
            *(float4*)&Al[f * 136 + ng * 4] = l;
            split4(vb, h, l);
            *(float4*)&Bh[f * 136 + ng * 4] = h;
            *(float4*)&Bl[f * 136 + ng * 4] = l;
        }
        __syncthreads();
#pragma unroll
        for (int kk = 0; kk < 32; kk += 8) {
            uint32_t Af[2][4], Alf[2][4], Bf[8][2], Blf[8][2];
#pragma unroll
            for (int i = 0; i < 2; i++) {
                int m = wm + 16 * i + gid;
                Af[i][0]  = f2u(Ah[(kk + tq) * 136 + m]);
                Af[i][1]  = f2u(Ah[(kk + tq) * 136 + m + 8]);
                Af[i][2]  = f2u(Ah[(kk + tq + 4) * 136 + m]);
                Af[i][3]  = f2u(Ah[(kk + tq + 4) * 136 + m + 8]);
                Alf[i][0] = f2u(Al[(kk + tq) * 136 + m]);
                Alf[i][1] = f2u(Al[(kk + tq) * 136 + m + 8]);
                Alf[i][2] = f2u(Al[(kk + tq + 4) * 136 + m]);
                Alf[i][3] = f2u(Al[(kk + tq + 4) * 136 + m + 8]);
            }
#pragma unroll
            for (int j = 0; j < 8; j++) {
                int n = wn + 8 * j + gid;
                Bf[j][0]  = f2u(Bh[(kk + tq) * 136 + n]);
                Bf[j][1]  = f2u(Bh[(kk + tq + 4) * 136 + n]);
                Blf[j][0] = f2u(Bl[(kk + tq) * 136 + n]);
                Blf[j][1] = f2u(Bl[(kk + tq + 4) * 136 + n]);
            }
#pragma unroll
            for (int j = 0; j < 8; j++)
#pragma unroll
                for (int i = 0; i < 2; i++) mma_tf32(acc[i][j], Af[i], Bf[j]);
#pragma unroll
            for (int j = 0; j < 8; j++)
#pragma unroll
                for (int i = 0; i < 2; i++) mma_tf32(acc[i][j], Af[i], Blf[j]);
#pragma unroll
            for (int j = 0; j < 8; j++)
#pragma unroll
                for (int i = 0; i < 2; i++) mma_tf32(acc[i][j], Alf[i], Bf[j]);
        }
        __syncthreads();
    }

#pragma unroll
    for (int i = 0; i < 2; i++)
#pragma unroll
        for (int j = 0; j < 8; j++) {
            int n = n0 + wm + 16 * i + gid;
            int m = m0 + wn + 8 * j + 2 * tq;
            *(float2*)&g_attn[b][n][m]     = make_float2(acc[i][j][0], acc[i][j][1]);
            *(float2*)&g_attn[b][n + 8][m] = make_float2(acc[i][j][2], acc[i][j][3]);
        }
}

// ---------------- 3) softmax -> single fp16 (vectorized) ----------------
__global__ __launch_bounds__(256) void k_softmax()
{
    int row = blockIdx.x;
    int tid = threadIdx.x;
    const float4* e4 = (const float4*)(&g_attn[0][0][0] + (size_t)row * 1024);
    float4 v = e4[tid];
    float m = fmaxf(fmaxf(v.x, v.y), fmaxf(v.z, v.w));
    __shared__ float red[8];
#pragma unroll
    for (int o = 16; o > 0; o >>= 1) m = fmaxf(m, __shfl_xor_sync(0xffffffffu, m, o));
    if ((tid & 31) == 0) red[tid >> 5] = m;
    __syncthreads();
    m = red[0];
#pragma unroll
    for (int j = 1; j < 8; j++) m = fmaxf(m, red[j]);
    v.x = __expf(v.x - m); v.y = __expf(v.y - m);
    v.z = __expf(v.z - m); v.w = __expf(v.w - m);
    float s = (v.x + v.y) + (v.z + v.w);
    __syncthreads();
#pragma unroll
    for (int o = 16; o > 0; o >>= 1) s += __shfl_xor_sync(0xffffffffu, s, o);
    if ((tid & 31) == 0) red[tid >> 5] = s;
    __syncthreads();
    s = red[0];
#pragma unroll
    for (int j = 1; j < 8; j++) s += red[j];
    float inv = 1.f / s;
    v.x *= inv; v.y *= inv; v.z *= inv; v.w *= inv;

    uint2 hp;
    hp.x = packh(__float2half_rn(v.x), __float2half_rn(v.y));
    hp.y = packh(__float2half_rn(v.z), __float2half_rn(v.w));
    ((uint2*)(&g_attn_s[0][0][0] + (size_t)row * 1024))[tid] = hp;
}

// ---------------- 4) CAM energy fp16x3 Gram: cp.async raw staging + split pass ----------------
#define CPAD 40
#define CAME_SMEM_BYTES (32768 + 2 * 128 * CPAD * 2)
__global__ __launch_bounds__(256, 2) void k_came_tc(const float* __restrict__ x)
{
    extern __shared__ char csm[];
    float* raw = (float*)csm;                               // [2][4096]
    __half* Xh = (__half*)(csm + 32768);                    // [128][CPAD]
    __half* Xl = (__half*)(csm + 32768 + 128 * CPAD * 2);
    uint32_t rawb = smem_to_u32(raw);

    int b  = blockIdx.x >> 5;
    int sl = blockIdx.x & 31;
    int tid = threadIdx.x, wid = tid >> 5, lane = tid & 31;
    int gid = lane >> 2, tq = lane & 3;
    int wm = (wid >> 1) * 32;
    int wn = (wid & 1) * 64;
    const float* xb = x + (size_t)b * (CC * NPOS) + sl * 256;

    float acc[2][8][4] = {};

    auto load_raw = [&](int st, int kc) {
#pragma unroll
        for (int q = 0; q < 4; q++) {
            int e = tid + q * 256;
            int row = e >> 3, c4 = e & 7;
            cp16(rawb + (uint32_t)(st * 4096 + row * 32 + c4 * 4) * 4,
                 xb + (size_t)row * NPOS + kc + c4 * 4);
        }
        CP_COMMIT();
    };

    load_raw(0, 0);

    for (int it = 0; it < 8; it++) {
        int st = it & 1;
        if (it < 7) { load_raw(st ^ 1, (it + 1) * 32); CP_WAIT(1); }
        else        { CP_WAIT(0); }
        __syncthreads();   // raw[st] visible; previous MMA done (X free)

        // split pass: raw fp32 -> Xh/Xl halves
#pragma unroll
        for (int q = 0; q < 4; q++) {
            int e = tid + q * 256;
            int row = e >> 3, c4 = e & 7;
            float4 v = *(const float4*)&raw[st * 4096 + row * 32 + c4 * 4];
            __half hx, lx, hy, ly, hz, lz, hw, lw;
            split_h(v.x, hx, lx); split_h(v.y, hy, ly);
            split_h(v.z, hz, lz); split_h(v.w, hw, lw);
            uint2 hp, lp;
            hp.x = packh(hx, hy); hp.y = packh(hz, hw);
            lp.x = packh(lx, ly); lp.y = packh(lz, lw);
            *(uint2*)&Xh[row * CPAD + c4 * 4] = hp;
            *(uint2*)&Xl[row * CPAD + c4 * 4] = lp;
        }
        __syncthreads();

#pragma unroll
        for (int kk = 0; kk < 32; kk += 16) {
            uint32_t Af[2][4], Alf[2][4], Bf[8][2], Blf[8][2];
            int c0 = kk + 2 * tq, c1 = c0 + 8;
#pragma unroll
            for (int i = 0; i < 2; i++) {
                int r0 = wm + 16 * i + gid, r1 = r0 + 8;
                Af[i][0]  = *(const uint32_t*)&Xh[r0 * CPAD + c0];
                Af[i][1]  = *(const uint32_t*)&Xh[r1 * CPAD + c0];
                Af[i][2]  = *(const uint32_t*)&Xh[r0 * CPAD + c1];
                Af[i][3]  = *(const uint32_t*)&Xh[r1 * CPAD + c1];
                Alf[i][0] = *(const uint32_t*)&Xl[r0 * CPAD + c0];
                Alf[i][1] = *(const uint32_t*)&Xl[r1 * CPAD + c0];
                Alf[i][2] = *(const uint32_t*)&Xl[r0 * CPAD + c1];
                Alf[i][3] = *(const uint32_t*)&Xl[r1 * CPAD + c1];
            }
#pragma unroll
            for (int j = 0; j < 8; j++) {
                int rn = wn + 8 * j + gid;
                Bf[j][0]  = *(const uint32_t*)&Xh[rn * CPAD + c0];
                Bf[j][1]  = *(const uint32_t*)&Xh[rn * CPAD + c1];
                Blf[j][0] = *(const uint32_t*)&Xl[rn * CPAD + c0];
                Blf[j][1] = *(const uint32_t*)&Xl[rn * CPAD + c1];
            }
#pragma unroll
            for (int j = 0; j < 8; j++)
#pragma unroll
                for (int i = 0; i < 2; i++) mma_f16(acc[i][j], Af[i], Bf[j]);
#pragma unroll
            for (int j = 0; j < 8; j++)
#pragma unroll
                for (int i = 0; i < 2; i++) mma_f16(acc[i][j], Af[i], Blf[j]);
#pragma unroll
            for (int j = 0; j < 8; j++)
#pragma unroll
                for (int i = 0; i < 2; i++) mma_f16(acc[i][j], Alf[i], Bf[j]);
        }
    }

#pragma unroll
    for (int i = 0; i < 2; i++)
#pragma unroll
        for (int j = 0; j < 8; j++) {
            int c = wm + 16 * i + gid;
            int d = wn + 8 * j + 2 * tq;
            *(float2*)&g_ecam_p[sl][b][c][d]     = make_float2(acc[i][j][0], acc[i][j][1]);
            *(float2*)&g_ecam_p[sl][b][c + 8][d] = make_float2(acc[i][j][2], acc[i][j][3]);
        }
}

// ---------------- 5) CAM negated-energy softmax ----------------
__global__ __launch_bounds__(128) void k_camsm()
{
    int b = blockIdx.x >> 7;
    int c = blockIdx.x & 127;
    int d = threadIdx.x;
    float ev = 0.f;
#pragma unroll
    for (int sl = 0; sl < 32; sl++) ev += g_ecam_p[sl][b][c][d];
    __shared__ float red[4];
    float mn = ev;
#pragma unroll
    for (int o = 16; o > 0; o >>= 1) mn = fminf(mn, __shfl_xor_sync(0xffffffffu, mn, o));
    if ((threadIdx.x & 31) == 0) red[threadIdx.x >> 5] = mn;
    __syncthreads();
    mn = fminf(fminf(red[0], red[1]), fminf(red[2], red[3]));
    float w = __expf(mn - ev);
    __syncthreads();
    float s = w;
#pragma unroll
    for (int o = 16; o > 0; o >>= 1) s += __shfl_xor_sync(0xffffffffu, s, o);
    if ((threadIdx.x & 31) == 0) red[threadIdx.x >> 5] = s;
    __syncthreads();
    s = (red[0] + red[1]) + (red[2] + red[3]);
    g_acam[b][c][d] = w / s;
}

// ---------------- 6) TIM Gram partials ----------------
__global__ __launch_bounds__(256) void k_time(const float* __restrict__ x)
{
    int c = blockIdx.x;
    int b = blockIdx.y;
    int tid = threadIdx.x;
    const float* xp = x + ((size_t)b * CC + c) * NPOS;
    float v[8][4];
#pragma unroll
    for (int t = 0; t < 8; t++) {
        float4 f = *reinterpret_cast<const float4*>(xp + t * 1024 + tid * 4);
        v[t][0] = f.x; v[t][1] = f.y; v[t][2] = f.z; v[t][3] = f.w;
    }
    float acc[36];
    int idx = 0;
#pragma unroll
    for (int t = 0; t < 8; t++)
#pragma unroll
        for (int s = t; s < 8; s++) {
            float a = 0.f;
#pragma unroll
            for (int j = 0; j < 4; j++) a += v[t][j] * v[s][j];
            acc[idx++] = a;
        }
    __shared__ float red[36][8];
    int lane = tid & 31, warp = tid >> 5;
#pragma unroll
    for (int i = 0; i < 36; i++) {
        float a = acc[i];
#pragma unroll
        for (int o = 16; o > 0; o >>= 1) a += __shfl_xor_sync(0xffffffffu, a, o);
        if (lane == 0) red[i][warp] = a;
    }
    __syncthreads();
    if (tid < 36) {
        float a = 0.f;
#pragma unroll
        for (int w = 0; w < 8; w++) a += red[tid][w];
        g_etim_p[b][c][tid] = a;
    }
}

// ---------------- 7) TIM reduce + softmax ----------------
__global__ __launch_bounds__(256) void k_timsm()
{
    __shared__ float e36[BB][36];
    int tid = threadIdx.x;
    for (int o = tid; o < BB * 36; o += 256) {
        int b = o / 36, i = o % 36;
        float a = 0.f;
        for (int c = 0; c < CC; c++) a += g_etim_p[b][c][i];
        e36[b][i] = a;
    }
    __syncthreads();
    if (tid < 64) {
        int b = tid >> 3, t = tid & 7;
        float e[8];
#pragma unroll
        for (int s = 0; s < 8; s++) {
            int lo = t < s ? t : s, hi = t < s ? s : t;
            int idx = 8 * lo - lo * (lo - 1) / 2 + (hi - lo);
            e[s] = e36[b][idx];
        }
        float mn = e[0];
#pragma unroll
        for (int s = 1; s < 8; s++) mn = fminf(mn, e[s]);
        float w[8], sum = 0.f;
#pragma unroll
        for (int s = 0; s < 8; s++) { w[s] = __expf(mn - e[s]); sum += w[s]; }
#pragma unroll
        for (int s = 0; s < 8; s++) g_atim[b][t][s] = w[s] / sum;
    }
}

// ---------------- 8) base: out = 3x + gc*(a_cam@xc) + gt*tim ----------------
__global__ __launch_bounds__(256) void k_base(
    const float* __restrict__ x,
    const float* __restrict__ gcp, const float* __restrict__ gtp,
    float* __restrict__ out)
{
    int b   = blockIdx.z;
    int c0  = blockIdx.y * 32;
    int hw0 = blockIdx.x * 32;
    __shared__ float As[32][33];
    __shared__ float Xs[32][8][33];
    __shared__ float at8[8][8];
    int tid = threadIdx.x;
    int hw_l = tid & 31, cg = tid >> 5;
    if (tid < 64) at8[tid >> 3][tid & 7] = g_atim[b][tid >> 3][tid & 7];
    float acc[4][8] = {};
    const float* xb = x + (size_t)b * (CC * NPOS);

    for (int kc = 0; kc < CC; kc += 32) {
#pragma unroll
        for (int q = 0; q < 4; q++) {
            int e = tid + q * 256;
            int i = e >> 5, k = e & 31;
            As[i][k] = g_acam[b][c0 + i][kc + k];
        }
#pragma unroll
        for (int q = 0; q < 32; q++) {
            int e = tid + q * 256;
            int k = e >> 8, t = (e >> 5) & 7, hw = e & 31;
            Xs[k][t][hw] = xb[(size_t)(kc + k) * NPOS + t * 1024 + hw0 + hw];
        }
        __syncthreads();
#pragma unroll
        for (int k = 0; k < 32; k++) {
            float av[4], xv[8];
#pragma unroll
            for (int j = 0; j < 4; j++) av[j] = As[cg + 8 * j][k];
#pragma unroll
            for (int t = 0; t < 8; t++) xv[t] = Xs[k][t][hw_l];
#pragma unroll
            for (int j = 0; j < 4; j++)
#pragma unroll
                for (int t = 0; t < 8; t++) acc[j][t] += av[j] * xv[t];
        }
        __syncthreads();
    }

    float gc = gcp[0], gt = gtp[0];
#pragma unroll
    for (int j = 0; j < 4; j++) {
        int c = c0 + cg + 8 * j;
        const float* xc = xb + (size_t)c * NPOS + hw0 + hw_l;
        float xrow[8];
#pragma unroll
        for (int s = 0; s < 8; s++) xrow[s] = xc[s * 1024];
        float* oc = out + (size_t)b * (CC * NPOS) + (size_t)c * NPOS + hw0 + hw_l;
#pragma unroll
        for (int t = 0; t < 8; t++) {
            float tim = 0.f;
#pragma unroll
            for (int s = 0; s < 8; s++) tim += at8[t][s] * xrow[s];
            oc[t * 1024] = 3.f * xrow[t] + gc * acc[j][t] + gt * tim;
        }
    }
}

// ---------------- 9) PAM GEMM: single-term fp16, cp.async 3-stage ----------------
#define PAD 40
#define PAM_TILE 5120
#define PAM_STAGE (2 * PAM_TILE)
#define PAM_SMEM_BYTES (3 * PAM_STAGE * 2)
__global__ __launch_bounds__(256, 2) void k_pam_mma(const float* __restrict__ gpp,
                                                    float* __restrict__ out)
{
    extern __shared__ __half smp[];
    uint32_t smb = smem_to_u32(smp);

    int tid = threadIdx.x;
    int b  = blockIdx.z;
    int r0 = blockIdx.y * 128;
    int n0 = blockIdx.x * 128;
    int wid = tid >> 5, lane = tid & 31;
    int gid = lane >> 2, tq = lane & 3;
    int wm = (wid & 1) * 64;
    int wn = (wid >> 1) * 32;

    const __half* Asp = &g_vf_s[b][0][0];
    const __half* Bsp = &g_attn_s[b][0][0];

    float acc[4][4][4] = {};

    auto stage_load = [&](int st, int kc) {
#pragma unroll
        for (int q = 0; q < 2; q++) {
            int e = tid + q * 256;
            int row = e >> 2, c4 = e & 3;
            uint32_t so = smb + (uint32_t)(st * PAM_STAGE + row * PAD + c4 * 8) * 2;
            size_t gA = (size_t)(r0 + row) * 1024 + kc + c4 * 8;
            size_t gB = (size_t)(n0 + row) * 1024 + kc + c4 * 8;
            cp16(so,                Asp + gA);
            cp16(so + PAM_TILE * 2, Bsp + gB);
        }
        CP_COMMIT();
    };

    stage_load(0, 0);
    stage_load(1, 32);

    int st = 0;
    for (int it = 0; it < 32; it++) {
        if (it < 30) { stage_load((st + 2) % 3, (it + 2) * 32); CP_WAIT(2); }
        else         { CP_WAIT(0); }
        __syncthreads();

        const __half* sAs = smp + st * PAM_STAGE;
        const __half* sBs = sAs + PAM_TILE;

#pragma unroll
        for (int ks = 0; ks < 32; ks += 16) {
            uint32_t Af[4][4], Bf[4][2];
            int col = ks + tq * 2;
#pragma unroll
            for (int i = 0; i < 4; i++) {
                int row = wm + 16 * i + gid;
                Af[i][0] = *(const uint32_t*)&sAs[row * PAD + col];
                Af[i][1] = *(const uint32_t*)&sAs[(row + 8) * PAD + col];
                Af[i][2] = *(const uint32_t*)&sAs[row * PAD + col + 8];
                Af[i][3] = *(const uint32_t*)&sAs[(row + 8) * PAD + col + 8];
            }
#pragma unroll
            for (int j = 0; j < 4; j++) {
                int nrow = wn + 8 * j + gid;
                Bf[j][0] = *(const uint32_t*)&sBs[nrow * PAD + col];
                Bf[j][1] = *(const uint32_t*)&sBs[nrow * PAD + col + 8];
            }
#pragma unroll
            for (int j = 0; j < 4; j++)
#pragma unroll
                for (int i = 0; i < 4; i++) mma_f16(acc[i][j], Af[i], Bf[j]);
        }
        __syncthreads();
        st = (st + 1) % 3;
    }

    float gpv = gpp[0];
    float* ob = out + (size_t)b * (CT * HWD);
#pragma unroll
    for (int i = 0; i < 4; i++) {
#pragma unroll
        for (int j = 0; j < 4; j++) {
            int r = r0 + wm + 16 * i + gid;
            int n = n0 + wn + 8 * j + tq * 2;
            float2* p0 = (float2*)(ob + (size_t)r * 1024 + n);
            float2 v0 = *p0;
            v0.x += gpv * acc[i][j][0];
            v0.y += gpv * acc[i][j][1];
            *p0 = v0;
            float2* p1 = (float2*)(ob + (size_t)(r + 8) * 1024 + n);
            float2 v1 = *p1;
            v1.x += gpv * acc[i][j][2];
            v1.y += gpv * acc[i][j][3];
            *p1 = v1;
        }
    }
}

// ---------------- launch ----------------
extern "C" void kernel_launch(void* const* d_in, const int* in_sizes, int n_in,
                              void* d_out, int out_size)
{
    const float* x  = (const float*)d_in[0];
    const float* Wq = (const float*)d_in[1];
    const float* bq = (const float*)d_in[2];
    const float* Wk = (const float*)d_in[3];
    const float* bk = (const float*)d_in[4];
    const float* Wv = (const float*)d_in[5];
    const float* bv = (const float*)d_in[6];
    const float* gp = (const float*)d_in[7];
    const float* gc = (const float*)d_in[8];
    const float* gt = (const float*)d_in[9];
    float* out = (float*)d_out;

    static int attrs_set = 0;
    if (!attrs_set) {
        cudaFuncSetAttribute(k_qkv_tc, cudaFuncAttributeMaxDynamicSharedMemorySize, QKV_SMEM_BYTES);
        cudaFuncSetAttribute(k_energy_tc, cudaFuncAttributeMaxDynamicSharedMemorySize, EN_SMEM_BYTES);
        cudaFuncSetAttribute(k_came_tc, cudaFuncAttributeMaxDynamicSharedMemorySize, CAME_SMEM_BYTES);
        cudaFuncSetAttribute(k_pam_mma, cudaFuncAttributeMaxDynamicSharedMemorySize, PAM_SMEM_BYTES);
        attrs_set = 1;
    }

    k_qkv_tc<<<dim3(64, 3, 8), 256, QKV_SMEM_BYTES>>>(x, Wq, bq, Wk, bk, Wv, bv);
    k_energy_tc<<<dim3(8, 8, 8), 256, EN_SMEM_BYTES>>>();
    k_softmax<<<8192, 256>>>();
    k_came_tc<<<256, 256, CAME_SMEM_BYTES>>>(x);
    k_camsm<<<1024, 128>>>();
    k_time<<<dim3(128, 8), 256>>>(x);
    k_timsm<<<1, 256>>>();
    k_base<<<dim3(32, 4, 8), 256>>>(x, gc, gt, out);
    k_pam_mma<<<dim3(8, 8, 8), 256, PAM_SMEM_BYTES>>>(gp, out);
}

// round 12
// speedup vs baseline: 1.0198x; 1.0198x over previous
#include <cuda_runtime.h>
#include <cuda_fp16.h>
#include <math.h>
#include <stdint.h>

#define BB 8
#define CC 128
#define TT 8
#define HWD 1024
#define NPOS 8192
#define CT 1024

// ---------------- scratch ----------------
__device__ float g_qf[BB][128][HWD];
__device__ float g_kf[BB][128][HWD];
__device__ __half g_vf_s[BB][CT][HWD];
__device__ float g_attn[BB][HWD][HWD];
__device__ __half g_attn_s[BB][HWD][HWD];
__device__ float g_ecam_p[32][BB][CC][CC];
__device__ float g_acam[BB][CC][CC];
__device__ float g_etim_p[BB][CC][36];
__device__ float g_atim[BB][TT][TT];

// ---------------- helpers ----------------
__device__ __forceinline__ void mma_f16(float* c, const uint32_t* a, const uint32_t* b) {
    asm volatile(
        "mma.sync.aligned.m16n8k16.row.col.f32.f16.f16.f32 "
        "{%0,%1,%2,%3}, {%4,%5,%6,%7}, {%8,%9}, {%0,%1,%2,%3};"
        : "+f"(c[0]), "+f"(c[1]), "+f"(c[2]), "+f"(c[3])
        : "r"(a[0]), "r"(a[1]), "r"(a[2]), "r"(a[3]), "r"(b[0]), "r"(b[1]));
}
__device__ __forceinline__ void mma_tf32(float* c, const uint32_t* a, const uint32_t* b) {
    asm volatile(
        "mma.sync.aligned.m16n8k8.row.col.f32.tf32.tf32.f32 "
        "{%0,%1,%2,%3}, {%4,%5,%6,%7}, {%8,%9}, {%0,%1,%2,%3};"
        : "+f"(c[0]), "+f"(c[1]), "+f"(c[2]), "+f"(c[3])
        : "r"(a[0]), "r"(a[1]), "r"(a[2]), "r"(a[3]), "r"(b[0]), "r"(b[1]));
}
__device__ __forceinline__ uint32_t f2tf32(float a) {
    uint32_t r; asm("cvt.rna.tf32.f32 %0, %1;" : "=r"(r) : "f"(a)); return r;
}
__device__ __forceinline__ void split_tf32(float a, float& h, float& l) {
    uint32_t hu = f2tf32(a);
    h = __uint_as_float(hu);
    l = __uint_as_float(f2tf32(a - h));
}
__device__ __forceinline__ void split4(float4 v, float4& h, float4& l) {
    split_tf32(v.x, h.x, l.x);
    split_tf32(v.y, h.y, l.y);
    split_tf32(v.z, h.z, l.z);
    split_tf32(v.w, h.w, l.w);
}
__device__ __forceinline__ void split_h(float a, __half& h, __half& l) {
    h = __float2half_rn(a);
    l = __float2half_rn(a - __half2float(h));
}
__device__ __forceinline__ uint32_t packh(__half a, __half b) {
    return ((uint32_t)__half_as_ushort(b) << 16) | __half_as_ushort(a);
}
__device__ __forceinline__ uint32_t f2u(float a) { return __float_as_uint(a); }
__device__ __forceinline__ uint32_t smem_to_u32(const void* p) {
    uint32_t a;
    asm("{ .reg .u64 t; cvta.to.shared.u64 t, %1; cvt.u32.u64 %0, t; }" : "=r"(a) : "l"(p));
    return a;
}
__device__ __forceinline__ void cp16(uint32_t s, const void* g) {
    asm volatile("cp.async.cg.shared.global [%0], [%1], 16;"
                 :: "r"(s), "l"(__cvta_generic_to_global(g)) : "memory");
}
#define CP_COMMIT() asm volatile("cp.async.commit_group;" ::: "memory")
#define CP_WAIT(n)  asm volatile("cp.async.wait_group %0;" :: "n"(n) : "memory")

// ---------------- 1) fused q/k/v projection via tf32 MMA (round-10 form) ----------------
#define QKV_SMEM_BYTES ((2048 * 2 + 32 * 136 * 2) * 4)
__global__ __launch_bounds__(256) void k_qkv_tc(
    const float* __restrict__ x,
    const float* __restrict__ Wq, const float* __restrict__ bq,
    const float* __restrict__ Wk, const float* __restrict__ bk,
    const float* __restrict__ Wv, const float* __restrict__ bv)
{
    extern __shared__ float dsm[];
    float* Wh = dsm;
    float* Wl = dsm + 2048;
    float* Bh = dsm + 4096;
    float* Bl = dsm + 4096 + 32 * 136;

    int b     = blockIdx.z;
    int rows0 = blockIdx.y * 64;
    int pos0  = blockIdx.x * 128;
    int tid = threadIdx.x, wid = tid >> 5, lane = tid & 31;
    int gid = lane >> 2, tq = lane & 3;
    int wm = (wid >> 1) * 16;
    int wn = (wid & 1) * 64;
    const float* xb = x + (size_t)b * (CC * NPOS);

    float acc[8][4] = {};

    for (int kc = 0; kc < 128; kc += 32) {
#pragma unroll
        for (int q = 0; q < 2; q++) {
            int e = tid + q * 256;
            int row = e >> 3, c4 = e & 7;
            int r = rows0 + row;
            float4 v = make_float4(0.f, 0.f, 0.f, 0.f);
            if (r < 16)       v = *(const float4*)(Wq + r * 128 + kc + c4 * 4);
            else if (r < 32)  v = *(const float4*)(Wk + (r - 16) * 128 + kc + c4 * 4);
            else if (r < 160) v = *(const float4*)(Wv + (r - 32) * 128 + kc + c4 * 4);
            float4 h, l; split4(v, h, l);
            int so = row * 32 + ((c4 * 4) ^ ((row & 7) * 4));
            *(float4*)&Wh[so] = h;
            *(float4*)&Wl[so] = l;
        }
#pragma unroll
        for (int q = 0; q < 4; q++) {
            int e = tid + q * 256;
            int f = e >> 5, ng = e & 31;
            float4 v = *(const float4*)(xb + (size_t)(kc + f) * NPOS + pos0 + ng * 4);
            float4 h, l; split4(v, h, l);
            *(float4*)&Bh[f * 136 + ng * 4] = h;
            *(float4*)&Bl[f * 136 + ng * 4] = l;
        }
        __syncthreads();
#pragma unroll
        for (int kk = 0; kk < 32; kk += 8) {
            uint32_t Af[4], Alf[4], Bf[8][2], Blf[8][2];
            int r0 = wm + gid, r1 = r0 + 8;
            int cA0 = kk + tq, cA1 = kk + tq + 4;
            Af[0]  = f2u(Wh[r0 * 32 + (cA0 ^ ((r0 & 7) * 4))]);
            Af[1]  = f2u(Wh[r1 * 32 + (cA0 ^ ((r1 & 7) * 4))]);
            Af[2]  = f2u(Wh[r0 * 32 + (cA1 ^ ((r0 & 7) * 4))]);
            Af[3]  = f2u(Wh[r1 * 32 + (cA1 ^ ((r1 & 7) * 4))]);
            Alf[0] = f2u(Wl[r0 * 32 + (cA0 ^ ((r0 & 7) * 4))]);
            Alf[1] = f2u(Wl[r1 * 32 + (cA0 ^ ((r1 & 7) * 4))]);
            Alf[2] = f2u(Wl[r0 * 32 + (cA1 ^ ((r0 & 7) * 4))]);
            Alf[3] = f2u(Wl[r1 * 32 + (cA1 ^ ((r1 & 7) * 4))]);
#pragma unroll
            for (int j = 0; j < 8; j++) {
                int n = wn + 8 * j + gid;
                Bf[j][0]  = f2u(Bh[(kk + tq) * 136 + n]);
                Bf[j][1]  = f2u(Bh[(kk + tq + 4) * 136 + n]);
                Blf[j][0] = f2u(Bl[(kk + tq) * 136 + n]);
                Blf[j][1] = f2u(Bl[(kk + tq + 4) * 136 + n]);
            }
#pragma unroll
            for (int j = 0; j < 8; j++) mma_tf32(acc[j], Af,  Bf[j]);
#pragma unroll
            for (int j = 0; j < 8; j++) mma_tf32(acc[j], Af,  Blf[j]);
#pragma unroll
            for (int j = 0; j < 8; j++) mma_tf32(acc[j], Alf, Bf[j]);
        }
        __syncthreads();
    }

    int t   = pos0 >> 10;
    int hw0 = pos0 & 1023;
#pragma unroll
    for (int j = 0; j < 8; j++) {
        int hw = hw0 + wn + 8 * j + 2 * tq;
#pragma unroll
        for (int half = 0; half < 2; half++) {
            int r = rows0 + wm + gid + half * 8;
            if (r >= 160) continue;
            float v0 = acc[j][half * 2 + 0];
            float v1 = acc[j][half * 2 + 1];
            if (r < 16) {
                float bias = bq[r];
                *(float2*)&g_qf[b][r * TT + t][hw] = make_float2(v0 + bias, v1 + bias);
            } else if (r < 32) {
                float bias = bk[r - 16];
                *(float2*)&g_kf[b][(r - 16) * TT + t][hw] = make_float2(v0 + bias, v1 + bias);
            } else {
                float bias = bv[r - 32];
                int row = (r - 32) * TT + t;
                *(uint32_t*)&g_vf_s[b][row][hw] =
                    packh(__float2half_rn(v0 + bias), __float2half_rn(v1 + bias));
            }
        }
    }
}

// ---------------- 2) PAM energy via tf32 MMA ----------------
#define EN_SMEM_BYTES (4 * 32 * 136 * 4)
__global__ __launch_bounds__(256, 2) void k_energy_tc()
{
    extern __shared__ float dsm[];
    float* Ah = dsm;
    float* Al = dsm + 32 * 136;
    float* Bh = dsm + 2 * 32 * 136;
    float* Bl = dsm + 3 * 32 * 136;

    int b  = blockIdx.z;
    int n0 = blockIdx.y * 128;
    int m0 = blockIdx.x * 128;
    int tid = threadIdx.x, wid = tid >> 5, lane = tid & 31;
    int gid = lane >> 2, tq = lane & 3;
    int wm = (wid >> 1) * 32;
    int wn = (wid & 1) * 64;

    float acc[2][8][4] = {};

    for (int kc = 0; kc < 128; kc += 32) {
#pragma unroll
        for (int q = 0; q < 4; q++) {
            int e = tid + q * 256;
            int f = e >> 5, ng = e & 31;
            float4 va = *(const float4*)(&g_qf[b][kc + f][n0 + ng * 4]);
            float4 vb = *(const float4*)(&g_kf[b][kc + f][m0 + ng * 4]);
            float4 h, l;
            split4(va, h, l);
            *(float4*)&Ah[f * 136 + ng * 4] = h;
            *(float4*)&Al[f * 136 + ng * 4] = l;
            split4(vb, h, l);
            *(float4*)&Bh[f * 136 + ng * 4] = h;
            *(float4*)&Bl[f * 136 + ng * 4] = l;
        }
        __syncthreads();
#pragma unroll
        for (int kk = 0; kk < 32; kk += 8) {
            uint32_t Af[2][4], Alf[2][4], Bf[8][2], Blf[8][2];
#pragma unroll
            for (int i = 0; i < 2; i++) {
                int m = wm + 16 * i + gid;
                Af[i][0]  = f2u(Ah[(kk + tq) * 136 + m]);
                Af[i][1]  = f2u(Ah[(kk + tq) * 136 + m + 8]);
                Af[i][2]  = f2u(Ah[(kk + tq + 4) * 136 + m]);
                Af[i][3]  = f2u(Ah[(kk + tq + 4) * 136 + m + 8]);
                Alf[i][0] = f2u(Al[(kk + tq) * 136 + m]);
                Alf[i][1] = f2u(Al[(kk + tq) * 136 + m + 8]);
                Alf[i][2] = f2u(Al[(kk + tq + 4) * 136 + m]);
                Alf[i][3] = f2u(Al[(kk + tq + 4) * 136 + m + 8]);
            }
#pragma unroll
            for (int j = 0; j < 8; j++) {
                int n = wn + 8 * j + gid;
                Bf[j][0]  = f2u(Bh[(kk + tq) * 136 + n]);
                Bf[j][1]  = f2u(Bh[(kk + tq + 4) * 136 + n]);
                Blf[j][0] = f2u(Bl[(kk + tq) * 136 + n]);
                Blf[j][1] = f2u(Bl[(kk + tq + 4) * 136 + n]);
            }
#pragma unroll
            for (int j = 0; j < 8; j++)
#pragma unroll
                for (int i = 0; i < 2; i++) mma_tf32(acc[i][j], Af[i], Bf[j]);
#pragma unroll
            for (int j = 0; j < 8; j++)
#pragma unroll
                for (int i = 0; i < 2; i++) mma_tf32(acc[i][j], Af[i], Blf[j]);
#pragma unroll
            for (int j = 0; j < 8; j++)
#pragma unroll
                for (int i = 0; i < 2; i++) mma_tf32(acc[i][j], Alf[i], Bf[j]);
        }
        __syncthreads();
    }

#pragma unroll
    for (int i = 0; i < 2; i++)
#pragma unroll
        for (int j = 0; j < 8; j++) {
            int n = n0 + wm + 16 * i + gid;
            int m = m0 + wn + 8 * j + 2 * tq;
            *(float2*)&g_attn[b][n][m]     = make_float2(acc[i][j][0], acc[i][j][1]);
            *(float2*)&g_attn[b][n + 8][m] = make_float2(acc[i][j][2], acc[i][j][3]);
        }
}

// ---------------- 3) softmax -> single fp16 (vectorized) ----------------
__global__ __launch_bounds__(256) void k_softmax()
{
    int row = blockIdx.x;
    int tid = threadIdx.x;
    const float4* e4 = (const float4*)(&g_attn[0][0][0] + (size_t)row * 1024);
    float4 v = e4[tid];
    float m = fmaxf(fmaxf(v.x, v.y), fmaxf(v.z, v.w));
    __shared__ float red[8];
#pragma unroll
    for (int o = 16; o > 0; o >>= 1) m = fmaxf(m, __shfl_xor_sync(0xffffffffu, m, o));
    if ((tid & 31) == 0) red[tid >> 5] = m;
    __syncthreads();
    m = red[0];
#pragma unroll
    for (int j = 1; j < 8; j++) m = fmaxf(m, red[j]);
    v.x = __expf(v.x - m); v.y = __expf(v.y - m);
    v.z = __expf(v.z - m); v.w = __expf(v.w - m);
    float s = (v.x + v.y) + (v.z + v.w);
    __syncthreads();
#pragma unroll
    for (int o = 16; o > 0; o >>= 1) s += __shfl_xor_sync(0xffffffffu, s, o);
    if ((tid & 31) == 0) red[tid >> 5] = s;
    __syncthreads();
    s = red[0];
#pragma unroll
    for (int j = 1; j < 8; j++) s += red[j];
    float inv = 1.f / s;
    v.x *= inv; v.y *= inv; v.z *= inv; v.w *= inv;

    uint2 hp;
    hp.x = packh(__float2half_rn(v.x), __float2half_rn(v.y));
    hp.y = packh(__float2half_rn(v.z), __float2half_rn(v.w));
    ((uint2*)(&g_attn_s[0][0][0] + (size_t)row * 1024))[tid] = hp;
}

// ---------------- 4) CAM energy fp16x3 Gram: cp.async raw staging + split pass (kept) ----------------
#define CPAD 40
#define CAME_SMEM_BYTES (32768 + 2 * 128 * CPAD * 2)
__global__ __launch_bounds__(256, 2) void k_came_tc(const float* __restrict__ x)
{
    extern __shared__ char csm[];
    float* raw = (float*)csm;
    __half* Xh = (__half*)(csm + 32768);
    __half* Xl = (__half*)(csm + 32768 + 128 * CPAD * 2);
    uint32_t rawb = smem_to_u32(raw);

    int b  = blockIdx.x >> 5;
    int sl = blockIdx.x & 31;
    int tid = threadIdx.x, wid = tid >> 5, lane = tid & 31;
    int gid = lane >> 2, tq = lane & 3;
    int wm = (wid >> 1) * 32;
    int wn = (wid & 1) * 64;
    const float* xb = x + (size_t)b * (CC * NPOS) + sl * 256;

    float acc[2][8][4] = {};

    auto load_raw = [&](int st, int kc) {
#pragma unroll
        for (int q = 0; q < 4; q++) {
            int e = tid + q * 256;
            int row = e >> 3, c4 = e & 7;
            cp16(rawb + (uint32_t)(st * 4096 + row * 32 + c4 * 4) * 4,
                 xb + (size_t)row * NPOS + kc + c4 * 4);
        }
        CP_COMMIT();
    };

    load_raw(0, 0);

    for (int it = 0; it < 8; it++) {
        int st = it & 1;
        if (it < 7) { load_raw(st ^ 1, (it + 1) * 32); CP_WAIT(1); }
        else        { CP_WAIT(0); }
        __syncthreads();

#pragma unroll
        for (int q = 0; q < 4; q++) {
            int e = tid + q * 256;
            int row = e >> 3, c4 = e & 7;
            float4 v = *(const float4*)&raw[st * 4096 + row * 32 + c4 * 4];
            __half hx, lx, hy, ly, hz, lz, hw, lw;
            split_h(v.x, hx, lx); split_h(v.y, hy, ly);
            split_h(v.z, hz, lz); split_h(v.w, hw, lw);
            uint2 hp, lp;
            hp.x = packh(hx, hy); hp.y = packh(hz, hw);
            lp.x = packh(lx, ly); lp.y = packh(lz, lw);
            *(uint2*)&Xh[row * CPAD + c4 * 4] = hp;
            *(uint2*)&Xl[row * CPAD + c4 * 4] = lp;
        }
        __syncthreads();

#pragma unroll
        for (int kk = 0; kk < 32; kk += 16) {
            uint32_t Af[2][4], Alf[2][4], Bf[8][2], Blf[8][2];
            int c0 = kk + 2 * tq, c1 = c0 + 8;
#pragma unroll
            for (int i = 0; i < 2; i++) {
                int r0 = wm + 16 * i + gid, r1 = r0 + 8;
                Af[i][0]  = *(const uint32_t*)&Xh[r0 * CPAD + c0];
                Af[i][1]  = *(const uint32_t*)&Xh[r1 * CPAD + c0];
                Af[i][2]  = *(const uint32_t*)&Xh[r0 * CPAD + c1];
                Af[i][3]  = *(const uint32_t*)&Xh[r1 * CPAD + c1];
                Alf[i][0] = *(const uint32_t*)&Xl[r0 * CPAD + c0];
                Alf[i][1] = *(const uint32_t*)&Xl[r1 * CPAD + c0];
                Alf[i][2] = *(const uint32_t*)&Xl[r0 * CPAD + c1];
                Alf[i][3] = *(const uint32_t*)&Xl[r1 * CPAD + c1];
            }
#pragma unroll
            for (int j = 0; j < 8; j++) {
                int rn = wn + 8 * j + gid;
                Bf[j][0]  = *(const uint32_t*)&Xh[rn * CPAD + c0];
                Bf[j][1]  = *(const uint32_t*)&Xh[rn * CPAD + c1];
                Blf[j][0] = *(const uint32_t*)&Xl[rn * CPAD + c0];
                Blf[j][1] = *(const uint32_t*)&Xl[rn * CPAD + c1];
            }
#pragma unroll
            for (int j = 0; j < 8; j++)
#pragma unroll
                for (int i = 0; i < 2; i++) mma_f16(acc[i][j], Af[i], Bf[j]);
#pragma unroll
            for (int j = 0; j < 8; j++)
#pragma unroll
                for (int i = 0; i < 2; i++) mma_f16(acc[i][j], Af[i], Blf[j]);
#pragma unroll
            for (int j = 0; j < 8; j++)
#pragma unroll
                for (int i = 0; i < 2; i++) mma_f16(acc[i][j], Alf[i], Bf[j]);
        }
    }

#pragma unroll
    for (int i = 0; i < 2; i++)
#pragma unroll
        for (int j = 0; j < 8; j++) {
            int c = wm + 16 * i + gid;
            int d = wn + 8 * j + 2 * tq;
            *(float2*)&g_ecam_p[sl][b][c][d]     = make_float2(acc[i][j][0], acc[i][j][1]);
            *(float2*)&g_ecam_p[sl][b][c + 8][d] = make_float2(acc[i][j][2], acc[i][j][3]);
        }
}

// ---------------- 5) CAM negated-energy softmax ----------------
__global__ __launch_bounds__(128) void k_camsm()
{
    int b = blockIdx.x >> 7;
    int c = blockIdx.x & 127;
    int d = threadIdx.x;
    float ev = 0.f;
#pragma unroll
    for (int sl = 0; sl < 32; sl++) ev += g_ecam_p[sl][b][c][d];
    __shared__ float red[4];
    float mn = ev;
#pragma unroll
    for (int o = 16; o > 0; o >>= 1) mn = fminf(mn, __shfl_xor_sync(0xffffffffu, mn, o));
    if ((threadIdx.x & 31) == 0) red[threadIdx.x >> 5] = mn;
    __syncthreads();
    mn = fminf(fminf(red[0], red[1]), fminf(red[2], red[3]));
    float w = __expf(mn - ev);
    __syncthreads();
    float s = w;
#pragma unroll
    for (int o = 16; o > 0; o >>= 1) s += __shfl_xor_sync(0xffffffffu, s, o);
    if ((threadIdx.x & 31) == 0) red[threadIdx.x >> 5] = s;
    __syncthreads();
    s = (red[0] + red[1]) + (red[2] + red[3]);
    g_acam[b][c][d] = w / s;
}

// ---------------- 6) TIM Gram partials ----------------
__global__ __launch_bounds__(256) void k_time(const float* __restrict__ x)
{
    int c = blockIdx.x;
    int b = blockIdx.y;
    int tid = threadIdx.x;
    const float* xp = x + ((size_t)b * CC + c) * NPOS;
    float v[8][4];
#pragma unroll
    for (int t = 0; t < 8; t++) {
        float4 f = *reinterpret_cast<const float4*>(xp + t * 1024 + tid * 4);
        v[t][0] = f.x; v[t][1] = f.y; v[t][2] = f.z; v[t][3] = f.w;
    }
    float acc[36];
    int idx = 0;
#pragma unroll
    for (int t = 0; t < 8; t++)
#pragma unroll
        for (int s = t; s < 8; s++) {
            float a = 0.f;
#pragma unroll
            for (int j = 0; j < 4; j++) a += v[t][j] * v[s][j];
            acc[idx++] = a;
        }
    __shared__ float red[36][8];
    int lane = tid & 31, warp = tid >> 5;
#pragma unroll
    for (int i = 0; i < 36; i++) {
        float a = acc[i];
#pragma unroll
        for (int o = 16; o > 0; o >>= 1) a += __shfl_xor_sync(0xffffffffu, a, o);
        if (lane == 0) red[i][warp] = a;
    }
    __syncthreads();
    if (tid < 36) {
        float a = 0.f;
#pragma unroll
        for (int w = 0; w < 8; w++) a += red[tid][w];
        g_etim_p[b][c][tid] = a;
    }
}

// ---------------- 7) TIM reduce + softmax ----------------
__global__ __launch_bounds__(256) void k_timsm()
{
    __shared__ float e36[BB][36];
    int tid = threadIdx.x;
    for (int o = tid; o < BB * 36; o += 256) {
        int b = o / 36, i = o % 36;
        float a = 0.f;
        for (int c = 0; c < CC; c++) a += g_etim_p[b][c][i];
        e36[b][i] = a;
    }
    __syncthreads();
    if (tid < 64) {
        int b = tid >> 3, t = tid & 7;
        float e[8];
#pragma unroll
        for (int s = 0; s < 8; s++) {
            int lo = t < s ? t : s, hi = t < s ? s : t;
            int idx = 8 * lo - lo * (lo - 1) / 2 + (hi - lo);
            e[s] = e36[b][idx];
        }
        float mn = e[0];
#pragma unroll
        for (int s = 1; s < 8; s++) mn = fminf(mn, e[s]);
        float w[8], sum = 0.f;
#pragma unroll
        for (int s = 0; s < 8; s++) { w[s] = __expf(mn - e[s]); sum += w[s]; }
#pragma unroll
        for (int s = 0; s < 8; s++) g_atim[b][t][s] = w[s] / sum;
    }
}

// ---------------- 8) base: out = 3x + gc*(a_cam@xc) + gt*tim ----------------
__global__ __launch_bounds__(256) void k_base(
    const float* __restrict__ x,
    const float* __restrict__ gcp, const float* __restrict__ gtp,
    float* __restrict__ out)
{
    int b   = blockIdx.z;
    int c0  = blockIdx.y * 32;
    int hw0 = blockIdx.x * 32;
    __shared__ float As[32][33];
    __shared__ float Xs[32][8][33];
    __shared__ float at8[8][8];
    int tid = threadIdx.x;
    int hw_l = tid & 31, cg = tid >> 5;
    if (tid < 64) at8[tid >> 3][tid & 7] = g_atim[b][tid >> 3][tid & 7];
    float acc[4][8] = {};
    const float* xb = x + (size_t)b * (CC * NPOS);

    for (int kc = 0; kc < CC; kc += 32) {
#pragma unroll
        for (int q = 0; q < 4; q++) {
            int e = tid + q * 256;
            int i = e >> 5, k = e & 31;
            As[i][k] = g_acam[b][c0 + i][kc + k];
        }
#pragma unroll
        for (int q = 0; q < 32; q++) {
            int e = tid + q * 256;
            int k = e >> 8, t = (e >> 5) & 7, hw = e & 31;
            Xs[k][t][hw] = xb[(size_t)(kc + k) * NPOS + t * 1024 + hw0 + hw];
        }
        __syncthreads();
#pragma unroll
        for (int k = 0; k < 32; k++) {
            float av[4], xv[8];
#pragma unroll
            for (int j = 0; j < 4; j++) av[j] = As[cg + 8 * j][k];
#pragma unroll
            for (int t = 0; t < 8; t++) xv[t] = Xs[k][t][hw_l];
#pragma unroll
            for (int j = 0; j < 4; j++)
#pragma unroll
                for (int t = 0; t < 8; t++) acc[j][t] += av[j] * xv[t];
        }
        __syncthreads();
    }

    float gc = gcp[0], gt = gtp[0];
#pragma unroll
    for (int j = 0; j < 4; j++) {
        int c = c0 + cg + 8 * j;
        const float* xc = xb + (size_t)c * NPOS + hw0 + hw_l;
        float xrow[8];
#pragma unroll
        for (int s = 0; s < 8; s++) xrow[s] = xc[s * 1024];
        float* oc = out + (size_t)b * (CC * NPOS) + (size_t)c * NPOS + hw0 + hw_l;
#pragma unroll
        for (int t = 0; t < 8; t++) {
            float tim = 0.f;
#pragma unroll
            for (int s = 0; s < 8; s++) tim += at8[t][s] * xrow[s];
            oc[t * 1024] = 3.f * xrow[t] + gc * acc[j][t] + gt * tim;
        }
    }
}

// ---------------- 9) PAM GEMM: single-term fp16, cp.async 2-stage (round-10 form) ----------------
#define PAD 40
#define PAM_TILE 5120
#define PAM_STAGE (2 * PAM_TILE)
#define PAM_SMEM_BYTES (2 * PAM_STAGE * 2)
__global__ __launch_bounds__(256, 2) void k_pam_mma(const float* __restrict__ gpp,
                                                    float* __restrict__ out)
{
    extern __shared__ __half smp[];
    uint32_t smb = smem_to_u32(smp);

    int tid = threadIdx.x;
    int b  = blockIdx.z;
    int r0 = blockIdx.y * 128;
    int n0 = blockIdx.x * 128;
    int wid = tid >> 5, lane = tid & 31;
    int gid = lane >> 2, tq = lane & 3;
    int wm = (wid & 1) * 64;
    int wn = (wid >> 1) * 32;

    const __half* Asp = &g_vf_s[b][0][0];
    const __half* Bsp = &g_attn_s[b][0][0];

    float acc[4][4][4] = {};

    auto stage_load = [&](int st, int kc) {
#pragma unroll
        for (int q = 0; q < 2; q++) {
            int e = tid + q * 256;
            int row = e >> 2, c4 = e & 3;
            uint32_t so = smb + (uint32_t)(st * PAM_STAGE + row * PAD + c4 * 8) * 2;
            size_t gA = (size_t)(r0 + row) * 1024 + kc + c4 * 8;
            size_t gB = (size_t)(n0 + row) * 1024 + kc + c4 * 8;
            cp16(so,                Asp + gA);
            cp16(so + PAM_TILE * 2, Bsp + gB);
        }
        CP_COMMIT();
    };

    stage_load(0, 0);

    for (int it = 0; it < 32; it++) {
        int st = it & 1;
        if (it < 31) { stage_load(st ^ 1, (it + 1) * 32); CP_WAIT(1); }
        else         { CP_WAIT(0); }
        __syncthreads();

        const __half* sAs = smp + st * PAM_STAGE;
        const __half* sBs = sAs + PAM_TILE;

#pragma unroll
        for (int ks = 0; ks < 32; ks += 16) {
            uint32_t Af[4][4], Bf[4][2];
            int col = ks + tq * 2;
#pragma unroll
            for (int i = 0; i < 4; i++) {
                int row = wm + 16 * i + gid;
                Af[i][0] = *(const uint32_t*)&sAs[row * PAD + col];
                Af[i][1] = *(const uint32_t*)&sAs[(row + 8) * PAD + col];
                Af[i][2] = *(const uint32_t*)&sAs[row * PAD + col + 8];
                Af[i][3] = *(const uint32_t*)&sAs[(row + 8) * PAD + col + 8];
            }
#pragma unroll
            for (int j = 0; j < 4; j++) {
                int nrow = wn + 8 * j + gid;
                Bf[j][0] = *(const uint32_t*)&sBs[nrow * PAD + col];
                Bf[j][1] = *(const uint32_t*)&sBs[nrow * PAD + col + 8];
            }
#pragma unroll
            for (int j = 0; j < 4; j++)
#pragma unroll
                for (int i = 0; i < 4; i++) mma_f16(acc[i][j], Af[i], Bf[j]);
        }
        __syncthreads();
    }

    float gpv = gpp[0];
    float* ob = out + (size_t)b * (CT * HWD);
#pragma unroll
    for (int i = 0; i < 4; i++) {
#pragma unroll
        for (int j = 0; j < 4; j++) {
            int r = r0 + wm + 16 * i + gid;
            int n = n0 + wn + 8 * j + tq * 2;
            float2* p0 = (float2*)(ob + (size_t)r * 1024 + n);
            float2 v0 = *p0;
            v0.x += gpv * acc[i][j][0];
            v0.y += gpv * acc[i][j][1];
            *p0 = v0;
            float2* p1 = (float2*)(ob + (size_t)(r + 8) * 1024 + n);
            float2 v1 = *p1;
            v1.x += gpv * acc[i][j][2];
            v1.y += gpv * acc[i][j][3];
            *p1 = v1;
        }
    }
}

// ---------------- launch ----------------
extern "C" void kernel_launch(void* const* d_in, const int* in_sizes, int n_in,
                              void* d_out, int out_size)
{
    const float* x  = (const float*)d_in[0];
    const float* Wq = (const float*)d_in[1];
    const float* bq = (const float*)d_in[2];
    const float* Wk = (const float*)d_in[3];
    const float* bk = (const float*)d_in[4];
    const float* Wv = (const float*)d_in[5];
    const float* bv = (const float*)d_in[6];
    const float* gp = (const float*)d_in[7];
    const float* gc = (const float*)d_in[8];
    const float* gt = (const float*)d_in[9];
    float* out = (float*)d_out;

    static int attrs_set = 0;
    if (!attrs_set) {
        cudaFuncSetAttribute(k_qkv_tc, cudaFuncAttributeMaxDynamicSharedMemorySize, QKV_SMEM_BYTES);
        cudaFuncSetAttribute(k_energy_tc, cudaFuncAttributeMaxDynamicSharedMemorySize, EN_SMEM_BYTES);
        cudaFuncSetAttribute(k_came_tc, cudaFuncAttributeMaxDynamicSharedMemorySize, CAME_SMEM_BYTES);
        cudaFuncSetAttribute(k_pam_mma, cudaFuncAttributeMaxDynamicSharedMemorySize, PAM_SMEM_BYTES);
        attrs_set = 1;
    }

    k_qkv_tc<<<dim3(64, 3, 8), 256, QKV_SMEM_BYTES>>>(x, Wq, bq, Wk, bk, Wv, bv);
    k_energy_tc<<<dim3(8, 8, 8), 256, EN_SMEM_BYTES>>>();
    k_softmax<<<8192, 256>>>();
    k_came_tc<<<256, 256, CAME_SMEM_BYTES>>>(x);
    k_camsm<<<1024, 128>>>();
    k_time<<<dim3(128, 8), 256>>>(x);
    k_timsm<<<1, 256>>>();
    k_base<<<dim3(32, 4, 8), 256>>>(x, gc, gt, out);
    k_pam_mma<<<dim3(8, 8, 8), 256, PAM_SMEM_BYTES>>>(gp, out);
}

// round 13
// speedup vs baseline: 1.1353x; 1.1133x over previous
#include <cuda_runtime.h>
#include <cuda_fp16.h>
#include <math.h>
#include <stdint.h>

#define BB 8
#define CC 128
#define TT 8
#define HWD 1024
#define NPOS 8192
#define CT 1024

// ---------------- scratch ----------------
__device__ float g_qf[BB][128][HWD];
__device__ float g_kf[BB][128][HWD];
__device__ __half g_vf_s[BB][CT][HWD];
__device__ float g_attn[BB][HWD][HWD];
__device__ __half g_attn_s[BB][HWD][HWD];
__device__ float g_ecam_p[32][BB][CC][CC];
__device__ float g_acam[BB][CC][CC];
__device__ float g_etim_p[BB][CC][36];
__device__ float g_atim[BB][TT][TT];

// ---------------- helpers ----------------
__device__ __forceinline__ void mma_f16(float* c, const uint32_t* a, const uint32_t* b) {
    asm volatile(
        "mma.sync.aligned.m16n8k16.row.col.f32.f16.f16.f32 "
        "{%0,%1,%2,%3}, {%4,%5,%6,%7}, {%8,%9}, {%0,%1,%2,%3};"
        : "+f"(c[0]), "+f"(c[1]), "+f"(c[2]), "+f"(c[3])
        : "r"(a[0]), "r"(a[1]), "r"(a[2]), "r"(a[3]), "r"(b[0]), "r"(b[1]));
}
__device__ __forceinline__ void split_h(float a, __half& h, __half& l) {
    h = __float2half_rn(a);
    l = __float2half_rn(a - __half2float(h));
}
__device__ __forceinline__ uint32_t packh(__half a, __half b) {
    return ((uint32_t)__half_as_ushort(b) << 16) | __half_as_ushort(a);
}
// pack two k-adjacent rows (a = even k, b = odd k) into hi/lo half2 vectors
__device__ __forceinline__ void pack2rows(float4 a, float4 b, uint4& hi, uint4& lo) {
    __half ha, la, hb, lb;
    split_h(a.x, ha, la); split_h(b.x, hb, lb);
    hi.x = packh(ha, hb); lo.x = packh(la, lb);
    split_h(a.y, ha, la); split_h(b.y, hb, lb);
    hi.y = packh(ha, hb); lo.y = packh(la, lb);
    split_h(a.z, ha, la); split_h(b.z, hb, lb);
    hi.z = packh(ha, hb); lo.z = packh(la, lb);
    split_h(a.w, ha, la); split_h(b.w, hb, lb);
    hi.w = packh(ha, hb); lo.w = packh(la, lb);
}
__device__ __forceinline__ uint32_t smem_to_u32(const void* p) {
    uint32_t a;
    asm("{ .reg .u64 t; cvta.to.shared.u64 t, %1; cvt.u32.u64 %0, t; }" : "=r"(a) : "l"(p));
    return a;
}
__device__ __forceinline__ void cp16(uint32_t s, const void* g) {
    asm volatile("cp.async.cg.shared.global [%0], [%1], 16;"
                 :: "r"(s), "l"(__cvta_generic_to_global(g)) : "memory");
}
#define CP_COMMIT() asm volatile("cp.async.commit_group;" ::: "memory")
#define CP_WAIT(n)  asm volatile("cp.async.wait_group %0;" :: "n"(n) : "memory")

// ---------------- 1) fused q/k/v projection via fp16x3 MMA ----------------
// A = W rows packed [row][kp] (stride 20 u32); B = x packed [kp][n] (stride 136 u32)
#define QKV_SMEM_BYTES ((2 * 64 * 20 + 2 * 16 * 136) * 4)
__global__ __launch_bounds__(256) void k_qkv_tc(
    const float* __restrict__ x,
    const float* __restrict__ Wq, const float* __restrict__ bq,
    const float* __restrict__ Wk, const float* __restrict__ bk,
    const float* __restrict__ Wv, const float* __restrict__ bv)
{
    extern __shared__ uint32_t qsm[];
    uint32_t* PWh = qsm;                       // 64 x 20
    uint32_t* PWl = qsm + 64 * 20;
    uint32_t* PBh = qsm + 2 * 64 * 20;         // 16 x 136
    uint32_t* PBl = PBh + 16 * 136;

    int b     = blockIdx.z;
    int rows0 = blockIdx.y * 64;
    int pos0  = blockIdx.x * 128;
    int tid = threadIdx.x, wid = tid >> 5, lane = tid & 31;
    int gid = lane >> 2, tq = lane & 3;
    int wm = (wid >> 1) * 16;
    int wn = (wid & 1) * 64;
    const float* xb = x + (size_t)b * (CC * NPOS);

    float acc[8][4] = {};

    for (int kc = 0; kc < 128; kc += 32) {
        // W tile: 64 rows x 32 k, packed within row
#pragma unroll
        for (int q = 0; q < 2; q++) {
            int e = tid + q * 256;
            int row = e >> 3, kg = e & 7;       // kg: group of 4 k
            int r = rows0 + row;
            float4 v = make_float4(0.f, 0.f, 0.f, 0.f);
            if (r < 16)       v = *(const float4*)(Wq + r * 128 + kc + kg * 4);
            else if (r < 32)  v = *(const float4*)(Wk + (r - 16) * 128 + kc + kg * 4);
            else if (r < 160) v = *(const float4*)(Wv + (r - 32) * 128 + kc + kg * 4);
            __half h0, l0, h1, l1, h2, l2, h3, l3;
            split_h(v.x, h0, l0); split_h(v.y, h1, l1);
            split_h(v.z, h2, l2); split_h(v.w, h3, l3);
            uint2 hp = make_uint2(packh(h0, h1), packh(h2, h3));
            uint2 lp = make_uint2(packh(l0, l1), packh(l2, l3));
            *(uint2*)&PWh[row * 20 + kg * 2] = hp;
            *(uint2*)&PWl[row * 20 + kg * 2] = lp;
        }
        // x tile: 32 k x 128 n -> packed pairs across k-rows: PB[kp][n]
#pragma unroll
        for (int q = 0; q < 2; q++) {
            int e = tid + q * 256;
            int kp = e >> 5, ng = e & 31;
            const float* r0p = xb + (size_t)(kc + 2 * kp) * NPOS + pos0 + ng * 4;
            float4 v0 = *(const float4*)r0p;
            float4 v1 = *(const float4*)(r0p + NPOS);
            uint4 hi, lo;
            pack2rows(v0, v1, hi, lo);
            *(uint4*)&PBh[kp * 136 + ng * 4] = hi;
            *(uint4*)&PBl[kp * 136 + ng * 4] = lo;
        }
        __syncthreads();
#pragma unroll
        for (int kk2 = 0; kk2 < 16; kk2 += 8) {
            uint32_t Af[4], Alf[4], Bf[8][2], Blf[8][2];
            int row = wm + gid;
            Af[0]  = PWh[row * 20 + kk2 + tq];
            Af[1]  = PWh[(row + 8) * 20 + kk2 + tq];
            Af[2]  = PWh[row * 20 + kk2 + tq + 4];
            Af[3]  = PWh[(row + 8) * 20 + kk2 + tq + 4];
            Alf[0] = PWl[row * 20 + kk2 + tq];
            Alf[1] = PWl[(row + 8) * 20 + kk2 + tq];
            Alf[2] = PWl[row * 20 + kk2 + tq + 4];
            Alf[3] = PWl[(row + 8) * 20 + kk2 + tq + 4];
#pragma unroll
            for (int j = 0; j < 8; j++) {
                int n = wn + 8 * j + gid;
                Bf[j][0]  = PBh[(kk2 + tq) * 136 + n];
                Bf[j][1]  = PBh[(kk2 + tq + 4) * 136 + n];
                Blf[j][0] = PBl[(kk2 + tq) * 136 + n];
                Blf[j][1] = PBl[(kk2 + tq + 4) * 136 + n];
            }
#pragma unroll
            for (int j = 0; j < 8; j++) mma_f16(acc[j], Af,  Bf[j]);
#pragma unroll
            for (int j = 0; j < 8; j++) mma_f16(acc[j], Af,  Blf[j]);
#pragma unroll
            for (int j = 0; j < 8; j++) mma_f16(acc[j], Alf, Bf[j]);
        }
        __syncthreads();
    }

    int t   = pos0 >> 10;
    int hw0 = pos0 & 1023;
#pragma unroll
    for (int j = 0; j < 8; j++) {
        int hw = hw0 + wn + 8 * j + 2 * tq;
#pragma unroll
        for (int half = 0; half < 2; half++) {
            int r = rows0 + wm + gid + half * 8;
            if (r >= 160) continue;
            float v0 = acc[j][half * 2 + 0];
            float v1 = acc[j][half * 2 + 1];
            if (r < 16) {
                float bias = bq[r];
                *(float2*)&g_qf[b][r * TT + t][hw] = make_float2(v0 + bias, v1 + bias);
            } else if (r < 32) {
                float bias = bk[r - 16];
                *(float2*)&g_kf[b][(r - 16) * TT + t][hw] = make_float2(v0 + bias, v1 + bias);
            } else {
                float bias = bv[r - 32];
                int row = (r - 32) * TT + t;
                *(uint32_t*)&g_vf_s[b][row][hw] =
                    packh(__float2half_rn(v0 + bias), __float2half_rn(v1 + bias));
            }
        }
    }
}

// ---------------- 2) PAM energy via fp16x3 MMA (packed k-pairs) ----------------
#define EN_SMEM_BYTES (4 * 16 * 136 * 4)
__global__ __launch_bounds__(256, 2) void k_energy_tc()
{
    extern __shared__ uint32_t esm[];
    uint32_t* Ah = esm;                 // qf packed [kp][n] 16x136
    uint32_t* Al = esm + 16 * 136;
    uint32_t* Bh = esm + 2 * 16 * 136;  // kf packed [kp][m]
    uint32_t* Bl = esm + 3 * 16 * 136;

    int b  = blockIdx.z;
    int n0 = blockIdx.y * 128;
    int m0 = blockIdx.x * 128;
    int tid = threadIdx.x, wid = tid >> 5, lane = tid & 31;
    int gid = lane >> 2, tq = lane & 3;
    int wm = (wid >> 1) * 32;   // n-dim (M of MMA)
    int wn = (wid & 1) * 64;    // m-dim (N of MMA)

    float acc[2][8][4] = {};

    for (int kc = 0; kc < 128; kc += 32) {
#pragma unroll
        for (int q = 0; q < 2; q++) {
            int e = tid + q * 256;
            int kp = e >> 5, ng = e & 31;
            const float* qa = &g_qf[b][kc + 2 * kp][n0 + ng * 4];
            const float* kb = &g_kf[b][kc + 2 * kp][m0 + ng * 4];
            float4 va0 = *(const float4*)qa;
            float4 va1 = *(const float4*)(qa + HWD);
            float4 vb0 = *(const float4*)kb;
            float4 vb1 = *(const float4*)(kb + HWD);
            uint4 hi, lo;
            pack2rows(va0, va1, hi, lo);
            *(uint4*)&Ah[kp * 136 + ng * 4] = hi;
            *(uint4*)&Al[kp * 136 + ng * 4] = lo;
            pack2rows(vb0, vb1, hi, lo);
            *(uint4*)&Bh[kp * 136 + ng * 4] = hi;
            *(uint4*)&Bl[kp * 136 + ng * 4] = lo;
        }
        __syncthreads();
#pragma unroll
        for (int kk2 = 0; kk2 < 16; kk2 += 8) {
            uint32_t Af[2][4], Alf[2][4], Bf[8][2], Blf[8][2];
#pragma unroll
            for (int i = 0; i < 2; i++) {
                int m = wm + 16 * i + gid;
                Af[i][0]  = Ah[(kk2 + tq) * 136 + m];
                Af[i][1]  = Ah[(kk2 + tq) * 136 + m + 8];
                Af[i][2]  = Ah[(kk2 + tq + 4) * 136 + m];
                Af[i][3]  = Ah[(kk2 + tq + 4) * 136 + m + 8];
                Alf[i][0] = Al[(kk2 + tq) * 136 + m];
                Alf[i][1] = Al[(kk2 + tq) * 136 + m + 8];
                Alf[i][2] = Al[(kk2 + tq + 4) * 136 + m];
                Alf[i][3] = Al[(kk2 + tq + 4) * 136 + m + 8];
            }
#pragma unroll
            for (int j = 0; j < 8; j++) {
                int n = wn + 8 * j + gid;
                Bf[j][0]  = Bh[(kk2 + tq) * 136 + n];
                Bf[j][1]  = Bh[(kk2 + tq + 4) * 136 + n];
                Blf[j][0] = Bl[(kk2 + tq) * 136 + n];
                Blf[j][1] = Bl[(kk2 + tq + 4) * 136 + n];
            }
#pragma unroll
            for (int j = 0; j < 8; j++)
#pragma unroll
                for (int i = 0; i < 2; i++) mma_f16(acc[i][j], Af[i], Bf[j]);
#pragma unroll
            for (int j = 0; j < 8; j++)
#pragma unroll
                for (int i = 0; i < 2; i++) mma_f16(acc[i][j], Af[i], Blf[j]);
#pragma unroll
            for (int j = 0; j < 8; j++)
#pragma unroll
                for (int i = 0; i < 2; i++) mma_f16(acc[i][j], Alf[i], Bf[j]);
        }
        __syncthreads();
    }

#pragma unroll
    for (int i = 0; i < 2; i++)
#pragma unroll
        for (int j = 0; j < 8; j++) {
            int n = n0 + wm + 16 * i + gid;
            int m = m0 + wn + 8 * j + 2 * tq;
            *(float2*)&g_attn[b][n][m]     = make_float2(acc[i][j][0], acc[i][j][1]);
            *(float2*)&g_attn[b][n + 8][m] = make_float2(acc[i][j][2], acc[i][j][3]);
        }
}

// ---------------- 3) softmax -> single fp16 (vectorized) ----------------
__global__ __launch_bounds__(256) void k_softmax()
{
    int row = blockIdx.x;
    int tid = threadIdx.x;
    const float4* e4 = (const float4*)(&g_attn[0][0][0] + (size_t)row * 1024);
    float4 v = e4[tid];
    float m = fmaxf(fmaxf(v.x, v.y), fmaxf(v.z, v.w));
    __shared__ float red[8];
#pragma unroll
    for (int o = 16; o > 0; o >>= 1) m = fmaxf(m, __shfl_xor_sync(0xffffffffu, m, o));
    if ((tid & 31) == 0) red[tid >> 5] = m;
    __syncthreads();
    m = red[0];
#pragma unroll
    for (int j = 1; j < 8; j++) m = fmaxf(m, red[j]);
    v.x = __expf(v.x - m); v.y = __expf(v.y - m);
    v.z = __expf(v.z - m); v.w = __expf(v.w - m);
    float s = (v.x + v.y) + (v.z + v.w);
    __syncthreads();
#pragma unroll
    for (int o = 16; o > 0; o >>= 1) s += __shfl_xor_sync(0xffffffffu, s, o);
    if ((tid & 31) == 0) red[tid >> 5] = s;
    __syncthreads();
    s = red[0];
#pragma unroll
    for (int j = 1; j < 8; j++) s += red[j];
    float inv = 1.f / s;
    v.x *= inv; v.y *= inv; v.z *= inv; v.w *= inv;

    uint2 hp;
    hp.x = packh(__float2half_rn(v.x), __float2half_rn(v.y));
    hp.y = packh(__float2half_rn(v.z), __float2half_rn(v.w));
    ((uint2*)(&g_attn_s[0][0][0] + (size_t)row * 1024))[tid] = hp;
}

// ---------------- 4) CAM energy fp16x3 Gram: cp.async raw staging + split pass ----------------
#define CPAD 40
#define CAME_SMEM_BYTES (32768 + 2 * 128 * CPAD * 2)
__global__ __launch_bounds__(256, 2) void k_came_tc(const float* __restrict__ x)
{
    extern __shared__ char csm[];
    float* raw = (float*)csm;
    __half* Xh = (__half*)(csm + 32768);
    __half* Xl = (__half*)(csm + 32768 + 128 * CPAD * 2);
    uint32_t rawb = smem_to_u32(raw);

    int b  = blockIdx.x >> 5;
    int sl = blockIdx.x & 31;
    int tid = threadIdx.x, wid = tid >> 5, lane = tid & 31;
    int gid = lane >> 2, tq = lane & 3;
    int wm = (wid >> 1) * 32;
    int wn = (wid & 1) * 64;
    const float* xb = x + (size_t)b * (CC * NPOS) + sl * 256;

    float acc[2][8][4] = {};

    auto load_raw = [&](int st, int kc) {
#pragma unroll
        for (int q = 0; q < 4; q++) {
            int e = tid + q * 256;
            int row = e >> 3, c4 = e & 7;
            cp16(rawb + (uint32_t)(st * 4096 + row * 32 + c4 * 4) * 4,
                 xb + (size_t)row * NPOS + kc + c4 * 4);
        }
        CP_COMMIT();
    };

    load_raw(0, 0);

    for (int it = 0; it < 8; it++) {
        int st = it & 1;
        if (it < 7) { load_raw(st ^ 1, (it + 1) * 32); CP_WAIT(1); }
        else        { CP_WAIT(0); }
        __syncthreads();

#pragma unroll
        for (int q = 0; q < 4; q++) {
            int e = tid + q * 256;
            int row = e >> 3, c4 = e & 7;
            float4 v = *(const float4*)&raw[st * 4096 + row * 32 + c4 * 4];
            __half hx, lx, hy, ly, hz, lz, hw, lw;
            split_h(v.x, hx, lx); split_h(v.y, hy, ly);
            split_h(v.z, hz, lz); split_h(v.w, hw, lw);
            uint2 hp, lp;
            hp.x = packh(hx, hy); hp.y = packh(hz, hw);
            lp.x = packh(lx, ly); lp.y = packh(lz, lw);
            *(uint2*)&Xh[row * CPAD + c4 * 4] = hp;
            *(uint2*)&Xl[row * CPAD + c4 * 4] = lp;
        }
        __syncthreads();

#pragma unroll
        for (int kk = 0; kk < 32; kk += 16) {
            uint32_t Af[2][4], Alf[2][4], Bf[8][2], Blf[8][2];
            int c0 = kk + 2 * tq, c1 = c0 + 8;
#pragma unroll
            for (int i = 0; i < 2; i++) {
                int r0 = wm + 16 * i + gid, r1 = r0 + 8;
                Af[i][0]  = *(const uint32_t*)&Xh[r0 * CPAD + c0];
                Af[i][1]  = *(const uint32_t*)&Xh[r1 * CPAD + c0];
                Af[i][2]  = *(const uint32_t*)&Xh[r0 * CPAD + c1];
                Af[i][3]  = *(const uint32_t*)&Xh[r1 * CPAD + c1];
                Alf[i][0] = *(const uint32_t*)&Xl[r0 * CPAD + c0];
                Alf[i][1] = *(const uint32_t*)&Xl[r1 * CPAD + c0];
                Alf[i][2] = *(const uint32_t*)&Xl[r0 * CPAD + c1];
                Alf[i][3] = *(const uint32_t*)&Xl[r1 * CPAD + c1];
            }
#pragma unroll
            for (int j = 0; j < 8; j++) {
                int rn = wn + 8 * j + gid;
                Bf[j][0]  = *(const uint32_t*)&Xh[rn * CPAD + c0];
                Bf[j][1]  = *(const uint32_t*)&Xh[rn * CPAD + c1];
                Blf[j][0] = *(const uint32_t*)&Xl[rn * CPAD + c0];
                Blf[j][1] = *(const uint32_t*)&Xl[rn * CPAD + c1];
            }
#pragma unroll
            for (int j = 0; j < 8; j++)
#pragma unroll
                for (int i = 0; i < 2; i++) mma_f16(acc[i][j], Af[i], Bf[j]);
#pragma unroll
            for (int j = 0; j < 8; j++)
#pragma unroll
                for (int i = 0; i < 2; i++) mma_f16(acc[i][j], Af[i], Blf[j]);
#pragma unroll
            for (int j = 0; j < 8; j++)
#pragma unroll
                for (int i = 0; i < 2; i++) mma_f16(acc[i][j], Alf[i], Bf[j]);
        }
    }

#pragma unroll
    for (int i = 0; i < 2; i++)
#pragma unroll
        for (int j = 0; j < 8; j++) {
            int c = wm + 16 * i + gid;
            int d = wn + 8 * j + 2 * tq;
            *(float2*)&g_ecam_p[sl][b][c][d]     = make_float2(acc[i][j][0], acc[i][j][1]);
            *(float2*)&g_ecam_p[sl][b][c + 8][d] = make_float2(acc[i][j][2], acc[i][j][3]);
        }
}

// ---------------- 5) CAM negated-energy softmax ----------------
__global__ __launch_bounds__(128) void k_camsm()
{
    int b = blockIdx.x >> 7;
    int c = blockIdx.x & 127;
    int d = threadIdx.x;
    float ev = 0.f;
#pragma unroll
    for (int sl = 0; sl < 32; sl++) ev += g_ecam_p[sl][b][c][d];
    __shared__ float red[4];
    float mn = ev;
#pragma unroll
    for (int o = 16; o > 0; o >>= 1) mn = fminf(mn, __shfl_xor_sync(0xffffffffu, mn, o));
    if ((threadIdx.x & 31) == 0) red[threadIdx.x >> 5] = mn;
    __syncthreads();
    mn = fminf(fminf(red[0], red[1]), fminf(red[2], red[3]));
    float w = __expf(mn - ev);
    __syncthreads();
    float s = w;
#pragma unroll
    for (int o = 16; o > 0; o >>= 1) s += __shfl_xor_sync(0xffffffffu, s, o);
    if ((threadIdx.x & 31) == 0) red[threadIdx.x >> 5] = s;
    __syncthreads();
    s = (red[0] + red[1]) + (red[2] + red[3]);
    g_acam[b][c][d] = w / s;
}

// ---------------- 6) TIM Gram partials ----------------
__global__ __launch_bounds__(256) void k_time(const float* __restrict__ x)
{
    int c = blockIdx.x;
    int b = blockIdx.y;
    int tid = threadIdx.x;
    const float* xp = x + ((size_t)b * CC + c) * NPOS;
    float v[8][4];
#pragma unroll
    for (int t = 0; t < 8; t++) {
        float4 f = *reinterpret_cast<const float4*>(xp + t * 1024 + tid * 4);
        v[t][0] = f.x; v[t][1] = f.y; v[t][2] = f.z; v[t][3] = f.w;
    }
    float acc[36];
    int idx = 0;
#pragma unroll
    for (int t = 0; t < 8; t++)
#pragma unroll
        for (int s = t; s < 8; s++) {
            float a = 0.f;
#pragma unroll
            for (int j = 0; j < 4; j++) a += v[t][j] * v[s][j];
            acc[idx++] = a;
        }
    __shared__ float red[36][8];
    int lane = tid & 31, warp = tid >> 5;
#pragma unroll
    for (int i = 0; i < 36; i++) {
        float a = acc[i];
#pragma unroll
        for (int o = 16; o > 0; o >>= 1) a += __shfl_xor_sync(0xffffffffu, a, o);
        if (lane == 0) red[i][warp] = a;
    }
    __syncthreads();
    if (tid < 36) {
        float a = 0.f;
#pragma unroll
        for (int w = 0; w < 8; w++) a += red[tid][w];
        g_etim_p[b][c][tid] = a;
    }
}

// ---------------- 7) TIM reduce + softmax ----------------
__global__ __launch_bounds__(256) void k_timsm()
{
    __shared__ float e36[BB][36];
    int tid = threadIdx.x;
    for (int o = tid; o < BB * 36; o += 256) {
        int b = o / 36, i = o % 36;
        float a = 0.f;
        for (int c = 0; c < CC; c++) a += g_etim_p[b][c][i];
        e36[b][i] = a;
    }
    __syncthreads();
    if (tid < 64) {
        int b = tid >> 3, t = tid & 7;
        float e[8];
#pragma unroll
        for (int s = 0; s < 8; s++) {
            int lo = t < s ? t : s, hi = t < s ? s : t;
            int idx = 8 * lo - lo * (lo - 1) / 2 + (hi - lo);
            e[s] = e36[b][idx];
        }
        float mn = e[0];
#pragma unroll
        for (int s = 1; s < 8; s++) mn = fminf(mn, e[s]);
        float w[8], sum = 0.f;
#pragma unroll
        for (int s = 0; s < 8; s++) { w[s] = __expf(mn - e[s]); sum += w[s]; }
#pragma unroll
        for (int s = 0; s < 8; s++) g_atim[b][t][s] = w[s] / sum;
    }
}

// ---------------- 8) base: out = 3x + gc*(a_cam@xc) + gt*tim ----------------
__global__ __launch_bounds__(256) void k_base(
    const float* __restrict__ x,
    const float* __restrict__ gcp, const float* __restrict__ gtp,
    float* __restrict__ out)
{
    int b   = blockIdx.z;
    int c0  = blockIdx.y * 32;
    int hw0 = blockIdx.x * 32;
    __shared__ float As[32][33];
    __shared__ float Xs[32][8][33];
    __shared__ float at8[8][8];
    int tid = threadIdx.x;
    int hw_l = tid & 31, cg = tid >> 5;
    if (tid < 64) at8[tid >> 3][tid & 7] = g_atim[b][tid >> 3][tid & 7];
    float acc[4][8] = {};
    const float* xb = x + (size_t)b * (CC * NPOS);

    for (int kc = 0; kc < CC; kc += 32) {
#pragma unroll
        for (int q = 0; q < 4; q++) {
            int e = tid + q * 256;
            int i = e >> 5, k = e & 31;
            As[i][k] = g_acam[b][c0 + i][kc + k];
        }
#pragma unroll
        for (int q = 0; q < 32; q++) {
            int e = tid + q * 256;
            int k = e >> 8, t = (e >> 5) & 7, hw = e & 31;
            Xs[k][t][hw] = xb[(size_t)(kc + k) * NPOS + t * 1024 + hw0 + hw];
        }
        __syncthreads();
#pragma unroll
        for (int k = 0; k < 32; k++) {
            float av[4], xv[8];
#pragma unroll
            for (int j = 0; j < 4; j++) av[j] = As[cg + 8 * j][k];
#pragma unroll
            for (int t = 0; t < 8; t++) xv[t] = Xs[k][t][hw_l];
#pragma unroll
            for (int j = 0; j < 4; j++)
#pragma unroll
                for (int t = 0; t < 8; t++) acc[j][t] += av[j] * xv[t];
        }
        __syncthreads();
    }

    float gc = gcp[0], gt = gtp[0];
#pragma unroll
    for (int j = 0; j < 4; j++) {
        int c = c0 + cg + 8 * j;
        const float* xc = xb + (size_t)c * NPOS + hw0 + hw_l;
        float xrow[8];
#pragma unroll
        for (int s = 0; s < 8; s++) xrow[s] = xc[s * 1024];
        float* oc = out + (size_t)b * (CC * NPOS) + (size_t)c * NPOS + hw0 + hw_l;
#pragma unroll
        for (int t = 0; t < 8; t++) {
            float tim = 0.f;
#pragma unroll
            for (int s = 0; s < 8; s++) tim += at8[t][s] * xrow[s];
            oc[t * 1024] = 3.f * xrow[t] + gc * acc[j][t] + gt * tim;
        }
    }
}

// ---------------- 9) PAM GEMM: single-term fp16, cp.async 2-stage ----------------
#define PAD 40
#define PAM_TILE 5120
#define PAM_STAGE (2 * PAM_TILE)
#define PAM_SMEM_BYTES (2 * PAM_STAGE * 2)
__global__ __launch_bounds__(256, 2) void k_pam_mma(const float* __restrict__ gpp,
                                                    float* __restrict__ out)
{
    extern __shared__ __half smp[];
    uint32_t smb = smem_to_u32(smp);

    int tid = threadIdx.x;
    int b  = blockIdx.z;
    int r0 = blockIdx.y * 128;
    int n0 = blockIdx.x * 128;
    int wid = tid >> 5, lane = tid & 31;
    int gid = lane >> 2, tq = lane & 3;
    int wm = (wid & 1) * 64;
    int wn = (wid >> 1) * 32;

    const __half* Asp = &g_vf_s[b][0][0];
    const __half* Bsp = &g_attn_s[b][0][0];

    float acc[4][4][4] = {};

    auto stage_load = [&](int st, int kc) {
#pragma unroll
        for (int q = 0; q < 2; q++) {
            int e = tid + q * 256;
            int row = e >> 2, c4 = e & 3;
            uint32_t so = smb + (uint32_t)(st * PAM_STAGE + row * PAD + c4 * 8) * 2;
            size_t gA = (size_t)(r0 + row) * 1024 + kc + c4 * 8;
            size_t gB = (size_t)(n0 + row) * 1024 + kc + c4 * 8;
            cp16(so,                Asp + gA);
            cp16(so + PAM_TILE * 2, Bsp + gB);
        }
        CP_COMMIT();
    };

    stage_load(0, 0);

    for (int it = 0; it < 32; it++) {
        int st = it & 1;
        if (it < 31) { stage_load(st ^ 1, (it + 1) * 32); CP_WAIT(1); }
        else         { CP_WAIT(0); }
        __syncthreads();

        const __half* sAs = smp + st * PAM_STAGE;
        const __half* sBs = sAs + PAM_TILE;

#pragma unroll
        for (int ks = 0; ks < 32; ks += 16) {
            uint32_t Af[4][4], Bf[4][2];
            int col = ks + tq * 2;
#pragma unroll
            for (int i = 0; i < 4; i++) {
                int row = wm + 16 * i + gid;
                Af[i][0] = *(const uint32_t*)&sAs[row * PAD + col];
                Af[i][1] = *(const uint32_t*)&sAs[(row + 8) * PAD + col];
                Af[i][2] = *(const uint32_t*)&sAs[row * PAD + col + 8];
                Af[i][3] = *(const uint32_t*)&sAs[(row + 8) * PAD + col + 8];
            }
#pragma unroll
            for (int j = 0; j < 4; j++) {
                int nrow = wn + 8 * j + gid;
                Bf[j][0] = *(const uint32_t*)&sBs[nrow * PAD + col];
                Bf[j][1] = *(const uint32_t*)&sBs[nrow * PAD + col + 8];
            }
#pragma unroll
            for (int j = 0; j < 4; j++)
#pragma unroll
                for (int i = 0; i < 4; i++) mma_f16(acc[i][j], Af[i], Bf[j]);
        }
        __syncthreads();
    }

    float gpv = gpp[0];
    float* ob = out + (size_t)b * (CT * HWD);
#pragma unroll
    for (int i = 0; i < 4; i++) {
#pragma unroll
        for (int j = 0; j < 4; j++) {
            int r = r0 + wm + 16 * i + gid;
            int n = n0 + wn + 8 * j + tq * 2;
            float2* p0 = (float2*)(ob + (size_t)r * 1024 + n);
            float2 v0 = *p0;
            v0.x += gpv * acc[i][j][0];
            v0.y += gpv * acc[i][j][1];
            *p0 = v0;
            float2* p1 = (float2*)(ob + (size_t)(r + 8) * 1024 + n);
            float2 v1 = *p1;
            v1.x += gpv * acc[i][j][2];
            v1.y += gpv * acc[i][j][3];
            *p1 = v1;
        }
    }
}

// ---------------- launch ----------------
extern "C" void kernel_launch(void* const* d_in, const int* in_sizes, int n_in,
                              void* d_out, int out_size)
{
    const float* x  = (const float*)d_in[0];
    const float* Wq = (const float*)d_in[1];
    const float* bq = (const float*)d_in[2];
    const float* Wk = (const float*)d_in[3];
    const float* bk = (const float*)d_in[4];
    const float* Wv = (const float*)d_in[5];
    const float* bv = (const float*)d_in[6];
    const float* gp = (const float*)d_in[7];
    const float* gc = (const float*)d_in[8];
    const float* gt = (const float*)d_in[9];
    float* out = (float*)d_out;

    static int attrs_set = 0;
    if (!attrs_set) {
        cudaFuncSetAttribute(k_qkv_tc, cudaFuncAttributeMaxDynamicSharedMemorySize, QKV_SMEM_BYTES);
        cudaFuncSetAttribute(k_energy_tc, cudaFuncAttributeMaxDynamicSharedMemorySize, EN_SMEM_BYTES);
        cudaFuncSetAttribute(k_came_tc, cudaFuncAttributeMaxDynamicSharedMemorySize, CAME_SMEM_BYTES);
        cudaFuncSetAttribute(k_pam_mma, cudaFuncAttributeMaxDynamicSharedMemorySize, PAM_SMEM_BYTES);
        attrs_set = 1;
    }

    k_qkv_tc<<<dim3(64, 3, 8), 256, QKV_SMEM_BYTES>>>(x, Wq, bq, Wk, bk, Wv, bv);
    k_energy_tc<<<dim3(8, 8, 8), 256, EN_SMEM_BYTES>>>();
    k_softmax<<<8192, 256>>>();
    k_came_tc<<<256, 256, CAME_SMEM_BYTES>>>(x);
    k_camsm<<<1024, 128>>>();
    k_time<<<dim3(128, 8), 256>>>(x);
    k_timsm<<<1, 256>>>();
    k_base<<<dim3(32, 4, 8), 256>>>(x, gc, gt, out);
    k_pam_mma<<<dim3(8, 8, 8), 256, PAM_SMEM_BYTES>>>(gp, out);
}

// round 14
// speedup vs baseline: 1.2407x; 1.0928x over previous
#include <cuda_runtime.h>
#include <cuda_fp16.h>
#include <math.h>
#include <stdint.h>

#define BB 8
#define CC 128
#define TT 8
#define HWD 1024
#define NPOS 8192
#define CT 1024

// ---------------- scratch ----------------
__device__ float g_qf[BB][128][HWD];
__device__ float g_kf[BB][128][HWD];
__device__ __half g_vf_s[BB][CT][HWD];
__device__ float g_attn[BB][HWD][HWD];
__device__ __half g_attn_s[BB][HWD][HWD];
__device__ float g_ecam_p[32][BB][CC][CC];
__device__ float g_acam[BB][CC][CC];
__device__ float g_etim_p[BB][CC][36];
__device__ float g_atim[BB][TT][TT];

// ---------------- helpers ----------------
__device__ __forceinline__ void mma_f16(float* c, const uint32_t* a, const uint32_t* b) {
    asm volatile(
        "mma.sync.aligned.m16n8k16.row.col.f32.f16.f16.f32 "
        "{%0,%1,%2,%3}, {%4,%5,%6,%7}, {%8,%9}, {%0,%1,%2,%3};"
        : "+f"(c[0]), "+f"(c[1]), "+f"(c[2]), "+f"(c[3])
        : "r"(a[0]), "r"(a[1]), "r"(a[2]), "r"(a[3]), "r"(b[0]), "r"(b[1]));
}
__device__ __forceinline__ void split_h(float a, __half& h, __half& l) {
    h = __float2half_rn(a);
    l = __float2half_rn(a - __half2float(h));
}
__device__ __forceinline__ uint32_t packh(__half a, __half b) {
    return ((uint32_t)__half_as_ushort(b) << 16) | __half_as_ushort(a);
}
__device__ __forceinline__ void pack2rows(float4 a, float4 b, uint4& hi, uint4& lo) {
    __half ha, la, hb, lb;
    split_h(a.x, ha, la); split_h(b.x, hb, lb);
    hi.x = packh(ha, hb); lo.x = packh(la, lb);
    split_h(a.y, ha, la); split_h(b.y, hb, lb);
    hi.y = packh(ha, hb); lo.y = packh(la, lb);
    split_h(a.z, ha, la); split_h(b.z, hb, lb);
    hi.z = packh(ha, hb); lo.z = packh(la, lb);
    split_h(a.w, ha, la); split_h(b.w, hb, lb);
    hi.w = packh(ha, hb); lo.w = packh(la, lb);
}
__device__ __forceinline__ uint32_t smem_to_u32(const void* p) {
    uint32_t a;
    asm("{ .reg .u64 t; cvta.to.shared.u64 t, %1; cvt.u32.u64 %0, t; }" : "=r"(a) : "l"(p));
    return a;
}
__device__ __forceinline__ void cp16(uint32_t s, const void* g) {
    asm volatile("cp.async.cg.shared.global [%0], [%1], 16;"
                 :: "r"(s), "l"(__cvta_generic_to_global(g)) : "memory");
}
#define CP_COMMIT() asm volatile("cp.async.commit_group;" ::: "memory")
#define CP_WAIT(n)  asm volatile("cp.async.wait_group %0;" :: "n"(n) : "memory")

// ---------------- 1) fused q/k/v projection via fp16x3 MMA ----------------
#define QKV_SMEM_BYTES ((2 * 64 * 20 + 2 * 16 * 136) * 4)
__global__ __launch_bounds__(256) void k_qkv_tc(
    const float* __restrict__ x,
    const float* __restrict__ Wq, const float* __restrict__ bq,
    const float* __restrict__ Wk, const float* __restrict__ bk,
    const float* __restrict__ Wv, const float* __restrict__ bv)
{
    extern __shared__ uint32_t qsm[];
    uint32_t* PWh = qsm;
    uint32_t* PWl = qsm + 64 * 20;
    uint32_t* PBh = qsm + 2 * 64 * 20;
    uint32_t* PBl = PBh + 16 * 136;

    int b     = blockIdx.z;
    int rows0 = blockIdx.y * 64;
    int pos0  = blockIdx.x * 128;
    int tid = threadIdx.x, wid = tid >> 5, lane = tid & 31;
    int gid = lane >> 2, tq = lane & 3;
    int wm = (wid >> 1) * 16;
    int wn = (wid & 1) * 64;
    const float* xb = x + (size_t)b * (CC * NPOS);

    float acc[8][4] = {};

    for (int kc = 0; kc < 128; kc += 32) {
#pragma unroll
        for (int q = 0; q < 2; q++) {
            int e = tid + q * 256;
            int row = e >> 3, kg = e & 7;
            int r = rows0 + row;
            float4 v = make_float4(0.f, 0.f, 0.f, 0.f);
            if (r < 16)       v = *(const float4*)(Wq + r * 128 + kc + kg * 4);
            else if (r < 32)  v = *(const float4*)(Wk + (r - 16) * 128 + kc + kg * 4);
            else if (r < 160) v = *(const float4*)(Wv + (r - 32) * 128 + kc + kg * 4);
            __half h0, l0, h1, l1, h2, l2, h3, l3;
            split_h(v.x, h0, l0); split_h(v.y, h1, l1);
            split_h(v.z, h2, l2); split_h(v.w, h3, l3);
            uint2 hp = make_uint2(packh(h0, h1), packh(h2, h3));
            uint2 lp = make_uint2(packh(l0, l1), packh(l2, l3));
            *(uint2*)&PWh[row * 20 + kg * 2] = hp;
            *(uint2*)&PWl[row * 20 + kg * 2] = lp;
        }
#pragma unroll
        for (int q = 0; q < 2; q++) {
            int e = tid + q * 256;
            int kp = e >> 5, ng = e & 31;
            const float* r0p = xb + (size_t)(kc + 2 * kp) * NPOS + pos0 + ng * 4;
            float4 v0 = *(const float4*)r0p;
            float4 v1 = *(const float4*)(r0p + NPOS);
            uint4 hi, lo;
            pack2rows(v0, v1, hi, lo);
            *(uint4*)&PBh[kp * 136 + ng * 4] = hi;
            *(uint4*)&PBl[kp * 136 + ng * 4] = lo;
        }
        __syncthreads();
#pragma unroll
        for (int kk2 = 0; kk2 < 16; kk2 += 8) {
            uint32_t Af[4], Alf[4], Bf[8][2], Blf[8][2];
            int row = wm + gid;
            Af[0]  = PWh[row * 20 + kk2 + tq];
            Af[1]  = PWh[(row + 8) * 20 + kk2 + tq];
            Af[2]  = PWh[row * 20 + kk2 + tq + 4];
            Af[3]  = PWh[(row + 8) * 20 + kk2 + tq + 4];
            Alf[0] = PWl[row * 20 + kk2 + tq];
            Alf[1] = PWl[(row + 8) * 20 + kk2 + tq];
            Alf[2] = PWl[row * 20 + kk2 + tq + 4];
            Alf[3] = PWl[(row + 8) * 20 + kk2 + tq + 4];
#pragma unroll
            for (int j = 0; j < 8; j++) {
                int n = wn + 8 * j + gid;
                Bf[j][0]  = PBh[(kk2 + tq) * 136 + n];
                Bf[j][1]  = PBh[(kk2 + tq + 4) * 136 + n];
                Blf[j][0] = PBl[(kk2 + tq) * 136 + n];
                Blf[j][1] = PBl[(kk2 + tq + 4) * 136 + n];
            }
#pragma unroll
            for (int j = 0; j < 8; j++) mma_f16(acc[j], Af,  Bf[j]);
#pragma unroll
            for (int j = 0; j < 8; j++) mma_f16(acc[j], Af,  Blf[j]);
#pragma unroll
            for (int j = 0; j < 8; j++) mma_f16(acc[j], Alf, Bf[j]);
        }
        __syncthreads();
    }

    int t   = pos0 >> 10;
    int hw0 = pos0 & 1023;
#pragma unroll
    for (int j = 0; j < 8; j++) {
        int hw = hw0 + wn + 8 * j + 2 * tq;
#pragma unroll
        for (int half = 0; half < 2; half++) {
            int r = rows0 + wm + gid + half * 8;
            if (r >= 160) continue;
            float v0 = acc[j][half * 2 + 0];
            float v1 = acc[j][half * 2 + 1];
            if (r < 16) {
                float bias = bq[r];
                *(float2*)&g_qf[b][r * TT + t][hw] = make_float2(v0 + bias, v1 + bias);
            } else if (r < 32) {
                float bias = bk[r - 16];
                *(float2*)&g_kf[b][(r - 16) * TT + t][hw] = make_float2(v0 + bias, v1 + bias);
            } else {
                float bias = bv[r - 32];
                int row = (r - 32) * TT + t;
                *(uint32_t*)&g_vf_s[b][row][hw] =
                    packh(__float2half_rn(v0 + bias), __float2half_rn(v1 + bias));
            }
        }
    }
}

// ---------------- 2) PAM energy via fp16x3 MMA (packed k-pairs) ----------------
#define EN_SMEM_BYTES (4 * 16 * 136 * 4)
__global__ __launch_bounds__(256, 2) void k_energy_tc()
{
    extern __shared__ uint32_t esm[];
    uint32_t* Ah = esm;
    uint32_t* Al = esm + 16 * 136;
    uint32_t* Bh = esm + 2 * 16 * 136;
    uint32_t* Bl = esm + 3 * 16 * 136;

    int b  = blockIdx.z;
    int n0 = blockIdx.y * 128;
    int m0 = blockIdx.x * 128;
    int tid = threadIdx.x, wid = tid >> 5, lane = tid & 31;
    int gid = lane >> 2, tq = lane & 3;
    int wm = (wid >> 1) * 32;
    int wn = (wid & 1) * 64;

    float acc[2][8][4] = {};

    for (int kc = 0; kc < 128; kc += 32) {
#pragma unroll
        for (int q = 0; q < 2; q++) {
            int e = tid + q * 256;
            int kp = e >> 5, ng = e & 31;
            const float* qa = &g_qf[b][kc + 2 * kp][n0 + ng * 4];
            const float* kb = &g_kf[b][kc + 2 * kp][m0 + ng * 4];
            float4 va0 = *(const float4*)qa;
            float4 va1 = *(const float4*)(qa + HWD);
            float4 vb0 = *(const float4*)kb;
            float4 vb1 = *(const float4*)(kb + HWD);
            uint4 hi, lo;
            pack2rows(va0, va1, hi, lo);
            *(uint4*)&Ah[kp * 136 + ng * 4] = hi;
            *(uint4*)&Al[kp * 136 + ng * 4] = lo;
            pack2rows(vb0, vb1, hi, lo);
            *(uint4*)&Bh[kp * 136 + ng * 4] = hi;
            *(uint4*)&Bl[kp * 136 + ng * 4] = lo;
        }
        __syncthreads();
#pragma unroll
        for (int kk2 = 0; kk2 < 16; kk2 += 8) {
            uint32_t Af[2][4], Alf[2][4], Bf[8][2], Blf[8][2];
#pragma unroll
            for (int i = 0; i < 2; i++) {
                int m = wm + 16 * i + gid;
                Af[i][0]  = Ah[(kk2 + tq) * 136 + m];
                Af[i][1]  = Ah[(kk2 + tq) * 136 + m + 8];
                Af[i][2]  = Ah[(kk2 + tq + 4) * 136 + m];
                Af[i][3]  = Ah[(kk2 + tq + 4) * 136 + m + 8];
                Alf[i][0] = Al[(kk2 + tq) * 136 + m];
                Alf[i][1] = Al[(kk2 + tq) * 136 + m + 8];
                Alf[i][2] = Al[(kk2 + tq + 4) * 136 + m];
                Alf[i][3] = Al[(kk2 + tq + 4) * 136 + m + 8];
            }
#pragma unroll
            for (int j = 0; j < 8; j++) {
                int n = wn + 8 * j + gid;
                Bf[j][0]  = Bh[(kk2 + tq) * 136 + n];
                Bf[j][1]  = Bh[(kk2 + tq + 4) * 136 + n];
                Blf[j][0] = Bl[(kk2 + tq) * 136 + n];
                Blf[j][1] = Bl[(kk2 + tq + 4) * 136 + n];
            }
#pragma unroll
            for (int j = 0; j < 8; j++)
#pragma unroll
                for (int i = 0; i < 2; i++) mma_f16(acc[i][j], Af[i], Bf[j]);
#pragma unroll
            for (int j = 0; j < 8; j++)
#pragma unroll
                for (int i = 0; i < 2; i++) mma_f16(acc[i][j], Af[i], Blf[j]);
#pragma unroll
            for (int j = 0; j < 8; j++)
#pragma unroll
                for (int i = 0; i < 2; i++) mma_f16(acc[i][j], Alf[i], Bf[j]);
        }
        __syncthreads();
    }

#pragma unroll
    for (int i = 0; i < 2; i++)
#pragma unroll
        for (int j = 0; j < 8; j++) {
            int n = n0 + wm + 16 * i + gid;
            int m = m0 + wn + 8 * j + 2 * tq;
            *(float2*)&g_attn[b][n][m]     = make_float2(acc[i][j][0], acc[i][j][1]);
            *(float2*)&g_attn[b][n + 8][m] = make_float2(acc[i][j][2], acc[i][j][3]);
        }
}

// ---------------- 3) softmax -> single fp16 (vectorized) ----------------
__global__ __launch_bounds__(256) void k_softmax()
{
    int row = blockIdx.x;
    int tid = threadIdx.x;
    const float4* e4 = (const float4*)(&g_attn[0][0][0] + (size_t)row * 1024);
    float4 v = e4[tid];
    float m = fmaxf(fmaxf(v.x, v.y), fmaxf(v.z, v.w));
    __shared__ float red[8];
#pragma unroll
    for (int o = 16; o > 0; o >>= 1) m = fmaxf(m, __shfl_xor_sync(0xffffffffu, m, o));
    if ((tid & 31) == 0) red[tid >> 5] = m;
    __syncthreads();
    m = red[0];
#pragma unroll
    for (int j = 1; j < 8; j++) m = fmaxf(m, red[j]);
    v.x = __expf(v.x - m); v.y = __expf(v.y - m);
    v.z = __expf(v.z - m); v.w = __expf(v.w - m);
    float s = (v.x + v.y) + (v.z + v.w);
    __syncthreads();
#pragma unroll
    for (int o = 16; o > 0; o >>= 1) s += __shfl_xor_sync(0xffffffffu, s, o);
    if ((tid & 31) == 0) red[tid >> 5] = s;
    __syncthreads();
    s = red[0];
#pragma unroll
    for (int j = 1; j < 8; j++) s += red[j];
    float inv = 1.f / s;
    v.x *= inv; v.y *= inv; v.z *= inv; v.w *= inv;

    uint2 hp;
    hp.x = packh(__float2half_rn(v.x), __float2half_rn(v.y));
    hp.y = packh(__float2half_rn(v.z), __float2half_rn(v.w));
    ((uint2*)(&g_attn_s[0][0][0] + (size_t)row * 1024))[tid] = hp;
}

// ---------------- 4) CAM energy fp16x3 Gram ----------------
#define CPAD 40
#define CAME_SMEM_BYTES (32768 + 2 * 128 * CPAD * 2)
__global__ __launch_bounds__(256, 2) void k_came_tc(const float* __restrict__ x)
{
    extern __shared__ char csm[];
    float* raw = (float*)csm;
    __half* Xh = (__half*)(csm + 32768);
    __half* Xl = (__half*)(csm + 32768 + 128 * CPAD * 2);
    uint32_t rawb = smem_to_u32(raw);

    int b  = blockIdx.x >> 5;
    int sl = blockIdx.x & 31;
    int tid = threadIdx.x, wid = tid >> 5, lane = tid & 31;
    int gid = lane >> 2, tq = lane & 3;
    int wm = (wid >> 1) * 32;
    int wn = (wid & 1) * 64;
    const float* xb = x + (size_t)b * (CC * NPOS) + sl * 256;

    float acc[2][8][4] = {};

    auto load_raw = [&](int st, int kc) {
#pragma unroll
        for (int q = 0; q < 4; q++) {
            int e = tid + q * 256;
            int row = e >> 3, c4 = e & 7;
            cp16(rawb + (uint32_t)(st * 4096 + row * 32 + c4 * 4) * 4,
                 xb + (size_t)row * NPOS + kc + c4 * 4);
        }
        CP_COMMIT();
    };

    load_raw(0, 0);

    for (int it = 0; it < 8; it++) {
        int st = it & 1;
        if (it < 7) { load_raw(st ^ 1, (it + 1) * 32); CP_WAIT(1); }
        else        { CP_WAIT(0); }
        __syncthreads();

#pragma unroll
        for (int q = 0; q < 4; q++) {
            int e = tid + q * 256;
            int row = e >> 3, c4 = e & 7;
            float4 v = *(const float4*)&raw[st * 4096 + row * 32 + c4 * 4];
            __half hx, lx, hy, ly, hz, lz, hw, lw;
            split_h(v.x, hx, lx); split_h(v.y, hy, ly);
            split_h(v.z, hz, lz); split_h(v.w, hw, lw);
            uint2 hp, lp;
            hp.x = packh(hx, hy); hp.y = packh(hz, hw);
            lp.x = packh(lx, ly); lp.y = packh(lz, lw);
            *(uint2*)&Xh[row * CPAD + c4 * 4] = hp;
            *(uint2*)&Xl[row * CPAD + c4 * 4] = lp;
        }
        __syncthreads();

#pragma unroll
        for (int kk = 0; kk < 32; kk += 16) {
            uint32_t Af[2][4], Alf[2][4], Bf[8][2], Blf[8][2];
            int c0 = kk + 2 * tq, c1 = c0 + 8;
#pragma unroll
            for (int i = 0; i < 2; i++) {
                int r0 = wm + 16 * i + gid, r1 = r0 + 8;
                Af[i][0]  = *(const uint32_t*)&Xh[r0 * CPAD + c0];
                Af[i][1]  = *(const uint32_t*)&Xh[r1 * CPAD + c0];
                Af[i][2]  = *(const uint32_t*)&Xh[r0 * CPAD + c1];
                Af[i][3]  = *(const uint32_t*)&Xh[r1 * CPAD + c1];
                Alf[i][0] = *(const uint32_t*)&Xl[r0 * CPAD + c0];
                Alf[i][1] = *(const uint32_t*)&Xl[r1 * CPAD + c0];
                Alf[i][2] = *(const uint32_t*)&Xl[r0 * CPAD + c1];
                Alf[i][3] = *(const uint32_t*)&Xl[r1 * CPAD + c1];
            }
#pragma unroll
            for (int j = 0; j < 8; j++) {
                int rn = wn + 8 * j + gid;
                Bf[j][0]  = *(const uint32_t*)&Xh[rn * CPAD + c0];
                Bf[j][1]  = *(const uint32_t*)&Xh[rn * CPAD + c1];
                Blf[j][0] = *(const uint32_t*)&Xl[rn * CPAD + c0];
                Blf[j][1] = *(const uint32_t*)&Xl[rn * CPAD + c1];
            }
#pragma unroll
            for (int j = 0; j < 8; j++)
#pragma unroll
                for (int i = 0; i < 2; i++) mma_f16(acc[i][j], Af[i], Bf[j]);
#pragma unroll
            for (int j = 0; j < 8; j++)
#pragma unroll
                for (int i = 0; i < 2; i++) mma_f16(acc[i][j], Af[i], Blf[j]);
#pragma unroll
            for (int j = 0; j < 8; j++)
#pragma unroll
                for (int i = 0; i < 2; i++) mma_f16(acc[i][j], Alf[i], Bf[j]);
        }
    }

#pragma unroll
    for (int i = 0; i < 2; i++)
#pragma unroll
        for (int j = 0; j < 8; j++) {
            int c = wm + 16 * i + gid;
            int d = wn + 8 * j + 2 * tq;
            *(float2*)&g_ecam_p[sl][b][c][d]     = make_float2(acc[i][j][0], acc[i][j][1]);
            *(float2*)&g_ecam_p[sl][b][c + 8][d] = make_float2(acc[i][j][2], acc[i][j][3]);
        }
}

// ---------------- 5) CAM negated-energy softmax ----------------
__global__ __launch_bounds__(128) void k_camsm()
{
    int b = blockIdx.x >> 7;
    int c = blockIdx.x & 127;
    int d = threadIdx.x;
    float ev = 0.f;
#pragma unroll
    for (int sl = 0; sl < 32; sl++) ev += g_ecam_p[sl][b][c][d];
    __shared__ float red[4];
    float mn = ev;
#pragma unroll
    for (int o = 16; o > 0; o >>= 1) mn = fminf(mn, __shfl_xor_sync(0xffffffffu, mn, o));
    if ((threadIdx.x & 31) == 0) red[threadIdx.x >> 5] = mn;
    __syncthreads();
    mn = fminf(fminf(red[0], red[1]), fminf(red[2], red[3]));
    float w = __expf(mn - ev);
    __syncthreads();
    float s = w;
#pragma unroll
    for (int o = 16; o > 0; o >>= 1) s += __shfl_xor_sync(0xffffffffu, s, o);
    if ((threadIdx.x & 31) == 0) red[threadIdx.x >> 5] = s;
    __syncthreads();
    s = (red[0] + red[1]) + (red[2] + red[3]);
    g_acam[b][c][d] = w / s;
}

// ---------------- 6) TIM Gram partials ----------------
__global__ __launch_bounds__(256) void k_time(const float* __restrict__ x)
{
    int c = blockIdx.x;
    int b = blockIdx.y;
    int tid = threadIdx.x;
    const float* xp = x + ((size_t)b * CC + c) * NPOS;
    float v[8][4];
#pragma unroll
    for (int t = 0; t < 8; t++) {
        float4 f = *reinterpret_cast<const float4*>(xp + t * 1024 + tid * 4);
        v[t][0] = f.x; v[t][1] = f.y; v[t][2] = f.z; v[t][3] = f.w;
    }
    float acc[36];
    int idx = 0;
#pragma unroll
    for (int t = 0; t < 8; t++)
#pragma unroll
        for (int s = t; s < 8; s++) {
            float a = 0.f;
#pragma unroll
            for (int j = 0; j < 4; j++) a += v[t][j] * v[s][j];
            acc[idx++] = a;
        }
    __shared__ float red[36][8];
    int lane = tid & 31, warp = tid >> 5;
#pragma unroll
    for (int i = 0; i < 36; i++) {
        float a = acc[i];
#pragma unroll
        for (int o = 16; o > 0; o >>= 1) a += __shfl_xor_sync(0xffffffffu, a, o);
        if (lane == 0) red[i][warp] = a;
    }
    __syncthreads();
    if (tid < 36) {
        float a = 0.f;
#pragma unroll
        for (int w = 0; w < 8; w++) a += red[tid][w];
        g_etim_p[b][c][tid] = a;
    }
}

// ---------------- 7) TIM reduce + softmax ----------------
__global__ __launch_bounds__(256) void k_timsm()
{
    __shared__ float e36[BB][36];
    int tid = threadIdx.x;
    for (int o = tid; o < BB * 36; o += 256) {
        int b = o / 36, i = o % 36;
        float a = 0.f;
        for (int c = 0; c < CC; c++) a += g_etim_p[b][c][i];
        e36[b][i] = a;
    }
    __syncthreads();
    if (tid < 64) {
        int b = tid >> 3, t = tid & 7;
        float e[8];
#pragma unroll
        for (int s = 0; s < 8; s++) {
            int lo = t < s ? t : s, hi = t < s ? s : t;
            int idx = 8 * lo - lo * (lo - 1) / 2 + (hi - lo);
            e[s] = e36[b][idx];
        }
        float mn = e[0];
#pragma unroll
        for (int s = 1; s < 8; s++) mn = fminf(mn, e[s]);
        float w[8], sum = 0.f;
#pragma unroll
        for (int s = 0; s < 8; s++) { w[s] = __expf(mn - e[s]); sum += w[s]; }
#pragma unroll
        for (int s = 0; s < 8; s++) g_atim[b][t][s] = w[s] / sum;
    }
}

// ---------------- 8) base: out = 3x + gc*(a_cam@xc) + gt*tim ----------------
__global__ __launch_bounds__(256) void k_base(
    const float* __restrict__ x,
    const float* __restrict__ gcp, const float* __restrict__ gtp,
    float* __restrict__ out)
{
    int b   = blockIdx.z;
    int c0  = blockIdx.y * 32;
    int hw0 = blockIdx.x * 32;
    __shared__ float As[32][33];
    __shared__ float Xs[32][8][33];
    __shared__ float at8[8][8];
    int tid = threadIdx.x;
    int hw_l = tid & 31, cg = tid >> 5;
    if (tid < 64) at8[tid >> 3][tid & 7] = g_atim[b][tid >> 3][tid & 7];
    float acc[4][8] = {};
    const float* xb = x + (size_t)b * (CC * NPOS);

    for (int kc = 0; kc < CC; kc += 32) {
#pragma unroll
        for (int q = 0; q < 4; q++) {
            int e = tid + q * 256;
            int i = e >> 5, k = e & 31;
            As[i][k] = g_acam[b][c0 + i][kc + k];
        }
#pragma unroll
        for (int q = 0; q < 32; q++) {
            int e = tid + q * 256;
            int k = e >> 8, t = (e >> 5) & 7, hw = e & 31;
            Xs[k][t][hw] = xb[(size_t)(kc + k) * NPOS + t * 1024 + hw0 + hw];
        }
        __syncthreads();
#pragma unroll
        for (int k = 0; k < 32; k++) {
            float av[4], xv[8];
#pragma unroll
            for (int j = 0; j < 4; j++) av[j] = As[cg + 8 * j][k];
#pragma unroll
            for (int t = 0; t < 8; t++) xv[t] = Xs[k][t][hw_l];
#pragma unroll
            for (int j = 0; j < 4; j++)
#pragma unroll
                for (int t = 0; t < 8; t++) acc[j][t] += av[j] * xv[t];
        }
        __syncthreads();
    }

    float gc = gcp[0], gt = gtp[0];
#pragma unroll
    for (int j = 0; j < 4; j++) {
        int c = c0 + cg + 8 * j;
        const float* xc = xb + (size_t)c * NPOS + hw0 + hw_l;
        float xrow[8];
#pragma unroll
        for (int s = 0; s < 8; s++) xrow[s] = xc[s * 1024];
        float* oc = out + (size_t)b * (CC * NPOS) + (size_t)c * NPOS + hw0 + hw_l;
#pragma unroll
        for (int t = 0; t < 8; t++) {
            float tim = 0.f;
#pragma unroll
            for (int s = 0; s < 8; s++) tim += at8[t][s] * xrow[s];
            oc[t * 1024] = 3.f * xrow[t] + gc * acc[j][t] + gt * tim;
        }
    }
}

// ---------------- 9) PAM GEMM: single-term fp16, cp.async 2-stage ----------------
#define PAD 40
#define PAM_TILE 5120
#define PAM_STAGE (2 * PAM_TILE)
#define PAM_SMEM_BYTES (2 * PAM_STAGE * 2)
__global__ __launch_bounds__(256, 2) void k_pam_mma(const float* __restrict__ gpp,
                                                    float* __restrict__ out)
{
    extern __shared__ __half smp[];
    uint32_t smb = smem_to_u32(smp);

    int tid = threadIdx.x;
    int b  = blockIdx.z;
    int r0 = blockIdx.y * 128;
    int n0 = blockIdx.x * 128;
    int wid = tid >> 5, lane = tid & 31;
    int gid = lane >> 2, tq = lane & 3;
    int wm = (wid & 1) * 64;
    int wn = (wid >> 1) * 32;

    const __half* Asp = &g_vf_s[b][0][0];
    const __half* Bsp = &g_attn_s[b][0][0];

    float acc[4][4][4] = {};

    auto stage_load = [&](int st, int kc) {
#pragma unroll
        for (int q = 0; q < 2; q++) {
            int e = tid + q * 256;
            int row = e >> 2, c4 = e & 3;
            uint32_t so = smb + (uint32_t)(st * PAM_STAGE + row * PAD + c4 * 8) * 2;
            size_t gA = (size_t)(r0 + row) * 1024 + kc + c4 * 8;
            size_t gB = (size_t)(n0 + row) * 1024 + kc + c4 * 8;
            cp16(so,                Asp + gA);
            cp16(so + PAM_TILE * 2, Bsp + gB);
        }
        CP_COMMIT();
    };

    stage_load(0, 0);

    for (int it = 0; it < 32; it++) {
        int st = it & 1;
        if (it < 31) { stage_load(st ^ 1, (it + 1) * 32); CP_WAIT(1); }
        else         { CP_WAIT(0); }
        __syncthreads();

        const __half* sAs = smp + st * PAM_STAGE;
        const __half* sBs = sAs + PAM_TILE;

#pragma unroll
        for (int ks = 0; ks < 32; ks += 16) {
            uint32_t Af[4][4], Bf[4][2];
            int col = ks + tq * 2;
#pragma unroll
            for (int i = 0; i < 4; i++) {
                int row = wm + 16 * i + gid;
                Af[i][0] = *(const uint32_t*)&sAs[row * PAD + col];
                Af[i][1] = *(const uint32_t*)&sAs[(row + 8) * PAD + col];
                Af[i][2] = *(const uint32_t*)&sAs[row * PAD + col + 8];
                Af[i][3] = *(const uint32_t*)&sAs[(row + 8) * PAD + col + 8];
            }
#pragma unroll
            for (int j = 0; j < 4; j++) {
                int nrow = wn + 8 * j + gid;
                Bf[j][0] = *(const uint32_t*)&sBs[nrow * PAD + col];
                Bf[j][1] = *(const uint32_t*)&sBs[nrow * PAD + col + 8];
            }
#pragma unroll
            for (int j = 0; j < 4; j++)
#pragma unroll
                for (int i = 0; i < 4; i++) mma_f16(acc[i][j], Af[i], Bf[j]);
        }
        __syncthreads();
    }

    float gpv = gpp[0];
    float* ob = out + (size_t)b * (CT * HWD);
#pragma unroll
    for (int i = 0; i < 4; i++) {
#pragma unroll
        for (int j = 0; j < 4; j++) {
            int r = r0 + wm + 16 * i + gid;
            int n = n0 + wn + 8 * j + tq * 2;
            float2* p0 = (float2*)(ob + (size_t)r * 1024 + n);
            float2 v0 = *p0;
            v0.x += gpv * acc[i][j][0];
            v0.y += gpv * acc[i][j][1];
            *p0 = v0;
            float2* p1 = (float2*)(ob + (size_t)(r + 8) * 1024 + n);
            float2 v1 = *p1;
            v1.x += gpv * acc[i][j][2];
            v1.y += gpv * acc[i][j][3];
            *p1 = v1;
        }
    }
}

// ---------------- launch: two-stream fork/join overlap ----------------
extern "C" void kernel_launch(void* const* d_in, const int* in_sizes, int n_in,
                              void* d_out, int out_size)
{
    const float* x  = (const float*)d_in[0];
    const float* Wq = (const float*)d_in[1];
    const float* bq = (const float*)d_in[2];
    const float* Wk = (const float*)d_in[3];
    const float* bk = (const float*)d_in[4];
    const float* Wv = (const float*)d_in[5];
    const float* bv = (const float*)d_in[6];
    const float* gp = (const float*)d_in[7];
    const float* gc = (const float*)d_in[8];
    const float* gt = (const float*)d_in[9];
    float* out = (float*)d_out;

    static cudaStream_t s2 = nullptr;
    static cudaEvent_t evFork = nullptr, evJoin = nullptr;
    static int attrs_set = 0;
    if (!attrs_set) {
        cudaFuncSetAttribute(k_qkv_tc, cudaFuncAttributeMaxDynamicSharedMemorySize, QKV_SMEM_BYTES);
        cudaFuncSetAttribute(k_energy_tc, cudaFuncAttributeMaxDynamicSharedMemorySize, EN_SMEM_BYTES);
        cudaFuncSetAttribute(k_came_tc, cudaFuncAttributeMaxDynamicSharedMemorySize, CAME_SMEM_BYTES);
        cudaFuncSetAttribute(k_pam_mma, cudaFuncAttributeMaxDynamicSharedMemorySize, PAM_SMEM_BYTES);
        cudaStreamCreateWithFlags(&s2, cudaStreamNonBlocking);
        cudaEventCreateWithFlags(&evFork, cudaEventDisableTiming);
        cudaEventCreateWithFlags(&evJoin, cudaEventDisableTiming);
        attrs_set = 1;
    }

    // fork: chain B (CAM + TIM + base) on s2, chain A (q/k/v attention) on default
    cudaEventRecord(evFork, 0);
    cudaStreamWaitEvent(s2, evFork, 0);

    // chain B (independent of chain A)
    k_came_tc<<<256, 256, CAME_SMEM_BYTES, s2>>>(x);
    k_camsm<<<1024, 128, 0, s2>>>();
    k_time<<<dim3(128, 8), 256, 0, s2>>>(x);
    k_timsm<<<1, 256, 0, s2>>>();
    k_base<<<dim3(32, 4, 8), 256, 0, s2>>>(x, gc, gt, out);

    // chain A
    k_qkv_tc<<<dim3(64, 3, 8), 256, QKV_SMEM_BYTES>>>(x, Wq, bq, Wk, bk, Wv, bv);
    k_energy_tc<<<dim3(8, 8, 8), 256, EN_SMEM_BYTES>>>();
    k_softmax<<<8192, 256>>>();

    // join: pam needs softmax (chain A) and base's out (chain B)
    cudaEventRecord(evJoin, s2);
    cudaStreamWaitEvent(0, evJoin, 0);
    k_pam_mma<<<dim3(8, 8, 8), 256, PAM_SMEM_BYTES>>>(gp, out);
}

// round 15
// speedup vs baseline: 1.2640x; 1.0187x over previous
#include <cuda_runtime.h>
#include <cuda_fp16.h>
#include <math.h>
#include <stdint.h>

#define BB 8
#define CC 128
#define TT 8
#define HWD 1024
#define NPOS 8192
#define CT 1024

// ---------------- scratch ----------------
__device__ float g_qf[BB][128][HWD];
__device__ float g_kf[BB][128][HWD];
__device__ __half g_vf_s[BB][CT][HWD];
__device__ float g_attn[BB][HWD][HWD];
__device__ __half g_attn_s[BB][HWD][HWD];
__device__ float g_ecam_p[32][BB][CC][CC];
__device__ float g_acam[BB][CC][CC];
__device__ float g_etim_p[BB][CC][36];
__device__ float g_etim36[BB][36];
__device__ float g_atim[BB][TT][TT];

// ---------------- helpers ----------------
__device__ __forceinline__ void mma_f16(float* c, const uint32_t* a, const uint32_t* b) {
    asm volatile(
        "mma.sync.aligned.m16n8k16.row.col.f32.f16.f16.f32 "
        "{%0,%1,%2,%3}, {%4,%5,%6,%7}, {%8,%9}, {%0,%1,%2,%3};"
        : "+f"(c[0]), "+f"(c[1]), "+f"(c[2]), "+f"(c[3])
        : "r"(a[0]), "r"(a[1]), "r"(a[2]), "r"(a[3]), "r"(b[0]), "r"(b[1]));
}
__device__ __forceinline__ void split_h(float a, __half& h, __half& l) {
    h = __float2half_rn(a);
    l = __float2half_rn(a - __half2float(h));
}
__device__ __forceinline__ uint32_t packh(__half a, __half b) {
    return ((uint32_t)__half_as_ushort(b) << 16) | __half_as_ushort(a);
}
__device__ __forceinline__ void pack2rows(float4 a, float4 b, uint4& hi, uint4& lo) {
    __half ha, la, hb, lb;
    split_h(a.x, ha, la); split_h(b.x, hb, lb);
    hi.x = packh(ha, hb); lo.x = packh(la, lb);
    split_h(a.y, ha, la); split_h(b.y, hb, lb);
    hi.y = packh(ha, hb); lo.y = packh(la, lb);
    split_h(a.z, ha, la); split_h(b.z, hb, lb);
    hi.z = packh(ha, hb); lo.z = packh(la, lb);
    split_h(a.w, ha, la); split_h(b.w, hb, lb);
    hi.w = packh(ha, hb); lo.w = packh(la, lb);
}
__device__ __forceinline__ uint32_t smem_to_u32(const void* p) {
    uint32_t a;
    asm("{ .reg .u64 t; cvta.to.shared.u64 t, %1; cvt.u32.u64 %0, t; }" : "=r"(a) : "l"(p));
    return a;
}
__device__ __forceinline__ void cp16(uint32_t s, const void* g) {
    asm volatile("cp.async.cg.shared.global [%0], [%1], 16;"
                 :: "r"(s), "l"(__cvta_generic_to_global(g)) : "memory");
}
#define CP_COMMIT() asm volatile("cp.async.commit_group;" ::: "memory")
#define CP_WAIT(n)  asm volatile("cp.async.wait_group %0;" :: "n"(n) : "memory")

// ---------------- 1) fused q/k/v projection via fp16x3 MMA ----------------
#define QKV_SMEM_BYTES ((2 * 64 * 20 + 2 * 16 * 136) * 4)
__global__ __launch_bounds__(256) void k_qkv_tc(
    const float* __restrict__ x,
    const float* __restrict__ Wq, const float* __restrict__ bq,
    const float* __restrict__ Wk, const float* __restrict__ bk,
    const float* __restrict__ Wv, const float* __restrict__ bv)
{
    extern __shared__ uint32_t qsm[];
    uint32_t* PWh = qsm;
    uint32_t* PWl = qsm + 64 * 20;
    uint32_t* PBh = qsm + 2 * 64 * 20;
    uint32_t* PBl = PBh + 16 * 136;

    int b     = blockIdx.z;
    int rows0 = blockIdx.y * 64;
    int pos0  = blockIdx.x * 128;
    int tid = threadIdx.x, wid = tid >> 5, lane = tid & 31;
    int gid = lane >> 2, tq = lane & 3;
    int wm = (wid >> 1) * 16;
    int wn = (wid & 1) * 64;
    const float* xb = x + (size_t)b * (CC * NPOS);

    float acc[8][4] = {};

    for (int kc = 0; kc < 128; kc += 32) {
#pragma unroll
        for (int q = 0; q < 2; q++) {
            int e = tid + q * 256;
            int row = e >> 3, kg = e & 7;
            int r = rows0 + row;
            float4 v = make_float4(0.f, 0.f, 0.f, 0.f);
            if (r < 16)       v = *(const float4*)(Wq + r * 128 + kc + kg * 4);
            else if (r < 32)  v = *(const float4*)(Wk + (r - 16) * 128 + kc + kg * 4);
            else if (r < 160) v = *(const float4*)(Wv + (r - 32) * 128 + kc + kg * 4);
            __half h0, l0, h1, l1, h2, l2, h3, l3;
            split_h(v.x, h0, l0); split_h(v.y, h1, l1);
            split_h(v.z, h2, l2); split_h(v.w, h3, l3);
            uint2 hp = make_uint2(packh(h0, h1), packh(h2, h3));
            uint2 lp = make_uint2(packh(l0, l1), packh(l2, l3));
            *(uint2*)&PWh[row * 20 + kg * 2] = hp;
            *(uint2*)&PWl[row * 20 + kg * 2] = lp;
        }
#pragma unroll
        for (int q = 0; q < 2; q++) {
            int e = tid + q * 256;
            int kp = e >> 5, ng = e & 31;
            const float* r0p = xb + (size_t)(kc + 2 * kp) * NPOS + pos0 + ng * 4;
            float4 v0 = *(const float4*)r0p;
            float4 v1 = *(const float4*)(r0p + NPOS);
            uint4 hi, lo;
            pack2rows(v0, v1, hi, lo);
            *(uint4*)&PBh[kp * 136 + ng * 4] = hi;
            *(uint4*)&PBl[kp * 136 + ng * 4] = lo;
        }
        __syncthreads();
#pragma unroll
        for (int kk2 = 0; kk2 < 16; kk2 += 8) {
            uint32_t Af[4], Alf[4], Bf[8][2], Blf[8][2];
            int row = wm + gid;
            Af[0]  = PWh[row * 20 + kk2 + tq];
            Af[1]  = PWh[(row + 8) * 20 + kk2 + tq];
            Af[2]  = PWh[row * 20 + kk2 + tq + 4];
            Af[3]  = PWh[(row + 8) * 20 + kk2 + tq + 4];
            Alf[0] = PWl[row * 20 + kk2 + tq];
            Alf[1] = PWl[(row + 8) * 20 + kk2 + tq];
            Alf[2] = PWl[row * 20 + kk2 + tq + 4];
            Alf[3] = PWl[(row + 8) * 20 + kk2 + tq + 4];
#pragma unroll
            for (int j = 0; j < 8; j++) {
                int n = wn + 8 * j + gid;
                Bf[j][0]  = PBh[(kk2 + tq) * 136 + n];
                Bf[j][1]  = PBh[(kk2 + tq + 4) * 136 + n];
                Blf[j][0] = PBl[(kk2 + tq) * 136 + n];
                Blf[j][1] = PBl[(kk2 + tq + 4) * 136 + n];
            }
#pragma unroll
            for (int j = 0; j < 8; j++) mma_f16(acc[j], Af,  Bf[j]);
#pragma unroll
            for (int j = 0; j < 8; j++) mma_f16(acc[j], Af,  Blf[j]);
#pragma unroll
            for (int j = 0; j < 8; j++) mma_f16(acc[j], Alf, Bf[j]);
        }
        __syncthreads();
    }

    int t   = pos0 >> 10;
    int hw0 = pos0 & 1023;
#pragma unroll
    for (int j = 0; j < 8; j++) {
        int hw = hw0 + wn + 8 * j + 2 * tq;
#pragma unroll
        for (int half = 0; half < 2; half++) {
            int r = rows0 + wm + gid + half * 8;
            if (r >= 160) continue;
            float v0 = acc[j][half * 2 + 0];
            float v1 = acc[j][half * 2 + 1];
            if (r < 16) {
                float bias = bq[r];
                *(float2*)&g_qf[b][r * TT + t][hw] = make_float2(v0 + bias, v1 + bias);
            } else if (r < 32) {
                float bias = bk[r - 16];
                *(float2*)&g_kf[b][(r - 16) * TT + t][hw] = make_float2(v0 + bias, v1 + bias);
            } else {
                float bias = bv[r - 32];
                int row = (r - 32) * TT + t;
                *(uint32_t*)&g_vf_s[b][row][hw] =
                    packh(__float2half_rn(v0 + bias), __float2half_rn(v1 + bias));
            }
        }
    }
}

// ---------------- 2) PAM energy via fp16x3 MMA (packed k-pairs) ----------------
#define EN_SMEM_BYTES (4 * 16 * 136 * 4)
__global__ __launch_bounds__(256, 2) void k_energy_tc()
{
    extern __shared__ uint32_t esm[];
    uint32_t* Ah = esm;
    uint32_t* Al = esm + 16 * 136;
    uint32_t* Bh = esm + 2 * 16 * 136;
    uint32_t* Bl = esm + 3 * 16 * 136;

    int b  = blockIdx.z;
    int n0 = blockIdx.y * 128;
    int m0 = blockIdx.x * 128;
    int tid = threadIdx.x, wid = tid >> 5, lane = tid & 31;
    int gid = lane >> 2, tq = lane & 3;
    int wm = (wid >> 1) * 32;
    int wn = (wid & 1) * 64;

    float acc[2][8][4] = {};

    for (int kc = 0; kc < 128; kc += 32) {
#pragma unroll
        for (int q = 0; q < 2; q++) {
            int e = tid + q * 256;
            int kp = e >> 5, ng = e & 31;
            const float* qa = &g_qf[b][kc + 2 * kp][n0 + ng * 4];
            const float* kb = &g_kf[b][kc + 2 * kp][m0 + ng * 4];
            float4 va0 = *(const float4*)qa;
            float4 va1 = *(const float4*)(qa + HWD);
            float4 vb0 = *(const float4*)kb;
            float4 vb1 = *(const float4*)(kb + HWD);
            uint4 hi, lo;
            pack2rows(va0, va1, hi, lo);
            *(uint4*)&Ah[kp * 136 + ng * 4] = hi;
            *(uint4*)&Al[kp * 136 + ng * 4] = lo;
            pack2rows(vb0, vb1, hi, lo);
            *(uint4*)&Bh[kp * 136 + ng * 4] = hi;
            *(uint4*)&Bl[kp * 136 + ng * 4] = lo;
        }
        __syncthreads();
#pragma unroll
        for (int kk2 = 0; kk2 < 16; kk2 += 8) {
            uint32_t Af[2][4], Alf[2][4], Bf[8][2], Blf[8][2];
#pragma unroll
            for (int i = 0; i < 2; i++) {
                int m = wm + 16 * i + gid;
                Af[i][0]  = Ah[(kk2 + tq) * 136 + m];
                Af[i][1]  = Ah[(kk2 + tq) * 136 + m + 8];
                Af[i][2]  = Ah[(kk2 + tq + 4) * 136 + m];
                Af[i][3]  = Ah[(kk2 + tq + 4) * 136 + m + 8];
                Alf[i][0] = Al[(kk2 + tq) * 136 + m];
                Alf[i][1] = Al[(kk2 + tq) * 136 + m + 8];
                Alf[i][2] = Al[(kk2 + tq + 4) * 136 + m];
                Alf[i][3] = Al[(kk2 + tq + 4) * 136 + m + 8];
            }
#pragma unroll
            for (int j = 0; j < 8; j++) {
                int n = wn + 8 * j + gid;
                Bf[j][0]  = Bh[(kk2 + tq) * 136 + n];
                Bf[j][1]  = Bh[(kk2 + tq + 4) * 136 + n];
                Blf[j][0] = Bl[(kk2 + tq) * 136 + n];
                Blf[j][1] = Bl[(kk2 + tq + 4) * 136 + n];
            }
#pragma unroll
            for (int j = 0; j < 8; j++)
#pragma unroll
                for (int i = 0; i < 2; i++) mma_f16(acc[i][j], Af[i], Bf[j]);
#pragma unroll
            for (int j = 0; j < 8; j++)
#pragma unroll
                for (int i = 0; i < 2; i++) mma_f16(acc[i][j], Af[i], Blf[j]);
#pragma unroll
            for (int j = 0; j < 8; j++)
#pragma unroll
                for (int i = 0; i < 2; i++) mma_f16(acc[i][j], Alf[i], Bf[j]);
        }
        __syncthreads();
    }

#pragma unroll
    for (int i = 0; i < 2; i++)
#pragma unroll
        for (int j = 0; j < 8; j++) {
            int n = n0 + wm + 16 * i + gid;
            int m = m0 + wn + 8 * j + 2 * tq;
            *(float2*)&g_attn[b][n][m]     = make_float2(acc[i][j][0], acc[i][j][1]);
            *(float2*)&g_attn[b][n + 8][m] = make_float2(acc[i][j][2], acc[i][j][3]);
        }
}

// ---------------- 3) softmax -> single fp16 (vectorized) ----------------
__global__ __launch_bounds__(256) void k_softmax()
{
    int row = blockIdx.x;
    int tid = threadIdx.x;
    const float4* e4 = (const float4*)(&g_attn[0][0][0] + (size_t)row * 1024);
    float4 v = e4[tid];
    float m = fmaxf(fmaxf(v.x, v.y), fmaxf(v.z, v.w));
    __shared__ float red[8];
#pragma unroll
    for (int o = 16; o > 0; o >>= 1) m = fmaxf(m, __shfl_xor_sync(0xffffffffu, m, o));
    if ((tid & 31) == 0) red[tid >> 5] = m;
    __syncthreads();
    m = red[0];
#pragma unroll
    for (int j = 1; j < 8; j++) m = fmaxf(m, red[j]);
    v.x = __expf(v.x - m); v.y = __expf(v.y - m);
    v.z = __expf(v.z - m); v.w = __expf(v.w - m);
    float s = (v.x + v.y) + (v.z + v.w);
    __syncthreads();
#pragma unroll
    for (int o = 16; o > 0; o >>= 1) s += __shfl_xor_sync(0xffffffffu, s, o);
    if ((tid & 31) == 0) red[tid >> 5] = s;
    __syncthreads();
    s = red[0];
#pragma unroll
    for (int j = 1; j < 8; j++) s += red[j];
    float inv = 1.f / s;
    v.x *= inv; v.y *= inv; v.z *= inv; v.w *= inv;

    uint2 hp;
    hp.x = packh(__float2half_rn(v.x), __float2half_rn(v.y));
    hp.y = packh(__float2half_rn(v.z), __float2half_rn(v.w));
    ((uint2*)(&g_attn_s[0][0][0] + (size_t)row * 1024))[tid] = hp;
}

// ---------------- 4) CAM energy fp16x3 Gram ----------------
#define CPAD 40
#define CAME_SMEM_BYTES (32768 + 2 * 128 * CPAD * 2)
__global__ __launch_bounds__(256, 2) void k_came_tc(const float* __restrict__ x)
{
    extern __shared__ char csm[];
    float* raw = (float*)csm;
    __half* Xh = (__half*)(csm + 32768);
    __half* Xl = (__half*)(csm + 32768 + 128 * CPAD * 2);
    uint32_t rawb = smem_to_u32(raw);

    int b  = blockIdx.x >> 5;
    int sl = blockIdx.x & 31;
    int tid = threadIdx.x, wid = tid >> 5, lane = tid & 31;
    int gid = lane >> 2, tq = lane & 3;
    int wm = (wid >> 1) * 32;
    int wn = (wid & 1) * 64;
    const float* xb = x + (size_t)b * (CC * NPOS) + sl * 256;

    float acc[2][8][4] = {};

    auto load_raw = [&](int st, int kc) {
#pragma unroll
        for (int q = 0; q < 4; q++) {
            int e = tid + q * 256;
            int row = e >> 3, c4 = e & 7;
            cp16(rawb + (uint32_t)(st * 4096 + row * 32 + c4 * 4) * 4,
                 xb + (size_t)row * NPOS + kc + c4 * 4);
        }
        CP_COMMIT();
    };

    load_raw(0, 0);

    for (int it = 0; it < 8; it++) {
        int st = it & 1;
        if (it < 7) { load_raw(st ^ 1, (it + 1) * 32); CP_WAIT(1); }
        else        { CP_WAIT(0); }
        __syncthreads();

#pragma unroll
        for (int q = 0; q < 4; q++) {
            int e = tid + q * 256;
            int row = e >> 3, c4 = e & 7;
            float4 v = *(const float4*)&raw[st * 4096 + row * 32 + c4 * 4];
            __half hx, lx, hy, ly, hz, lz, hw, lw;
            split_h(v.x, hx, lx); split_h(v.y, hy, ly);
            split_h(v.z, hz, lz); split_h(v.w, hw, lw);
            uint2 hp, lp;
            hp.x = packh(hx, hy); hp.y = packh(hz, hw);
            lp.x = packh(lx, ly); lp.y = packh(lz, lw);
            *(uint2*)&Xh[row * CPAD + c4 * 4] = hp;
            *(uint2*)&Xl[row * CPAD + c4 * 4] = lp;
        }
        __syncthreads();

#pragma unroll
        for (int kk = 0; kk < 32; kk += 16) {
            uint32_t Af[2][4], Alf[2][4], Bf[8][2], Blf[8][2];
            int c0 = kk + 2 * tq, c1 = c0 + 8;
#pragma unroll
            for (int i = 0; i < 2; i++) {
                int r0 = wm + 16 * i + gid, r1 = r0 + 8;
                Af[i][0]  = *(const uint32_t*)&Xh[r0 * CPAD + c0];
                Af[i][1]  = *(const uint32_t*)&Xh[r1 * CPAD + c0];
                Af[i][2]  = *(const uint32_t*)&Xh[r0 * CPAD + c1];
                Af[i][3]  = *(const uint32_t*)&Xh[r1 * CPAD + c1];
                Alf[i][0] = *(const uint32_t*)&Xl[r0 * CPAD + c0];
                Alf[i][1] = *(const uint32_t*)&Xl[r1 * CPAD + c0];
                Alf[i][2] = *(const uint32_t*)&Xl[r0 * CPAD + c1];
                Alf[i][3] = *(const uint32_t*)&Xl[r1 * CPAD + c1];
            }
#pragma unroll
            for (int j = 0; j < 8; j++) {
                int rn = wn + 8 * j + gid;
                Bf[j][0]  = *(const uint32_t*)&Xh[rn * CPAD + c0];
                Bf[j][1]  = *(const uint32_t*)&Xh[rn * CPAD + c1];
                Blf[j][0] = *(const uint32_t*)&Xl[rn * CPAD + c0];
                Blf[j][1] = *(const uint32_t*)&Xl[rn * CPAD + c1];
            }
#pragma unroll
            for (int j = 0; j < 8; j++)
#pragma unroll
                for (int i = 0; i < 2; i++) mma_f16(acc[i][j], Af[i], Bf[j]);
#pragma unroll
            for (int j = 0; j < 8; j++)
#pragma unroll
                for (int i = 0; i < 2; i++) mma_f16(acc[i][j], Af[i], Blf[j]);
#pragma unroll
            for (int j = 0; j < 8; j++)
#pragma unroll
                for (int i = 0; i < 2; i++) mma_f16(acc[i][j], Alf[i], Bf[j]);
        }
    }

#pragma unroll
    for (int i = 0; i < 2; i++)
#pragma unroll
        for (int j = 0; j < 8; j++) {
            int c = wm + 16 * i + gid;
            int d = wn + 8 * j + 2 * tq;
            *(float2*)&g_ecam_p[sl][b][c][d]     = make_float2(acc[i][j][0], acc[i][j][1]);
            *(float2*)&g_ecam_p[sl][b][c + 8][d] = make_float2(acc[i][j][2], acc[i][j][3]);
        }
}

// ---------------- 5) CAM negated-energy softmax ----------------
__global__ __launch_bounds__(128) void k_camsm()
{
    int b = blockIdx.x >> 7;
    int c = blockIdx.x & 127;
    int d = threadIdx.x;
    float ev = 0.f;
#pragma unroll
    for (int sl = 0; sl < 32; sl++) ev += g_ecam_p[sl][b][c][d];
    __shared__ float red[4];
    float mn = ev;
#pragma unroll
    for (int o = 16; o > 0; o >>= 1) mn = fminf(mn, __shfl_xor_sync(0xffffffffu, mn, o));
    if ((threadIdx.x & 31) == 0) red[threadIdx.x >> 5] = mn;
    __syncthreads();
    mn = fminf(fminf(red[0], red[1]), fminf(red[2], red[3]));
    float w = __expf(mn - ev);
    __syncthreads();
    float s = w;
#pragma unroll
    for (int o = 16; o > 0; o >>= 1) s += __shfl_xor_sync(0xffffffffu, s, o);
    if ((threadIdx.x & 31) == 0) red[threadIdx.x >> 5] = s;
    __syncthreads();
    s = (red[0] + red[1]) + (red[2] + red[3]);
    g_acam[b][c][d] = w / s;
}

// ---------------- 6) TIM Gram partials ----------------
__global__ __launch_bounds__(256) void k_time(const float* __restrict__ x)
{
    int c = blockIdx.x;
    int b = blockIdx.y;
    int tid = threadIdx.x;
    const float* xp = x + ((size_t)b * CC + c) * NPOS;
    float v[8][4];
#pragma unroll
    for (int t = 0; t < 8; t++) {
        float4 f = *reinterpret_cast<const float4*>(xp + t * 1024 + tid * 4);
        v[t][0] = f.x; v[t][1] = f.y; v[t][2] = f.z; v[t][3] = f.w;
    }
    float acc[36];
    int idx = 0;
#pragma unroll
    for (int t = 0; t < 8; t++)
#pragma unroll
        for (int s = t; s < 8; s++) {
            float a = 0.f;
#pragma unroll
            for (int j = 0; j < 4; j++) a += v[t][j] * v[s][j];
            acc[idx++] = a;
        }
    __shared__ float red[36][8];
    int lane = tid & 31, warp = tid >> 5;
#pragma unroll
    for (int i = 0; i < 36; i++) {
        float a = acc[i];
#pragma unroll
        for (int o = 16; o > 0; o >>= 1) a += __shfl_xor_sync(0xffffffffu, a, o);
        if (lane == 0) red[i][warp] = a;
    }
    __syncthreads();
    if (tid < 36) {
        float a = 0.f;
#pragma unroll
        for (int w = 0; w < 8; w++) a += red[tid][w];
        g_etim_p[b][c][tid] = a;
    }
}

// ---------------- 6b) TIM partial reduce over channels (parallel) ----------------
__global__ __launch_bounds__(128) void k_timred()
{
    int i = blockIdx.x;   // 0..35
    int b = blockIdx.y;   // 0..7
    int tid = threadIdx.x;
    float a = g_etim_p[b][tid][i];
#pragma unroll
    for (int o = 16; o > 0; o >>= 1) a += __shfl_xor_sync(0xffffffffu, a, o);
    __shared__ float r[4];
    if ((tid & 31) == 0) r[tid >> 5] = a;
    __syncthreads();
    if (tid == 0) g_etim36[b][i] = (r[0] + r[1]) + (r[2] + r[3]);
}

// ---------------- 7) TIM softmax (tiny) ----------------
__global__ __launch_bounds__(64) void k_timsm()
{
    int tid = threadIdx.x;
    int b = tid >> 3, t = tid & 7;
    float e[8];
#pragma unroll
    for (int s = 0; s < 8; s++) {
        int lo = t < s ? t : s, hi = t < s ? s : t;
        int idx = 8 * lo - lo * (lo - 1) / 2 + (hi - lo);
        e[s] = g_etim36[b][idx];
    }
    float mn = e[0];
#pragma unroll
    for (int s = 1; s < 8; s++) mn = fminf(mn, e[s]);
    float w[8], sum = 0.f;
#pragma unroll
    for (int s = 0; s < 8; s++) { w[s] = __expf(mn - e[s]); sum += w[s]; }
#pragma unroll
    for (int s = 0; s < 8; s++) g_atim[b][t][s] = w[s] / sum;
}

// ---------------- 8) base: out = 3x + gc*(a_cam@xc) + gt*tim ----------------
__global__ __launch_bounds__(256) void k_base(
    const float* __restrict__ x,
    const float* __restrict__ gcp, const float* __restrict__ gtp,
    float* __restrict__ out)
{
    int b   = blockIdx.z;
    int c0  = blockIdx.y * 32;
    int hw0 = blockIdx.x * 32;
    __shared__ float As[32][33];
    __shared__ float Xs[32][8][33];
    __shared__ float at8[8][8];
    int tid = threadIdx.x;
    int hw_l = tid & 31, cg = tid >> 5;
    if (tid < 64) at8[tid >> 3][tid & 7] = g_atim[b][tid >> 3][tid & 7];
    float acc[4][8] = {};
    const float* xb = x + (size_t)b * (CC * NPOS);

    for (int kc = 0; kc < CC; kc += 32) {
#pragma unroll
        for (int q = 0; q < 4; q++) {
            int e = tid + q * 256;
            int i = e >> 5, k = e & 31;
            As[i][k] = g_acam[b][c0 + i][kc + k];
        }
#pragma unroll
        for (int q = 0; q < 32; q++) {
            int e = tid + q * 256;
            int k = e >> 8, t = (e >> 5) & 7, hw = e & 31;
            Xs[k][t][hw] = xb[(size_t)(kc + k) * NPOS + t * 1024 + hw0 + hw];
        }
        __syncthreads();
#pragma unroll
        for (int k = 0; k < 32; k++) {
            float av[4], xv[8];
#pragma unroll
            for (int j = 0; j < 4; j++) av[j] = As[cg + 8 * j][k];
#pragma unroll
            for (int t = 0; t < 8; t++) xv[t] = Xs[k][t][hw_l];
#pragma unroll
            for (int j = 0; j < 4; j++)
#pragma unroll
                for (int t = 0; t < 8; t++) acc[j][t] += av[j] * xv[t];
        }
        __syncthreads();
    }

    float gc = gcp[0], gt = gtp[0];
#pragma unroll
    for (int j = 0; j < 4; j++) {
        int c = c0 + cg + 8 * j;
        const float* xc = xb + (size_t)c * NPOS + hw0 + hw_l;
        float xrow[8];
#pragma unroll
        for (int s = 0; s < 8; s++) xrow[s] = xc[s * 1024];
        float* oc = out + (size_t)b * (CC * NPOS) + (size_t)c * NPOS + hw0 + hw_l;
#pragma unroll
        for (int t = 0; t < 8; t++) {
            float tim = 0.f;
#pragma unroll
            for (int s = 0; s < 8; s++) tim += at8[t][s] * xrow[s];
            oc[t * 1024] = 3.f * xrow[t] + gc * acc[j][t] + gt * tim;
        }
    }
}

// ---------------- 9) PAM GEMM: single-term fp16, cp.async 2-stage ----------------
#define PAD 40
#define PAM_TILE 5120
#define PAM_STAGE (2 * PAM_TILE)
#define PAM_SMEM_BYTES (2 * PAM_STAGE * 2)
__global__ __launch_bounds__(256, 2) void k_pam_mma(const float* __restrict__ gpp,
                                                    float* __restrict__ out)
{
    extern __shared__ __half smp[];
    uint32_t smb = smem_to_u32(smp);

    int tid = threadIdx.x;
    int b  = blockIdx.z;
    int r0 = blockIdx.y * 128;
    int n0 = blockIdx.x * 128;
    int wid = tid >> 5, lane = tid & 31;
    int gid = lane >> 2, tq = lane & 3;
    int wm = (wid & 1) * 64;
    int wn = (wid >> 1) * 32;

    const __half* Asp = &g_vf_s[b][0][0];
    const __half* Bsp = &g_attn_s[b][0][0];

    float acc[4][4][4] = {};

    auto stage_load = [&](int st, int kc) {
#pragma unroll
        for (int q = 0; q < 2; q++) {
            int e = tid + q * 256;
            int row = e >> 2, c4 = e & 3;
            uint32_t so = smb + (uint32_t)(st * PAM_STAGE + row * PAD + c4 * 8) * 2;
            size_t gA = (size_t)(r0 + row) * 1024 + kc + c4 * 8;
            size_t gB = (size_t)(n0 + row) * 1024 + kc + c4 * 8;
            cp16(so,                Asp + gA);
            cp16(so + PAM_TILE * 2, Bsp + gB);
        }
        CP_COMMIT();
    };

    stage_load(0, 0);

    for (int it = 0; it < 32; it++) {
        int st = it & 1;
        if (it < 31) { stage_load(st ^ 1, (it + 1) * 32); CP_WAIT(1); }
        else         { CP_WAIT(0); }
        __syncthreads();

        const __half* sAs = smp + st * PAM_STAGE;
        const __half* sBs = sAs + PAM_TILE;

#pragma unroll
        for (int ks = 0; ks < 32; ks += 16) {
            uint32_t Af[4][4], Bf[4][2];
            int col = ks + tq * 2;
#pragma unroll
            for (int i = 0; i < 4; i++) {
                int row = wm + 16 * i + gid;
                Af[i][0] = *(const uint32_t*)&sAs[row * PAD + col];
                Af[i][1] = *(const uint32_t*)&sAs[(row + 8) * PAD + col];
                Af[i][2] = *(const uint32_t*)&sAs[row * PAD + col + 8];
                Af[i][3] = *(const uint32_t*)&sAs[(row + 8) * PAD + col + 8];
            }
#pragma unroll
            for (int j = 0; j < 4; j++) {
                int nrow = wn + 8 * j + gid;
                Bf[j][0] = *(const uint32_t*)&sBs[nrow * PAD + col];
                Bf[j][1] = *(const uint32_t*)&sBs[nrow * PAD + col + 8];
            }
#pragma unroll
            for (int j = 0; j < 4; j++)
#pragma unroll
                for (int i = 0; i < 4; i++) mma_f16(acc[i][j], Af[i], Bf[j]);
        }
        __syncthreads();
    }

    float gpv = gpp[0];
    float* ob = out + (size_t)b * (CT * HWD);
#pragma unroll
    for (int i = 0; i < 4; i++) {
#pragma unroll
        for (int j = 0; j < 4; j++) {
            int r = r0 + wm + 16 * i + gid;
            int n = n0 + wn + 8 * j + tq * 2;
            float2* p0 = (float2*)(ob + (size_t)r * 1024 + n);
            float2 v0 = *p0;
            v0.x += gpv * acc[i][j][0];
            v0.y += gpv * acc[i][j][1];
            *p0 = v0;
            float2* p1 = (float2*)(ob + (size_t)(r + 8) * 1024 + n);
            float2 v1 = *p1;
            v1.x += gpv * acc[i][j][2];
            v1.y += gpv * acc[i][j][3];
            *p1 = v1;
        }
    }
}

// ---------------- launch: three-stream fork/join overlap ----------------
extern "C" void kernel_launch(void* const* d_in, const int* in_sizes, int n_in,
                              void* d_out, int out_size)
{
    const float* x  = (const float*)d_in[0];
    const float* Wq = (const float*)d_in[1];
    const float* bq = (const float*)d_in[2];
    const float* Wk = (const float*)d_in[3];
    const float* bk = (const float*)d_in[4];
    const float* Wv = (const float*)d_in[5];
    const float* bv = (const float*)d_in[6];
    const float* gp = (const float*)d_in[7];
    const float* gc = (const float*)d_in[8];
    const float* gt = (const float*)d_in[9];
    float* out = (float*)d_out;

    static cudaStream_t s2 = nullptr, s3 = nullptr;
    static cudaEvent_t evFork = nullptr, evTim = nullptr, evJoin = nullptr;
    static int attrs_set = 0;
    if (!attrs_set) {
        cudaFuncSetAttribute(k_qkv_tc, cudaFuncAttributeMaxDynamicSharedMemorySize, QKV_SMEM_BYTES);
        cudaFuncSetAttribute(k_energy_tc, cudaFuncAttributeMaxDynamicSharedMemorySize, EN_SMEM_BYTES);
        cudaFuncSetAttribute(k_came_tc, cudaFuncAttributeMaxDynamicSharedMemorySize, CAME_SMEM_BYTES);
        cudaFuncSetAttribute(k_pam_mma, cudaFuncAttributeMaxDynamicSharedMemorySize, PAM_SMEM_BYTES);
        cudaStreamCreateWithFlags(&s2, cudaStreamNonBlocking);
        cudaStreamCreateWithFlags(&s3, cudaStreamNonBlocking);
        cudaEventCreateWithFlags(&evFork, cudaEventDisableTiming);
        cudaEventCreateWithFlags(&evTim, cudaEventDisableTiming);
        cudaEventCreateWithFlags(&evJoin, cudaEventDisableTiming);
        attrs_set = 1;
    }

    // fork
    cudaEventRecord(evFork, 0);
    cudaStreamWaitEvent(s2, evFork, 0);
    cudaStreamWaitEvent(s3, evFork, 0);

    // chain B1 on s2: CAM
    k_came_tc<<<256, 256, CAME_SMEM_BYTES, s2>>>(x);
    k_camsm<<<1024, 128, 0, s2>>>();
    // chain B2 on s3: TIM
    k_time<<<dim3(128, 8), 256, 0, s3>>>(x);
    k_timred<<<dim3(36, 8), 128, 0, s3>>>();
    k_timsm<<<1, 64, 0, s3>>>();
    // base on s2 after both B1 and B2
    cudaEventRecord(evTim, s3);
    cudaStreamWaitEvent(s2, evTim, 0);
    k_base<<<dim3(32, 4, 8), 256, 0, s2>>>(x, gc, gt, out);

    // chain A on default
    k_qkv_tc<<<dim3(64, 3, 8), 256, QKV_SMEM_BYTES>>>(x, Wq, bq, Wk, bk, Wv, bv);
    k_energy_tc<<<dim3(8, 8, 8), 256, EN_SMEM_BYTES>>>();
    k_softmax<<<8192, 256>>>();

    // join: pam needs softmax (A) and base's out (B)
    cudaEventRecord(evJoin, s2);
    cudaStreamWaitEvent(0, evJoin, 0);
    k_pam_mma<<<dim3(8, 8, 8), 256, PAM_SMEM_BYTES>>>(gp, out);
}

// round 16
// speedup vs baseline: 1.4633x; 1.1577x over previous
#include <cuda_runtime.h>
#include <cuda_fp16.h>
#include <math.h>
#include <stdint.h>

#define BB 8
#define CC 128
#define TT 8
#define HWD 1024
#define NPOS 8192
#define CT 1024

// ---------------- scratch ----------------
__device__ float g_qf[BB][128][HWD];
__device__ float g_kf[BB][128][HWD];
__device__ __half g_vf_s[BB][CT][HWD];
__device__ float g_attn[BB][HWD][HWD];
__device__ __half g_attn_s[BB][HWD][HWD];
__device__ float g_ecam_p[32][BB][CC][CC];
__device__ float g_acam[BB][CC][CC];
__device__ float g_cam[BB][CC][NPOS];
__device__ float g_etim_p[BB][CC][36];
__device__ float g_etim36[BB][36];
__device__ float g_atim[BB][TT][TT];

// ---------------- helpers ----------------
__device__ __forceinline__ void mma_f16(float* c, const uint32_t* a, const uint32_t* b) {
    asm volatile(
        "mma.sync.aligned.m16n8k16.row.col.f32.f16.f16.f32 "
        "{%0,%1,%2,%3}, {%4,%5,%6,%7}, {%8,%9}, {%0,%1,%2,%3};"
        : "+f"(c[0]), "+f"(c[1]), "+f"(c[2]), "+f"(c[3])
        : "r"(a[0]), "r"(a[1]), "r"(a[2]), "r"(a[3]), "r"(b[0]), "r"(b[1]));
}
__device__ __forceinline__ void split_h(float a, __half& h, __half& l) {
    h = __float2half_rn(a);
    l = __float2half_rn(a - __half2float(h));
}
__device__ __forceinline__ uint32_t packh(__half a, __half b) {
    return ((uint32_t)__half_as_ushort(b) << 16) | __half_as_ushort(a);
}
__device__ __forceinline__ void pack2rows(float4 a, float4 b, uint4& hi, uint4& lo) {
    __half ha, la, hb, lb;
    split_h(a.x, ha, la); split_h(b.x, hb, lb);
    hi.x = packh(ha, hb); lo.x = packh(la, lb);
    split_h(a.y, ha, la); split_h(b.y, hb, lb);
    hi.y = packh(ha, hb); lo.y = packh(la, lb);
    split_h(a.z, ha, la); split_h(b.z, hb, lb);
    hi.z = packh(ha, hb); lo.z = packh(la, lb);
    split_h(a.w, ha, la); split_h(b.w, hb, lb);
    hi.w = packh(ha, hb); lo.w = packh(la, lb);
}
__device__ __forceinline__ uint4 pack2rows_hi(float4 a, float4 b) {
    uint4 hi;
    hi.x = packh(__float2half_rn(a.x), __float2half_rn(b.x));
    hi.y = packh(__float2half_rn(a.y), __float2half_rn(b.y));
    hi.z = packh(__float2half_rn(a.z), __float2half_rn(b.z));
    hi.w = packh(__float2half_rn(a.w), __float2half_rn(b.w));
    return hi;
}
__device__ __forceinline__ uint2 pack4_hi(float4 v) {
    uint2 p;
    p.x = packh(__float2half_rn(v.x), __float2half_rn(v.y));
    p.y = packh(__float2half_rn(v.z), __float2half_rn(v.w));
    return p;
}
__device__ __forceinline__ uint32_t smem_to_u32(const void* p) {
    uint32_t a;
    asm("{ .reg .u64 t; cvta.to.shared.u64 t, %1; cvt.u32.u64 %0, t; }" : "=r"(a) : "l"(p));
    return a;
}
__device__ __forceinline__ void cp16(uint32_t s, const void* g) {
    asm volatile("cp.async.cg.shared.global [%0], [%1], 16;"
                 :: "r"(s), "l"(__cvta_generic_to_global(g)) : "memory");
}
#define CP_COMMIT() asm volatile("cp.async.commit_group;" ::: "memory")
#define CP_WAIT(n)  asm volatile("cp.async.wait_group %0;" :: "n"(n) : "memory")

// ---------------- 1) fused q/k/v projection via fp16x3 MMA ----------------
#define QKV_SMEM_BYTES ((2 * 64 * 20 + 2 * 16 * 136) * 4)
__global__ __launch_bounds__(256) void k_qkv_tc(
    const float* __restrict__ x,
    const float* __restrict__ Wq, const float* __restrict__ bq,
    const float* __restrict__ Wk, const float* __restrict__ bk,
    const float* __restrict__ Wv, const float* __restrict__ bv)
{
    extern __shared__ uint32_t qsm[];
    uint32_t* PWh = qsm;
    uint32_t* PWl = qsm + 64 * 20;
    uint32_t* PBh = qsm + 2 * 64 * 20;
    uint32_t* PBl = PBh + 16 * 136;

    int b     = blockIdx.z;
    int rows0 = blockIdx.y * 64;
    int pos0  = blockIdx.x * 128;
    int tid = threadIdx.x, wid = tid >> 5, lane = tid & 31;
    int gid = lane >> 2, tq = lane & 3;
    int wm = (wid >> 1) * 16;
    int wn = (wid & 1) * 64;
    const float* xb = x + (size_t)b * (CC * NPOS);

    float acc[8][4] = {};

    for (int kc = 0; kc < 128; kc += 32) {
#pragma unroll
        for (int q = 0; q < 2; q++) {
            int e = tid + q * 256;
            int row = e >> 3, kg = e & 7;
            int r = rows0 + row;
            float4 v = make_float4(0.f, 0.f, 0.f, 0.f);
            if (r < 16)       v = *(const float4*)(Wq + r * 128 + kc + kg * 4);
            else if (r < 32)  v = *(const float4*)(Wk + (r - 16) * 128 + kc + kg * 4);
            else if (r < 160) v = *(const float4*)(Wv + (r - 32) * 128 + kc + kg * 4);
            __half h0, l0, h1, l1, h2, l2, h3, l3;
            split_h(v.x, h0, l0); split_h(v.y, h1, l1);
            split_h(v.z, h2, l2); split_h(v.w, h3, l3);
            uint2 hp = make_uint2(packh(h0, h1), packh(h2, h3));
            uint2 lp = make_uint2(packh(l0, l1), packh(l2, l3));
            *(uint2*)&PWh[row * 20 + kg * 2] = hp;
            *(uint2*)&PWl[row * 20 + kg * 2] = lp;
        }
#pragma unroll
        for (int q = 0; q < 2; q++) {
            int e = tid + q * 256;
            int kp = e >> 5, ng = e & 31;
            const float* r0p = xb + (size_t)(kc + 2 * kp) * NPOS + pos0 + ng * 4;
            float4 v0 = *(const float4*)r0p;
            float4 v1 = *(const float4*)(r0p + NPOS);
            uint4 hi, lo;
            pack2rows(v0, v1, hi, lo);
            *(uint4*)&PBh[kp * 136 + ng * 4] = hi;
            *(uint4*)&PBl[kp * 136 + ng * 4] = lo;
        }
        __syncthreads();
#pragma unroll
        for (int kk2 = 0; kk2 < 16; kk2 += 8) {
            uint32_t Af[4], Alf[4], Bf[8][2], Blf[8][2];
            int row = wm + gid;
            Af[0]  = PWh[row * 20 + kk2 + tq];
            Af[1]  = PWh[(row + 8) * 20 + kk2 + tq];
            Af[2]  = PWh[row * 20 + kk2 + tq + 4];
            Af[3]  = PWh[(row + 8) * 20 + kk2 + tq + 4];
            Alf[0] = PWl[row * 20 + kk2 + tq];
            Alf[1] = PWl[(row + 8) * 20 + kk2 + tq];
            Alf[2] = PWl[row * 20 + kk2 + tq + 4];
            Alf[3] = PWl[(row + 8) * 20 + kk2 + tq + 4];
#pragma unroll
            for (int j = 0; j < 8; j++) {
                int n = wn + 8 * j + gid;
                Bf[j][0]  = PBh[(kk2 + tq) * 136 + n];
                Bf[j][1]  = PBh[(kk2 + tq + 4) * 136 + n];
                Blf[j][0] = PBl[(kk2 + tq) * 136 + n];
                Blf[j][1] = PBl[(kk2 + tq + 4) * 136 + n];
            }
#pragma unroll
            for (int j = 0; j < 8; j++) mma_f16(acc[j], Af,  Bf[j]);
#pragma unroll
            for (int j = 0; j < 8; j++) mma_f16(acc[j], Af,  Blf[j]);
#pragma unroll
            for (int j = 0; j < 8; j++) mma_f16(acc[j], Alf, Bf[j]);
        }
        __syncthreads();
    }

    int t   = pos0 >> 10;
    int hw0 = pos0 & 1023;
#pragma unroll
    for (int j = 0; j < 8; j++) {
        int hw = hw0 + wn + 8 * j + 2 * tq;
#pragma unroll
        for (int half = 0; half < 2; half++) {
            int r = rows0 + wm + gid + half * 8;
            if (r >= 160) continue;
            float v0 = acc[j][half * 2 + 0];
            float v1 = acc[j][half * 2 + 1];
            if (r < 16) {
                float bias = bq[r];
                *(float2*)&g_qf[b][r * TT + t][hw] = make_float2(v0 + bias, v1 + bias);
            } else if (r < 32) {
                float bias = bk[r - 16];
                *(float2*)&g_kf[b][(r - 16) * TT + t][hw] = make_float2(v0 + bias, v1 + bias);
            } else {
                float bias = bv[r - 32];
                int row = (r - 32) * TT + t;
                *(uint32_t*)&g_vf_s[b][row][hw] =
                    packh(__float2half_rn(v0 + bias), __float2half_rn(v1 + bias));
            }
        }
    }
}

// ---------------- 2) PAM energy via fp16x3 MMA (packed k-pairs) ----------------
#define EN_SMEM_BYTES (4 * 16 * 136 * 4)
__global__ __launch_bounds__(256, 2) void k_energy_tc()
{
    extern __shared__ uint32_t esm[];
    uint32_t* Ah = esm;
    uint32_t* Al = esm + 16 * 136;
    uint32_t* Bh = esm + 2 * 16 * 136;
    uint32_t* Bl = esm + 3 * 16 * 136;

    int b  = blockIdx.z;
    int n0 = blockIdx.y * 128;
    int m0 = blockIdx.x * 128;
    int tid = threadIdx.x, wid = tid >> 5, lane = tid & 31;
    int gid = lane >> 2, tq = lane & 3;
    int wm = (wid >> 1) * 32;
    int wn = (wid & 1) * 64;

    float acc[2][8][4] = {};

    for (int kc = 0; kc < 128; kc += 32) {
#pragma unroll
        for (int q = 0; q < 2; q++) {
            int e = tid + q * 256;
            int kp = e >> 5, ng = e & 31;
            const float* qa = &g_qf[b][kc + 2 * kp][n0 + ng * 4];
            const float* kb = &g_kf[b][kc + 2 * kp][m0 + ng * 4];
            float4 va0 = *(const float4*)qa;
            float4 va1 = *(const float4*)(qa + HWD);
            float4 vb0 = *(const float4*)kb;
            float4 vb1 = *(const float4*)(kb + HWD);
            uint4 hi, lo;
            pack2rows(va0, va1, hi, lo);
            *(uint4*)&Ah[kp * 136 + ng * 4] = hi;
            *(uint4*)&Al[kp * 136 + ng * 4] = lo;
            pack2rows(vb0, vb1, hi, lo);
            *(uint4*)&Bh[kp * 136 + ng * 4] = hi;
            *(uint4*)&Bl[kp * 136 + ng * 4] = lo;
        }
        __syncthreads();
#pragma unroll
        for (int kk2 = 0; kk2 < 16; kk2 += 8) {
            uint32_t Af[2][4], Alf[2][4], Bf[8][2], Blf[8][2];
#pragma unroll
            for (int i = 0; i < 2; i++) {
                int m = wm + 16 * i + gid;
                Af[i][0]  = Ah[(kk2 + tq) * 136 + m];
                Af[i][1]  = Ah[(kk2 + tq) * 136 + m + 8];
                Af[i][2]  = Ah[(kk2 + tq + 4) * 136 + m];
                Af[i][3]  = Ah[(kk2 + tq + 4) * 136 + m + 8];
                Alf[i][0] = Al[(kk2 + tq) * 136 + m];
                Alf[i][1] = Al[(kk2 + tq) * 136 + m + 8];
                Alf[i][2] = Al[(kk2 + tq + 4) * 136 + m];
                Alf[i][3] = Al[(kk2 + tq + 4) * 136 + m + 8];
            }
#pragma unroll
            for (int j = 0; j < 8; j++) {
                int n = wn + 8 * j + gid;
                Bf[j][0]  = Bh[(kk2 + tq) * 136 + n];
                Bf[j][1]  = Bh[(kk2 + tq + 4) * 136 + n];
                Blf[j][0] = Bl[(kk2 + tq) * 136 + n];
                Blf[j][1] = Bl[(kk2 + tq + 4) * 136 + n];
            }
#pragma unroll
            for (int j = 0; j < 8; j++)
#pragma unroll
                for (int i = 0; i < 2; i++) mma_f16(acc[i][j], Af[i], Bf[j]);
#pragma unroll
            for (int j = 0; j < 8; j++)
#pragma unroll
                for (int i = 0; i < 2; i++) mma_f16(acc[i][j], Af[i], Blf[j]);
#pragma unroll
            for (int j = 0; j < 8; j++)
#pragma unroll
                for (int i = 0; i < 2; i++) mma_f16(acc[i][j], Alf[i], Bf[j]);
        }
        __syncthreads();
    }

#pragma unroll
    for (int i = 0; i < 2; i++)
#pragma unroll
        for (int j = 0; j < 8; j++) {
            int n = n0 + wm + 16 * i + gid;
            int m = m0 + wn + 8 * j + 2 * tq;
            *(float2*)&g_attn[b][n][m]     = make_float2(acc[i][j][0], acc[i][j][1]);
            *(float2*)&g_attn[b][n + 8][m] = make_float2(acc[i][j][2], acc[i][j][3]);
        }
}

// ---------------- 3) softmax -> single fp16 (vectorized) ----------------
__global__ __launch_bounds__(256) void k_softmax()
{
    int row = blockIdx.x;
    int tid = threadIdx.x;
    const float4* e4 = (const float4*)(&g_attn[0][0][0] + (size_t)row * 1024);
    float4 v = e4[tid];
    float m = fmaxf(fmaxf(v.x, v.y), fmaxf(v.z, v.w));
    __shared__ float red[8];
#pragma unroll
    for (int o = 16; o > 0; o >>= 1) m = fmaxf(m, __shfl_xor_sync(0xffffffffu, m, o));
    if ((tid & 31) == 0) red[tid >> 5] = m;
    __syncthreads();
    m = red[0];
#pragma unroll
    for (int j = 1; j < 8; j++) m = fmaxf(m, red[j]);
    v.x = __expf(v.x - m); v.y = __expf(v.y - m);
    v.z = __expf(v.z - m); v.w = __expf(v.w - m);
    float s = (v.x + v.y) + (v.z + v.w);
    __syncthreads();
#pragma unroll
    for (int o = 16; o > 0; o >>= 1) s += __shfl_xor_sync(0xffffffffu, s, o);
    if ((tid & 31) == 0) red[tid >> 5] = s;
    __syncthreads();
    s = red[0];
#pragma unroll
    for (int j = 1; j < 8; j++) s += red[j];
    float inv = 1.f / s;
    v.x *= inv; v.y *= inv; v.z *= inv; v.w *= inv;

    uint2 hp;
    hp.x = packh(__float2half_rn(v.x), __float2half_rn(v.y));
    hp.y = packh(__float2half_rn(v.z), __float2half_rn(v.w));
    ((uint2*)(&g_attn_s[0][0][0] + (size_t)row * 1024))[tid] = hp;
}

// ---------------- 4) CAM energy fp16x3 Gram ----------------
#define CPAD 40
#define CAME_SMEM_BYTES (32768 + 2 * 128 * CPAD * 2)
__global__ __launch_bounds__(256, 2) void k_came_tc(const float* __restrict__ x)
{
    extern __shared__ char csm[];
    float* raw = (float*)csm;
    __half* Xh = (__half*)(csm + 32768);
    __half* Xl = (__half*)(csm + 32768 + 128 * CPAD * 2);
    uint32_t rawb = smem_to_u32(raw);

    int b  = blockIdx.x >> 5;
    int sl = blockIdx.x & 31;
    int tid = threadIdx.x, wid = tid >> 5, lane = tid & 31;
    int gid = lane >> 2, tq = lane & 3;
    int wm = (wid >> 1) * 32;
    int wn = (wid & 1) * 64;
    const float* xb = x + (size_t)b * (CC * NPOS) + sl * 256;

    float acc[2][8][4] = {};

    auto load_raw = [&](int st, int kc) {
#pragma unroll
        for (int q = 0; q < 4; q++) {
            int e = tid + q * 256;
            int row = e >> 3, c4 = e & 7;
            cp16(rawb + (uint32_t)(st * 4096 + row * 32 + c4 * 4) * 4,
                 xb + (size_t)row * NPOS + kc + c4 * 4);
        }
        CP_COMMIT();
    };

    load_raw(0, 0);

    for (int it = 0; it < 8; it++) {
        int st = it & 1;
        if (it < 7) { load_raw(st ^ 1, (it + 1) * 32); CP_WAIT(1); }
        else        { CP_WAIT(0); }
        __syncthreads();

#pragma unroll
        for (int q = 0; q < 4; q++) {
            int e = tid + q * 256;
            int row = e >> 3, c4 = e & 7;
            float4 v = *(const float4*)&raw[st * 4096 + row * 32 + c4 * 4];
            __half hx, lx, hy, ly, hz, lz, hw, lw;
            split_h(v.x, hx, lx); split_h(v.y, hy, ly);
            split_h(v.z, hz, lz); split_h(v.w, hw, lw);
            uint2 hp, lp;
            hp.x = packh(hx, hy); hp.y = packh(hz, hw);
            lp.x = packh(lx, ly); lp.y = packh(lz, lw);
            *(uint2*)&Xh[row * CPAD + c4 * 4] = hp;
            *(uint2*)&Xl[row * CPAD + c4 * 4] = lp;
        }
        __syncthreads();

#pragma unroll
        for (int kk = 0; kk < 32; kk += 16) {
            uint32_t Af[2][4], Alf[2][4], Bf[8][2], Blf[8][2];
            int c0 = kk + 2 * tq, c1 = c0 + 8;
#pragma unroll
            for (int i = 0; i < 2; i++) {
                int r0 = wm + 16 * i + gid, r1 = r0 + 8;
                Af[i][0]  = *(const uint32_t*)&Xh[r0 * CPAD + c0];
                Af[i][1]  = *(const uint32_t*)&Xh[r1 * CPAD + c0];
                Af[i][2]  = *(const uint32_t*)&Xh[r0 * CPAD + c1];
                Af[i][3]  = *(const uint32_t*)&Xh[r1 * CPAD + c1];
                Alf[i][0] = *(const uint32_t*)&Xl[r0 * CPAD + c0];
                Alf[i][1] = *(const uint32_t*)&Xl[r1 * CPAD + c0];
                Alf[i][2] = *(const uint32_t*)&Xl[r0 * CPAD + c1];
                Alf[i][3] = *(const uint32_t*)&Xl[r1 * CPAD + c1];
            }
#pragma unroll
            for (int j = 0; j < 8; j++) {
                int rn = wn + 8 * j + gid;
                Bf[j][0]  = *(const uint32_t*)&Xh[rn * CPAD + c0];
                Bf[j][1]  = *(const uint32_t*)&Xh[rn * CPAD + c1];
                Blf[j][0] = *(const uint32_t*)&Xl[rn * CPAD + c0];
                Blf[j][1] = *(const uint32_t*)&Xl[rn * CPAD + c1];
            }
#pragma unroll
            for (int j = 0; j < 8; j++)
#pragma unroll
                for (int i = 0; i < 2; i++) mma_f16(acc[i][j], Af[i], Bf[j]);
#pragma unroll
            for (int j = 0; j < 8; j++)
#pragma unroll
                for (int i = 0; i < 2; i++) mma_f16(acc[i][j], Af[i], Blf[j]);
#pragma unroll
            for (int j = 0; j < 8; j++)
#pragma unroll
                for (int i = 0; i < 2; i++) mma_f16(acc[i][j], Alf[i], Bf[j]);
        }
    }

#pragma unroll
    for (int i = 0; i < 2; i++)
#pragma unroll
        for (int j = 0; j < 8; j++) {
            int c = wm + 16 * i + gid;
            int d = wn + 8 * j + 2 * tq;
            *(float2*)&g_ecam_p[sl][b][c][d]     = make_float2(acc[i][j][0], acc[i][j][1]);
            *(float2*)&g_ecam_p[sl][b][c + 8][d] = make_float2(acc[i][j][2], acc[i][j][3]);
        }
}

// ---------------- 5) CAM negated-energy softmax ----------------
__global__ __launch_bounds__(128) void k_camsm()
{
    int b = blockIdx.x >> 7;
    int c = blockIdx.x & 127;
    int d = threadIdx.x;
    float ev = 0.f;
#pragma unroll
    for (int sl = 0; sl < 32; sl++) ev += g_ecam_p[sl][b][c][d];
    __shared__ float red[4];
    float mn = ev;
#pragma unroll
    for (int o = 16; o > 0; o >>= 1) mn = fminf(mn, __shfl_xor_sync(0xffffffffu, mn, o));
    if ((threadIdx.x & 31) == 0) red[threadIdx.x >> 5] = mn;
    __syncthreads();
    mn = fminf(fminf(red[0], red[1]), fminf(red[2], red[3]));
    float w = __expf(mn - ev);
    __syncthreads();
    float s = w;
#pragma unroll
    for (int o = 16; o > 0; o >>= 1) s += __shfl_xor_sync(0xffffffffu, s, o);
    if ((threadIdx.x & 31) == 0) red[threadIdx.x >> 5] = s;
    __syncthreads();
    s = (red[0] + red[1]) + (red[2] + red[3]);
    g_acam[b][c][d] = w / s;
}

// ---------------- 6) TIM Gram partials ----------------
__global__ __launch_bounds__(256) void k_time(const float* __restrict__ x)
{
    int c = blockIdx.x;
    int b = blockIdx.y;
    int tid = threadIdx.x;
    const float* xp = x + ((size_t)b * CC + c) * NPOS;
    float v[8][4];
#pragma unroll
    for (int t = 0; t < 8; t++) {
        float4 f = *reinterpret_cast<const float4*>(xp + t * 1024 + tid * 4);
        v[t][0] = f.x; v[t][1] = f.y; v[t][2] = f.z; v[t][3] = f.w;
    }
    float acc[36];
    int idx = 0;
#pragma unroll
    for (int t = 0; t < 8; t++)
#pragma unroll
        for (int s = t; s < 8; s++) {
            float a = 0.f;
#pragma unroll
            for (int j = 0; j < 4; j++) a += v[t][j] * v[s][j];
            acc[idx++] = a;
        }
    __shared__ float red[36][8];
    int lane = tid & 31, warp = tid >> 5;
#pragma unroll
    for (int i = 0; i < 36; i++) {
        float a = acc[i];
#pragma unroll
        for (int o = 16; o > 0; o >>= 1) a += __shfl_xor_sync(0xffffffffu, a, o);
        if (lane == 0) red[i][warp] = a;
    }
    __syncthreads();
    if (tid < 36) {
        float a = 0.f;
#pragma unroll
        for (int w = 0; w < 8; w++) a += red[tid][w];
        g_etim_p[b][c][tid] = a;
    }
}

// ---------------- 6b) TIM partial reduce over channels ----------------
__global__ __launch_bounds__(128) void k_timred()
{
    int i = blockIdx.x;
    int b = blockIdx.y;
    int tid = threadIdx.x;
    float a = g_etim_p[b][tid][i];
#pragma unroll
    for (int o = 16; o > 0; o >>= 1) a += __shfl_xor_sync(0xffffffffu, a, o);
    __shared__ float r[4];
    if ((tid & 31) == 0) r[tid >> 5] = a;
    __syncthreads();
    if (tid == 0) g_etim36[b][i] = (r[0] + r[1]) + (r[2] + r[3]);
}

// ---------------- 7) TIM softmax (tiny) ----------------
__global__ __launch_bounds__(64) void k_timsm()
{
    int tid = threadIdx.x;
    int b = tid >> 3, t = tid & 7;
    float e[8];
#pragma unroll
    for (int s = 0; s < 8; s++) {
        int lo = t < s ? t : s, hi = t < s ? s : t;
        int idx = 8 * lo - lo * (lo - 1) / 2 + (hi - lo);
        e[s] = g_etim36[b][idx];
    }
    float mn = e[0];
#pragma unroll
    for (int s = 1; s < 8; s++) mn = fminf(mn, e[s]);
    float w[8], sum = 0.f;
#pragma unroll
    for (int s = 0; s < 8; s++) { w[s] = __expf(mn - e[s]); sum += w[s]; }
#pragma unroll
    for (int s = 0; s < 8; s++) g_atim[b][t][s] = w[s] / sum;
}

// ---------------- 8a) CAM apply via single-term fp16 MMA: g_cam = acam @ x ----------------
// A = acam [c][c'] row-major (pack within row); B = x [c'][pos] (pack k-pairs). Full K=128.
#define CAP_SMEM_BYTES ((128 * 68 + 64 * 136) * 4)
__global__ __launch_bounds__(256, 2) void k_camapply(const float* __restrict__ x)
{
    extern __shared__ uint32_t psm[];
    uint32_t* PA = psm;                 // 128 rows x 64 kp (stride 68)
    uint32_t* PB = psm + 128 * 68;      // 64 kp x 128 pos (stride 136)

    int b    = blockIdx.y;
    int pos0 = blockIdx.x * 128;
    int tid = threadIdx.x, wid = tid >> 5, lane = tid & 31;
    int gid = lane >> 2, tq = lane & 3;
    int wm = (wid >> 1) * 32;
    int wn = (wid & 1) * 64;
    const float* xb = x + (size_t)b * (CC * NPOS);

    // load acam: 128 rows x 32 float4 groups
#pragma unroll
    for (int q = 0; q < 16; q++) {
        int e = tid + q * 256;
        int row = e >> 5, kg = e & 31;
        float4 v = *(const float4*)&g_acam[b][row][kg * 4];
        *(uint2*)&PA[row * 68 + kg * 2] = pack4_hi(v);
    }
    // load x packed k-pairs: 64 kp x 32 ng
#pragma unroll
    for (int q = 0; q < 8; q++) {
        int e = tid + q * 256;
        int kp = e >> 5, ng = e & 31;
        const float* r0p = xb + (size_t)(2 * kp) * NPOS + pos0 + ng * 4;
        float4 v0 = *(const float4*)r0p;
        float4 v1 = *(const float4*)(r0p + NPOS);
        *(uint4*)&PB[kp * 136 + ng * 4] = pack2rows_hi(v0, v1);
    }
    __syncthreads();

    float acc[2][8][4] = {};
#pragma unroll
    for (int kk2 = 0; kk2 < 64; kk2 += 8) {
        uint32_t Af[2][4], Bf[8][2];
#pragma unroll
        for (int i = 0; i < 2; i++) {
            int row = wm + 16 * i + gid;
            Af[i][0] = PA[row * 68 + kk2 + tq];
            Af[i][1] = PA[(row + 8) * 68 + kk2 + tq];
            Af[i][2] = PA[row * 68 + kk2 + tq + 4];
            Af[i][3] = PA[(row + 8) * 68 + kk2 + tq + 4];
        }
#pragma unroll
        for (int j = 0; j < 8; j++) {
            int n = wn + 8 * j + gid;
            Bf[j][0] = PB[(kk2 + tq) * 136 + n];
            Bf[j][1] = PB[(kk2 + tq + 4) * 136 + n];
        }
#pragma unroll
        for (int j = 0; j < 8; j++)
#pragma unroll
            for (int i = 0; i < 2; i++) mma_f16(acc[i][j], Af[i], Bf[j]);
    }

#pragma unroll
    for (int i = 0; i < 2; i++)
#pragma unroll
        for (int j = 0; j < 8; j++) {
            int c = wm + 16 * i + gid;
            int n = pos0 + wn + 8 * j + 2 * tq;
            *(float2*)&g_cam[b][c][n]     = make_float2(acc[i][j][0], acc[i][j][1]);
            *(float2*)&g_cam[b][c + 8][n] = make_float2(acc[i][j][2], acc[i][j][3]);
        }
}

// ---------------- 8b) base elementwise: out = 3x + gc*cam + gt*tim ----------------
__global__ __launch_bounds__(256) void k_base2(
    const float* __restrict__ x,
    const float* __restrict__ gcp, const float* __restrict__ gtp,
    float* __restrict__ out)
{
    int c = blockIdx.x;
    int b = blockIdx.y;
    int tid = threadIdx.x;
    __shared__ float at8[8][8];
    if (tid < 64) at8[tid >> 3][tid & 7] = g_atim[b][tid >> 3][tid & 7];
    __syncthreads();
    int hw = tid * 4;
    const float* xc = x + ((size_t)b * CC + c) * NPOS + hw;
    const float* cp = &g_cam[b][c][hw];
    float* oc = out + ((size_t)b * CC + c) * NPOS + hw;

    float4 xr[8], cr[8];
#pragma unroll
    for (int s = 0; s < 8; s++) xr[s] = *(const float4*)(xc + s * 1024);
#pragma unroll
    for (int s = 0; s < 8; s++) cr[s] = *(const float4*)(cp + s * 1024);
    float gc = gcp[0], gt = gtp[0];
#pragma unroll
    for (int t = 0; t < 8; t++) {
        float4 tim = make_float4(0.f, 0.f, 0.f, 0.f);
#pragma unroll
        for (int s = 0; s < 8; s++) {
            float a = at8[t][s];
            tim.x += a * xr[s].x;
            tim.y += a * xr[s].y;
            tim.z += a * xr[s].z;
            tim.w += a * xr[s].w;
        }
        float4 o;
        o.x = 3.f * xr[t].x + gc * cr[t].x + gt * tim.x;
        o.y = 3.f * xr[t].y + gc * cr[t].y + gt * tim.y;
        o.z = 3.f * xr[t].z + gc * cr[t].z + gt * tim.z;
        o.w = 3.f * xr[t].w + gc * cr[t].w + gt * tim.w;
        *(float4*)(oc + t * 1024) = o;
    }
}

// ---------------- 9) PAM GEMM: single-term fp16, cp.async 2-stage ----------------
#define PAD 40
#define PAM_TILE 5120
#define PAM_STAGE (2 * PAM_TILE)
#define PAM_SMEM_BYTES (2 * PAM_STAGE * 2)
__global__ __launch_bounds__(256, 2) void k_pam_mma(const float* __restrict__ gpp,
                                                    float* __restrict__ out)
{
    extern __shared__ __half smp[];
    uint32_t smb = smem_to_u32(smp);

    int tid = threadIdx.x;
    int b  = blockIdx.z;
    int r0 = blockIdx.y * 128;
    int n0 = blockIdx.x * 128;
    int wid = tid >> 5, lane = tid & 31;
    int gid = lane >> 2, tq = lane & 3;
    int wm = (wid & 1) * 64;
    int wn = (wid >> 1) * 32;

    const __half* Asp = &g_vf_s[b][0][0];
    const __half* Bsp = &g_attn_s[b][0][0];

    float acc[4][4][4] = {};

    auto stage_load = [&](int st, int kc) {
#pragma unroll
        for (int q = 0; q < 2; q++) {
            int e = tid + q * 256;
            int row = e >> 2, c4 = e & 3;
            uint32_t so = smb + (uint32_t)(st * PAM_STAGE + row * PAD + c4 * 8) * 2;
            size_t gA = (size_t)(r0 + row) * 1024 + kc + c4 * 8;
            size_t gB = (size_t)(n0 + row) * 1024 + kc + c4 * 8;
            cp16(so,                Asp + gA);
            cp16(so + PAM_TILE * 2, Bsp + gB);
        }
        CP_COMMIT();
    };

    stage_load(0, 0);

    for (int it = 0; it < 32; it++) {
        int st = it & 1;
        if (it < 31) { stage_load(st ^ 1, (it + 1) * 32); CP_WAIT(1); }
        else         { CP_WAIT(0); }
        __syncthreads();

        const __half* sAs = smp + st * PAM_STAGE;
        const __half* sBs = sAs + PAM_TILE;

#pragma unroll
        for (int ks = 0; ks < 32; ks += 16) {
            uint32_t Af[4][4], Bf[4][2];
            int col = ks + tq * 2;
#pragma unroll
            for (int i = 0; i < 4; i++) {
                int row = wm + 16 * i + gid;
                Af[i][0] = *(const uint32_t*)&sAs[row * PAD + col];
                Af[i][1] = *(const uint32_t*)&sAs[(row + 8) * PAD + col];
                Af[i][2] = *(const uint32_t*)&sAs[row * PAD + col + 8];
                Af[i][3] = *(const uint32_t*)&sAs[(row + 8) * PAD + col + 8];
            }
#pragma unroll
            for (int j = 0; j < 4; j++) {
                int nrow = wn + 8 * j + gid;
                Bf[j][0] = *(const uint32_t*)&sBs[nrow * PAD + col];
                Bf[j][1] = *(const uint32_t*)&sBs[nrow * PAD + col + 8];
            }
#pragma unroll
            for (int j = 0; j < 4; j++)
#pragma unroll
                for (int i = 0; i < 4; i++) mma_f16(acc[i][j], Af[i], Bf[j]);
        }
        __syncthreads();
    }

    float gpv = gpp[0];
    float* ob = out + (size_t)b * (CT * HWD);
#pragma unroll
    for (int i = 0; i < 4; i++) {
#pragma unroll
        for (int j = 0; j < 4; j++) {
            int r = r0 + wm + 16 * i + gid;
            int n = n0 + wn + 8 * j + tq * 2;
            float2* p0 = (float2*)(ob + (size_t)r * 1024 + n);
            float2 v0 = *p0;
            v0.x += gpv * acc[i][j][0];
            v0.y += gpv * acc[i][j][1];
            *p0 = v0;
            float2* p1 = (float2*)(ob + (size_t)(r + 8) * 1024 + n);
            float2 v1 = *p1;
            v1.x += gpv * acc[i][j][2];
            v1.y += gpv * acc[i][j][3];
            *p1 = v1;
        }
    }
}

// ---------------- launch: three-stream fork/join overlap ----------------
extern "C" void kernel_launch(void* const* d_in, const int* in_sizes, int n_in,
                              void* d_out, int out_size)
{
    const float* x  = (const float*)d_in[0];
    const float* Wq = (const float*)d_in[1];
    const float* bq = (const float*)d_in[2];
    const float* Wk = (const float*)d_in[3];
    const float* bk = (const float*)d_in[4];
    const float* Wv = (const float*)d_in[5];
    const float* bv = (const float*)d_in[6];
    const float* gp = (const float*)d_in[7];
    const float* gc = (const float*)d_in[8];
    const float* gt = (const float*)d_in[9];
    float* out = (float*)d_out;

    static cudaStream_t s2 = nullptr, s3 = nullptr;
    static cudaEvent_t evFork = nullptr, evTim = nullptr, evJoin = nullptr;
    static int attrs_set = 0;
    if (!attrs_set) {
        cudaFuncSetAttribute(k_qkv_tc, cudaFuncAttributeMaxDynamicSharedMemorySize, QKV_SMEM_BYTES);
        cudaFuncSetAttribute(k_energy_tc, cudaFuncAttributeMaxDynamicSharedMemorySize, EN_SMEM_BYTES);
        cudaFuncSetAttribute(k_came_tc, cudaFuncAttributeMaxDynamicSharedMemorySize, CAME_SMEM_BYTES);
        cudaFuncSetAttribute(k_camapply, cudaFuncAttributeMaxDynamicSharedMemorySize, CAP_SMEM_BYTES);
        cudaFuncSetAttribute(k_pam_mma, cudaFuncAttributeMaxDynamicSharedMemorySize, PAM_SMEM_BYTES);
        cudaStreamCreateWithFlags(&s2, cudaStreamNonBlocking);
        cudaStreamCreateWithFlags(&s3, cudaStreamNonBlocking);
        cudaEventCreateWithFlags(&evFork, cudaEventDisableTiming);
        cudaEventCreateWithFlags(&evTim, cudaEventDisableTiming);
        cudaEventCreateWithFlags(&evJoin, cudaEventDisableTiming);
        attrs_set = 1;
    }

    // fork
    cudaEventRecord(evFork, 0);
    cudaStreamWaitEvent(s2, evFork, 0);
    cudaStreamWaitEvent(s3, evFork, 0);

    // chain B1 on s2: CAM energy -> softmax -> apply
    k_came_tc<<<256, 256, CAME_SMEM_BYTES, s2>>>(x);
    k_camsm<<<1024, 128, 0, s2>>>();
    k_camapply<<<dim3(64, 8), 256, CAP_SMEM_BYTES, s2>>>(x);
    // chain B2 on s3: TIM
    k_time<<<dim3(128, 8), 256, 0, s3>>>(x);
    k_timred<<<dim3(36, 8), 128, 0, s3>>>();
    k_timsm<<<1, 64, 0, s3>>>();
    // base2 on s2 after both
    cudaEventRecord(evTim, s3);
    cudaStreamWaitEvent(s2, evTim, 0);
    k_base2<<<dim3(128, 8), 256, 0, s2>>>(x, gc, gt, out);

    // chain A on default
    k_qkv_tc<<<dim3(64, 3, 8), 256, QKV_SMEM_BYTES>>>(x, Wq, bq, Wk, bk, Wv, bv);
    k_energy_tc<<<dim3(8, 8, 8), 256, EN_SMEM_BYTES>>>();
    k_softmax<<<8192, 256>>>();

    // join: pam needs softmax (A) and base2's out (B)
    cudaEventRecord(evJoin, s2);
    cudaStreamWaitEvent(0, evJoin, 0);
    k_pam_mma<<<dim3(8, 8, 8), 256, PAM_SMEM_BYTES>>>(gp, out);
}